// round 1
// baseline (speedup 1.0000x reference)
#include <cuda_runtime.h>
#include <cuda_bf16.h>
#include <math.h>

// Problem constants (shapes fixed by the dataset)
#define NNODE 8000
#define DDIM  256
#define K3    768      // 3*D for the fuse GEMM
#define EMAX  256000
#define LLAYERS 2
#define PRESERVE_F 0.1f

// ---------------- scratch (static device memory; no allocation allowed) ---------
__device__ float g_X3[NNODE * K3];        // concat(emb1, demand_last, supply_last)
__device__ float g_U [NNODE * DDIM];      // update_emb
__device__ float g_tmpD[NNODE * DDIM];    // dense GCN running temp
__device__ float g_tmpS[NNODE * DDIM];    // sparse GCN running temp
__device__ float g_xw [NNODE * DDIM];
__device__ float g_Y  [NNODE * DDIM];
__device__ float g_Z2 [NNODE * DDIM];     // also reused as sparse agg buffer
__device__ float g_deg [NNODE];
__device__ float g_dis [NNODE];
__device__ float g_deg2[NNODE];
__device__ float g_dis2[NNODE];
__device__ float g_enorm[EMAX];

// ---------------- generic fp32 SGEMM: 128x128x8, 8x8 per thread -----------------
#define BM 128
#define BN 128
#define BK 8
#define TM 8
#define TN 8

template<int TRA, int TRB, bool BIAS>
__global__ __launch_bounds__(256, 2)
void sgemm_kernel(const float* __restrict__ A, const float* __restrict__ B,
                  float* __restrict__ C, const float* __restrict__ bias,
                  int M, int N, int K, int lda, int ldb, int ldc)
{
    __shared__ float As[BK][BM];
    __shared__ float Bs[BK][BN];

    const int tid = threadIdx.x;
    const int m0  = blockIdx.y * BM;
    const int n0  = blockIdx.x * BN;
    const int ty  = tid >> 4;     // 0..15
    const int tx  = tid & 15;     // 0..15

    float acc[TM][TN];
#pragma unroll
    for (int i = 0; i < TM; i++)
#pragma unroll
        for (int j = 0; j < TN; j++) acc[i][j] = 0.f;

    for (int k0 = 0; k0 < K; k0 += BK) {
        // ---- load A tile -> As[k][m]
        if (TRA == 0) {
            // A[M,K] row-major: 128 rows x 8 cols, 1 float4 per thread
            int r  = tid >> 1;
            int c4 = (tid & 1) * 4;
            int gm = m0 + r;
            float4 v = make_float4(0.f, 0.f, 0.f, 0.f);
            if (gm < M)
                v = *reinterpret_cast<const float4*>(A + (size_t)gm * lda + k0 + c4);
            As[c4 + 0][r] = v.x; As[c4 + 1][r] = v.y;
            As[c4 + 2][r] = v.z; As[c4 + 3][r] = v.w;
        } else {
            // A[K,M] row-major (op = A^T): 8 rows x 128 cols, coalesced
            int rr  = tid >> 5;
            int cc4 = (tid & 31) * 4;
            int gm  = m0 + cc4;
            float4 v = make_float4(0.f, 0.f, 0.f, 0.f);
            if (gm < M)
                v = *reinterpret_cast<const float4*>(A + (size_t)(k0 + rr) * lda + gm);
            As[rr][cc4 + 0] = v.x; As[rr][cc4 + 1] = v.y;
            As[rr][cc4 + 2] = v.z; As[rr][cc4 + 3] = v.w;
        }
        // ---- load B tile -> Bs[k][n]
        if (TRB == 0) {
            int rr  = tid >> 5;
            int cc4 = (tid & 31) * 4;
            int gn  = n0 + cc4;
            float4 v = make_float4(0.f, 0.f, 0.f, 0.f);
            if (gn < N)
                v = *reinterpret_cast<const float4*>(B + (size_t)(k0 + rr) * ldb + gn);
            Bs[rr][cc4 + 0] = v.x; Bs[rr][cc4 + 1] = v.y;
            Bs[rr][cc4 + 2] = v.z; Bs[rr][cc4 + 3] = v.w;
        } else {
            // B[N,K] row-major (op = B^T)
            int r  = tid >> 1;
            int c4 = (tid & 1) * 4;
            int gn = n0 + r;
            float4 v = make_float4(0.f, 0.f, 0.f, 0.f);
            if (gn < N)
                v = *reinterpret_cast<const float4*>(B + (size_t)gn * ldb + k0 + c4);
            Bs[c4 + 0][r] = v.x; Bs[c4 + 1][r] = v.y;
            Bs[c4 + 2][r] = v.z; Bs[c4 + 3][r] = v.w;
        }
        __syncthreads();

#pragma unroll
        for (int kk = 0; kk < BK; kk++) {
            float a[TM], b[TN];
#pragma unroll
            for (int i = 0; i < TM; i++) a[i] = As[kk][ty * TM + i];
#pragma unroll
            for (int j = 0; j < TN; j++) b[j] = Bs[kk][tx * TN + j];
#pragma unroll
            for (int i = 0; i < TM; i++)
#pragma unroll
                for (int j = 0; j < TN; j++)
                    acc[i][j] = fmaf(a[i], b[j], acc[i][j]);
        }
        __syncthreads();
    }

#pragma unroll
    for (int i = 0; i < TM; i++) {
        int gm = m0 + ty * TM + i;
        if (gm >= M) continue;
#pragma unroll
        for (int j = 0; j < TN; j++) {
            int gn = n0 + tx * TN + j;
            if (gn < N) {
                float v = acc[i][j];
                if (BIAS) v += bias[gn];
                C[(size_t)gm * ldc + gn] = v;
            }
        }
    }
}

// ---------------- small kernels --------------------------------------------------

__global__ void gather_x3_kernel(const float* __restrict__ emb1,
                                 const float* __restrict__ demand,
                                 const float* __restrict__ supply,
                                 float* __restrict__ X3, int n, int T)
{
    int i = blockIdx.x * blockDim.x + threadIdx.x;
    int total = n * DDIM;
    if (i >= total) return;
    int node = i / DDIM, d = i % DDIM;
    float* row = X3 + (size_t)node * K3;
    row[d]            = emb1[(size_t)node * DDIM + d];
    row[DDIM + d]     = demand[((size_t)node * T + (T - 1)) * DDIM + d];
    row[2 * DDIM + d] = supply[((size_t)node * T + (T - 1)) * DDIM + d];
}

// one block per row: in-place  Z -> relu(softmax(Z) - 0.2)
__global__ void softmax_relu_kernel(float* __restrict__ Z, int n)
{
    __shared__ float row[NNODE];
    __shared__ float red[256];
    int r = blockIdx.x;
    int t = threadIdx.x;
    float* zr = Z + (size_t)r * n;

    float mx = -3.4e38f;
    for (int c = t; c < n; c += 256) {
        float v = zr[c];
        row[c] = v;
        mx = fmaxf(mx, v);
    }
    red[t] = mx; __syncthreads();
    for (int s = 128; s > 0; s >>= 1) {
        if (t < s) red[t] = fmaxf(red[t], red[t + s]);
        __syncthreads();
    }
    mx = red[0];
    __syncthreads();

    float sm = 0.f;
    for (int c = t; c < n; c += 256) {
        float e = expf(row[c] - mx);
        row[c] = e;
        sm += e;
    }
    red[t] = sm; __syncthreads();
    for (int s = 128; s > 0; s >>= 1) {
        if (t < s) red[t] += red[t + s];
        __syncthreads();
    }
    float inv = 1.0f / red[0];
    for (int c = t; c < n; c += 256) {
        float p = row[c] * inv - 0.2f;
        zr[c] = p > 0.f ? p : 0.f;
    }
}

__global__ void fill_kernel(float* p, float v, int n)
{
    int i = blockIdx.x * blockDim.x + threadIdx.x;
    if (i < n) p[i] = v;
}

// column sums of G accumulated into deg (deg pre-filled with 1.0 for self loop)
__global__ void colsum_kernel(const float* __restrict__ G, float* __restrict__ deg, int n)
{
    int c = blockIdx.x * blockDim.x + threadIdx.x;
    if (c >= n) return;
    int chunk = (n + gridDim.y - 1) / gridDim.y;
    int r0 = blockIdx.y * chunk;
    int r1 = min(r0 + chunk, n);
    float s = 0.f;
    for (int r = r0; r < r1; r++) s += G[(size_t)r * n + c];
    atomicAdd(&deg[c], s);
}

__global__ void rsqrt_kernel(float* __restrict__ dst, const float* __restrict__ src, int n)
{
    int i = blockIdx.x * blockDim.x + threadIdx.x;
    if (i < n) dst[i] = rsqrtf(src[i]);
}

__global__ void scale_rows_kernel(float* __restrict__ Y, const float* __restrict__ X,
                                  const float* __restrict__ dis, int n, int d)
{
    int i = blockIdx.x * blockDim.x + threadIdx.x;
    if (i >= n * d) return;
    Y[i] = dis[i / d] * X[i];
}

// temp = 0.9*(dis[c]*Z2 + dis[c]^2*xw + b) + 0.1*temp
__global__ void dense_combine_kernel(float* __restrict__ temp, const float* __restrict__ Z2,
                                     const float* __restrict__ xw, const float* __restrict__ dis,
                                     const float* __restrict__ b, int n, int d)
{
    int i = blockIdx.x * blockDim.x + threadIdx.x;
    if (i >= n * d) return;
    int c = i / d, dd = i - c * d;
    float s = dis[c];
    float out = s * Z2[i] + s * s * xw[i] + b[dd];
    temp[i] = (1.0f - PRESERVE_F) * out + PRESERVE_F * temp[i];
}

__global__ void edge_deg_kernel(const int* __restrict__ dst, const float* __restrict__ attr,
                                float* __restrict__ deg2, int E)
{
    int e = blockIdx.x * blockDim.x + threadIdx.x;
    if (e < E) atomicAdd(&deg2[dst[e]], attr[e]);
}

__global__ void enorm_kernel(const int* __restrict__ src, const int* __restrict__ dst,
                             const float* __restrict__ attr, const float* __restrict__ dis2,
                             float* __restrict__ enorm, int E)
{
    int e = blockIdx.x * blockDim.x + threadIdx.x;
    if (e < E) enorm[e] = dis2[src[e]] * attr[e] * dis2[dst[e]];
}

// warp per edge: agg[dst] += enorm * xw[src]
__global__ void scatter_kernel(const float* __restrict__ xw, const int* __restrict__ src,
                               const int* __restrict__ dst, const float* __restrict__ enorm,
                               float* __restrict__ agg, int E, int d)
{
    int warp = (blockIdx.x * blockDim.x + threadIdx.x) >> 5;
    int lane = threadIdx.x & 31;
    if (warp >= E) return;
    int s = src[warp], t = dst[warp];
    float w = enorm[warp];
    const float* xr = xw + (size_t)s * d;
    float* ar = agg + (size_t)t * d;
    for (int f = lane; f < d; f += 32)
        atomicAdd(&ar[f], w * xr[f]);
}

// temp = 0.9*(agg + dis2[c]^2*xw + b) + 0.1*temp
__global__ void sparse_combine_kernel(float* __restrict__ temp, const float* __restrict__ agg,
                                      const float* __restrict__ xw, const float* __restrict__ dis2,
                                      const float* __restrict__ b, int n, int d)
{
    int i = blockIdx.x * blockDim.x + threadIdx.x;
    if (i >= n * d) return;
    int c = i / d, dd = i - c * d;
    float s = dis2[c];
    float out = agg[i] + s * s * xw[i] + b[dd];
    temp[i] = (1.0f - PRESERVE_F) * out + PRESERVE_F * temp[i];
}

__global__ void add_kernel(float* __restrict__ out, const float* __restrict__ a,
                           const float* __restrict__ b, int n)
{
    int i = blockIdx.x * blockDim.x + threadIdx.x;
    if (i < n) out[i] = a[i] + b[i];
}

// ---------------- host orchestration ---------------------------------------------

extern "C" void kernel_launch(void* const* d_in, const int* in_sizes, int n_in,
                              void* d_out, int out_size)
{
    const float* demand  = (const float*)d_in[0];
    const float* supply  = (const float*)d_in[1];
    const int*   eidx    = (const int*)  d_in[2];
    const float* eattr   = (const float*)d_in[3];
    const float* emb1    = (const float*)d_in[4];
    const float* fuse_W  = (const float*)d_in[5];
    const float* fuse_b  = (const float*)d_in[6];
    const float* gnn0_W  = (const float*)d_in[7];
    const float* gnn0_b  = (const float*)d_in[8];
    const float* gnn1_W  = (const float*)d_in[9];
    const float* gnn1_b  = (const float*)d_in[10];

    const int n = in_sizes[4] / DDIM;             // 8000
    const int E = in_sizes[3];                    // 256000
    const int T = in_sizes[0] / (n * DDIM);       // 16

    float* out_emb1  = (float*)d_out;
    float* out_skill = out_emb1 + (size_t)n * DDIM;
    float* out_pred  = out_skill + (size_t)n * DDIM;   // also logits scratch

    float *pX3, *pU, *ptD, *ptS, *pxw, *pY, *pZ2, *pdeg, *pdis, *pdeg2, *pdis2, *pen;
    cudaGetSymbolAddress((void**)&pX3,  g_X3);
    cudaGetSymbolAddress((void**)&pU,   g_U);
    cudaGetSymbolAddress((void**)&ptD,  g_tmpD);
    cudaGetSymbolAddress((void**)&ptS,  g_tmpS);
    cudaGetSymbolAddress((void**)&pxw,  g_xw);
    cudaGetSymbolAddress((void**)&pY,   g_Y);
    cudaGetSymbolAddress((void**)&pZ2,  g_Z2);
    cudaGetSymbolAddress((void**)&pdeg, g_deg);
    cudaGetSymbolAddress((void**)&pdis, g_dis);
    cudaGetSymbolAddress((void**)&pdeg2,g_deg2);
    cudaGetSymbolAddress((void**)&pdis2,g_dis2);
    cudaGetSymbolAddress((void**)&pen,  g_enorm);

    const int ND = n * DDIM;
    const int TPB = 256;
    dim3 blk(TPB);

    // 1) gather [emb1 | demand_last | supply_last]
    gather_x3_kernel<<<(ND + TPB - 1) / TPB, blk>>>(emb1, demand, supply, pX3, n, T);

    // 2) update_emb = X3 @ fuse_W + fuse_b     [n, 256]
    {
        dim3 grid((DDIM + BN - 1) / BN, (n + BM - 1) / BM);
        sgemm_kernel<0, 0, true><<<grid, blk>>>(pX3, fuse_W, pU, fuse_b,
                                                n, DDIM, K3, K3, DDIM, DDIM);
    }

    // 3) logits Z = U @ U^T  -> out_pred (scratch)
    {
        dim3 grid((n + BN - 1) / BN, (n + BM - 1) / BM);
        sgemm_kernel<0, 1, false><<<grid, blk>>>(pU, pU, out_pred, nullptr,
                                                 n, n, DDIM, DDIM, DDIM, n);
    }

    // 4) in-place row softmax + relu(.-0.2) -> pred_g
    softmax_relu_kernel<<<n, blk>>>(out_pred, n);

    // 5) dense degrees: deg = colsum(pred_g) + 1 ;  dis = rsqrt(deg)
    fill_kernel<<<(n + TPB - 1) / TPB, blk>>>(pdeg, 1.0f, n);
    {
        dim3 grid((n + TPB - 1) / TPB, 40);
        colsum_kernel<<<grid, blk>>>(out_pred, pdeg, n);
    }
    rsqrt_kernel<<<(n + TPB - 1) / TPB, blk>>>(pdis, pdeg, n);

    // 6) temps start at update_emb
    cudaMemcpyAsync(ptD, pU, (size_t)ND * sizeof(float), cudaMemcpyDeviceToDevice);
    cudaMemcpyAsync(ptS, pU, (size_t)ND * sizeof(float), cudaMemcpyDeviceToDevice);

    // 7) dense GCN layers
    for (int l = 0; l < LLAYERS; l++) {
        dim3 gsmall((DDIM + BN - 1) / BN, (n + BM - 1) / BM);
        sgemm_kernel<0, 0, false><<<gsmall, blk>>>(ptD, gnn0_W + (size_t)l * DDIM * DDIM,
                                                   pxw, nullptr, n, DDIM, DDIM,
                                                   DDIM, DDIM, DDIM);
        scale_rows_kernel<<<(ND + TPB - 1) / TPB, blk>>>(pY, pxw, pdis, n, DDIM);
        // Z2 = G^T @ Y   (TN: A = pred_g [n,n], op A^T)
        sgemm_kernel<1, 0, false><<<gsmall, blk>>>(out_pred, pY, pZ2, nullptr,
                                                   n, DDIM, n, n, DDIM, DDIM);
        dense_combine_kernel<<<(ND + TPB - 1) / TPB, blk>>>(ptD, pZ2, pxw, pdis,
                                                            gnn0_b + (size_t)l * DDIM,
                                                            n, DDIM);
    }

    // 8) sparse graph normalization
    fill_kernel<<<(n + TPB - 1) / TPB, blk>>>(pdeg2, 1.0f, n);
    edge_deg_kernel<<<(E + TPB - 1) / TPB, blk>>>(eidx + E, eattr, pdeg2, E);
    rsqrt_kernel<<<(n + TPB - 1) / TPB, blk>>>(pdis2, pdeg2, n);
    enorm_kernel<<<(E + TPB - 1) / TPB, blk>>>(eidx, eidx + E, eattr, pdis2, pen, E);

    // 9) sparse GCN layers
    for (int l = 0; l < LLAYERS; l++) {
        dim3 gsmall((DDIM + BN - 1) / BN, (n + BM - 1) / BM);
        sgemm_kernel<0, 0, false><<<gsmall, blk>>>(ptS, gnn1_W + (size_t)l * DDIM * DDIM,
                                                   pxw, nullptr, n, DDIM, DDIM,
                                                   DDIM, DDIM, DDIM);
        fill_kernel<<<(ND + TPB - 1) / TPB, blk>>>(pZ2, 0.0f, ND);
        {
            int warps_needed = E;
            int blocks = (warps_needed * 32 + TPB - 1) / TPB;
            scatter_kernel<<<blocks, blk>>>(pxw, eidx, eidx + E, pen, pZ2, E, DDIM);
        }
        sparse_combine_kernel<<<(ND + TPB - 1) / TPB, blk>>>(ptS, pZ2, pxw, pdis2,
                                                             gnn1_b + (size_t)l * DDIM,
                                                             n, DDIM);
    }

    // 10) outputs: emb1 passthrough, skill = dense + sparse
    cudaMemcpyAsync(out_emb1, emb1, (size_t)ND * sizeof(float), cudaMemcpyDeviceToDevice);
    add_kernel<<<(ND + TPB - 1) / TPB, blk>>>(out_skill, ptD, ptS, ND);
}

// round 2
// speedup vs baseline: 3.7077x; 3.7077x over previous
#include <cuda_runtime.h>
#include <cuda_bf16.h>
#include <math.h>

// Problem constants (shapes fixed by the dataset)
#define NNODE 8000
#define DDIM  256
#define K3    768      // 3*D for the fuse GEMM
#define EMAX  256000
#define LLAYERS 2
#define PRESERVE_F 0.1f
// softmax rows sum to 1 => at most 4 entries per row exceed 0.2 => nnz <= 4*N
#define MAXNNZ (4 * NNODE)

// ---------------- scratch (static device memory; no allocation allowed) ---------
__device__ float g_X3[NNODE * K3];        // concat(emb1, demand_last, supply_last)
__device__ float g_U [NNODE * DDIM];      // update_emb
__device__ float g_tmpD[NNODE * DDIM];    // dense GCN running temp
__device__ float g_tmpS[NNODE * DDIM];    // sparse GCN running temp
__device__ float g_xw [NNODE * DDIM];
__device__ float g_Z2 [NNODE * DDIM];     // agg buffer (dense + sparse paths)
__device__ float g_deg [NNODE];
__device__ float g_dis [NNODE];
__device__ float g_deg2[NNODE];
__device__ float g_dis2[NNODE];
__device__ float g_enorm[EMAX];
__device__ int   g_nnz;
__device__ int   g_sp_r[MAXNNZ];
__device__ int   g_sp_c[MAXNNZ];
__device__ float g_sp_v[MAXNNZ];

// ---------------- generic fp32 SGEMM: 128x128x8, 8x8 per thread -----------------
#define BM 128
#define BN 128
#define BK 8
#define TM 8
#define TN 8

template<int TRA, int TRB, bool BIAS>
__global__ __launch_bounds__(256, 2)
void sgemm_kernel(const float* __restrict__ A, const float* __restrict__ B,
                  float* __restrict__ C, const float* __restrict__ bias,
                  int M, int N, int K, int lda, int ldb, int ldc)
{
    __shared__ float As[BK][BM];
    __shared__ float Bs[BK][BN];

    const int tid = threadIdx.x;
    const int m0  = blockIdx.y * BM;
    const int n0  = blockIdx.x * BN;
    const int ty  = tid >> 4;     // 0..15
    const int tx  = tid & 15;     // 0..15

    float acc[TM][TN];
#pragma unroll
    for (int i = 0; i < TM; i++)
#pragma unroll
        for (int j = 0; j < TN; j++) acc[i][j] = 0.f;

    for (int k0 = 0; k0 < K; k0 += BK) {
        // ---- load A tile -> As[k][m]
        if (TRA == 0) {
            int r  = tid >> 1;
            int c4 = (tid & 1) * 4;
            int gm = m0 + r;
            float4 v = make_float4(0.f, 0.f, 0.f, 0.f);
            if (gm < M)
                v = *reinterpret_cast<const float4*>(A + (size_t)gm * lda + k0 + c4);
            As[c4 + 0][r] = v.x; As[c4 + 1][r] = v.y;
            As[c4 + 2][r] = v.z; As[c4 + 3][r] = v.w;
        } else {
            int rr  = tid >> 5;
            int cc4 = (tid & 31) * 4;
            int gm  = m0 + cc4;
            float4 v = make_float4(0.f, 0.f, 0.f, 0.f);
            if (gm < M)
                v = *reinterpret_cast<const float4*>(A + (size_t)(k0 + rr) * lda + gm);
            As[rr][cc4 + 0] = v.x; As[rr][cc4 + 1] = v.y;
            As[rr][cc4 + 2] = v.z; As[rr][cc4 + 3] = v.w;
        }
        // ---- load B tile -> Bs[k][n]
        if (TRB == 0) {
            int rr  = tid >> 5;
            int cc4 = (tid & 31) * 4;
            int gn  = n0 + cc4;
            float4 v = make_float4(0.f, 0.f, 0.f, 0.f);
            if (gn < N)
                v = *reinterpret_cast<const float4*>(B + (size_t)(k0 + rr) * ldb + gn);
            Bs[rr][cc4 + 0] = v.x; Bs[rr][cc4 + 1] = v.y;
            Bs[rr][cc4 + 2] = v.z; Bs[rr][cc4 + 3] = v.w;
        } else {
            int r  = tid >> 1;
            int c4 = (tid & 1) * 4;
            int gn = n0 + r;
            float4 v = make_float4(0.f, 0.f, 0.f, 0.f);
            if (gn < N)
                v = *reinterpret_cast<const float4*>(B + (size_t)gn * ldb + k0 + c4);
            Bs[c4 + 0][r] = v.x; Bs[c4 + 1][r] = v.y;
            Bs[c4 + 2][r] = v.z; Bs[c4 + 3][r] = v.w;
        }
        __syncthreads();

#pragma unroll
        for (int kk = 0; kk < BK; kk++) {
            float a[TM], b[TN];
#pragma unroll
            for (int i = 0; i < TM; i++) a[i] = As[kk][ty * TM + i];
#pragma unroll
            for (int j = 0; j < TN; j++) b[j] = Bs[kk][tx * TN + j];
#pragma unroll
            for (int i = 0; i < TM; i++)
#pragma unroll
                for (int j = 0; j < TN; j++)
                    acc[i][j] = fmaf(a[i], b[j], acc[i][j]);
        }
        __syncthreads();
    }

#pragma unroll
    for (int i = 0; i < TM; i++) {
        int gm = m0 + ty * TM + i;
        if (gm >= M) continue;
#pragma unroll
        for (int j = 0; j < TN; j++) {
            int gn = n0 + tx * TN + j;
            if (gn < N) {
                float v = acc[i][j];
                if (BIAS) v += bias[gn];
                C[(size_t)gm * ldc + gn] = v;
            }
        }
    }
}

// ---------------- symmetric rank-k: C = U @ U^T (only lower-tri blocks computed,
// mirrored into the upper triangle). ----------------------------------------------
__global__ __launch_bounds__(256, 2)
void syrk_kernel(const float* __restrict__ U, float* __restrict__ C, int Mn, int K)
{
    if (blockIdx.y < blockIdx.x) return;    // keep m0 >= n0

    __shared__ float As[BK][BM];
    __shared__ float Bs[BK][BN];

    const int tid = threadIdx.x;
    const int m0  = blockIdx.y * BM;
    const int n0  = blockIdx.x * BN;
    const int ty  = tid >> 4;
    const int tx  = tid & 15;

    float acc[TM][TN];
#pragma unroll
    for (int i = 0; i < TM; i++)
#pragma unroll
        for (int j = 0; j < TN; j++) acc[i][j] = 0.f;

    for (int k0 = 0; k0 < K; k0 += BK) {
        {   // A tile: U rows m0..m0+127
            int r  = tid >> 1;
            int c4 = (tid & 1) * 4;
            int gm = m0 + r;
            float4 v = make_float4(0.f, 0.f, 0.f, 0.f);
            if (gm < Mn)
                v = *reinterpret_cast<const float4*>(U + (size_t)gm * K + k0 + c4);
            As[c4 + 0][r] = v.x; As[c4 + 1][r] = v.y;
            As[c4 + 2][r] = v.z; As[c4 + 3][r] = v.w;
        }
        {   // B tile: U rows n0..n0+127 (op B^T)
            int r  = tid >> 1;
            int c4 = (tid & 1) * 4;
            int gn = n0 + r;
            float4 v = make_float4(0.f, 0.f, 0.f, 0.f);
            if (gn < Mn)
                v = *reinterpret_cast<const float4*>(U + (size_t)gn * K + k0 + c4);
            Bs[c4 + 0][r] = v.x; Bs[c4 + 1][r] = v.y;
            Bs[c4 + 2][r] = v.z; Bs[c4 + 3][r] = v.w;
        }
        __syncthreads();

#pragma unroll
        for (int kk = 0; kk < BK; kk++) {
            float a[TM], b[TN];
#pragma unroll
            for (int i = 0; i < TM; i++) a[i] = As[kk][ty * TM + i];
#pragma unroll
            for (int j = 0; j < TN; j++) b[j] = Bs[kk][tx * TN + j];
#pragma unroll
            for (int i = 0; i < TM; i++)
#pragma unroll
                for (int j = 0; j < TN; j++)
                    acc[i][j] = fmaf(a[i], b[j], acc[i][j]);
        }
        __syncthreads();
    }

    // normal write C[gm][gn]
#pragma unroll
    for (int i = 0; i < TM; i++) {
        int gm = m0 + ty * TM + i;
        if (gm >= Mn) continue;
#pragma unroll
        for (int j = 0; j < TN; j++) {
            int gn = n0 + tx * TN + j;
            if (gn < Mn)
                C[(size_t)gm * Mn + gn] = acc[i][j];
        }
    }
    // mirror write C[gn][gm] (float4 along i)
#pragma unroll
    for (int j = 0; j < TN; j++) {
        int gn = n0 + tx * TN + j;
        if (gn >= Mn) continue;
#pragma unroll
        for (int h = 0; h < TM / 4; h++) {
            int gm = m0 + ty * TM + h * 4;
            if (gm + 3 < Mn) {
                float4 v = make_float4(acc[h * 4 + 0][j], acc[h * 4 + 1][j],
                                       acc[h * 4 + 2][j], acc[h * 4 + 3][j]);
                *reinterpret_cast<float4*>(C + (size_t)gn * Mn + gm) = v;
            } else {
                for (int q = 0; q < 4; q++)
                    if (gm + q < Mn)
                        C[(size_t)gn * Mn + gm + q] = acc[h * 4 + q][j];
            }
        }
    }
}

// ---------------- small kernels --------------------------------------------------

__global__ void gather_x3_kernel(const float* __restrict__ emb1,
                                 const float* __restrict__ demand,
                                 const float* __restrict__ supply,
                                 float* __restrict__ X3, int n, int T)
{
    int i = blockIdx.x * blockDim.x + threadIdx.x;
    int total = n * DDIM;
    if (i >= total) return;
    int node = i / DDIM, d = i % DDIM;
    float* row = X3 + (size_t)node * K3;
    row[d]            = emb1[(size_t)node * DDIM + d];
    row[DDIM + d]     = demand[((size_t)node * T + (T - 1)) * DDIM + d];
    row[2 * DDIM + d] = supply[((size_t)node * T + (T - 1)) * DDIM + d];
}

// one block per row: in-place  Z -> relu(softmax(Z) - 0.2), and emit nonzeros
// into a global sparse list (+ accumulate column degrees).
__global__ void softmax_relu_kernel(float* __restrict__ Z, int n,
                                    int* __restrict__ nnz,
                                    int* __restrict__ sr, int* __restrict__ sc,
                                    float* __restrict__ sv,
                                    float* __restrict__ deg)
{
    __shared__ float row[NNODE];
    __shared__ float red[256];
    int r = blockIdx.x;
    int t = threadIdx.x;
    float* zr = Z + (size_t)r * n;

    float mx = -3.4e38f;
    for (int c = t; c < n; c += 256) {
        float v = zr[c];
        row[c] = v;
        mx = fmaxf(mx, v);
    }
    red[t] = mx; __syncthreads();
    for (int s = 128; s > 0; s >>= 1) {
        if (t < s) red[t] = fmaxf(red[t], red[t + s]);
        __syncthreads();
    }
    mx = red[0];
    __syncthreads();

    float sm = 0.f;
    for (int c = t; c < n; c += 256) {
        float e = expf(row[c] - mx);
        row[c] = e;
        sm += e;
    }
    red[t] = sm; __syncthreads();
    for (int s = 128; s > 0; s >>= 1) {
        if (t < s) red[t] += red[t + s];
        __syncthreads();
    }
    float inv = 1.0f / red[0];
    for (int c = t; c < n; c += 256) {
        float p = row[c] * inv - 0.2f;
        p = p > 0.f ? p : 0.f;
        zr[c] = p;
        if (p > 0.f) {
            int idx = atomicAdd(nnz, 1);
            if (idx < MAXNNZ) {
                sr[idx] = r; sc[idx] = c; sv[idx] = p;
            }
            atomicAdd(&deg[c], p);
        }
    }
}

__global__ void fill_kernel(float* p, float v, int n)
{
    int i = blockIdx.x * blockDim.x + threadIdx.x;
    if (i < n) p[i] = v;
}

__global__ void zero_int_kernel(int* p) { *p = 0; }

__global__ void rsqrt_kernel(float* __restrict__ dst, const float* __restrict__ src, int n)
{
    int i = blockIdx.x * blockDim.x + threadIdx.x;
    if (i < n) dst[i] = rsqrtf(src[i]);
}

// warp per nonzero of G: agg[c] += G[r,c] * dis[r] * xw[r]
__global__ void dense_scatter_kernel(const float* __restrict__ xw,
                                     const int* __restrict__ sr,
                                     const int* __restrict__ sc,
                                     const float* __restrict__ sv,
                                     const float* __restrict__ dis,
                                     float* __restrict__ agg,
                                     const int* __restrict__ nnz)
{
    int warp = (blockIdx.x * blockDim.x + threadIdx.x) >> 5;
    int lane = threadIdx.x & 31;
    int m = *nnz; if (m > MAXNNZ) m = MAXNNZ;
    if (warp >= m) return;
    int r = sr[warp], c = sc[warp];
    float w = sv[warp] * dis[r];
    const float* xr = xw + (size_t)r * DDIM;
    float* ar = agg + (size_t)c * DDIM;
    for (int f = lane; f < DDIM; f += 32)
        atomicAdd(&ar[f], w * xr[f]);
}

// temp = 0.9*(dis[c]*Z2 + dis[c]^2*xw + b) + 0.1*temp
__global__ void dense_combine_kernel(float* __restrict__ temp, const float* __restrict__ Z2,
                                     const float* __restrict__ xw, const float* __restrict__ dis,
                                     const float* __restrict__ b, int n, int d)
{
    int i = blockIdx.x * blockDim.x + threadIdx.x;
    if (i >= n * d) return;
    int c = i / d, dd = i - c * d;
    float s = dis[c];
    float out = s * Z2[i] + s * s * xw[i] + b[dd];
    temp[i] = (1.0f - PRESERVE_F) * out + PRESERVE_F * temp[i];
}

__global__ void edge_deg_kernel(const int* __restrict__ dst, const float* __restrict__ attr,
                                float* __restrict__ deg2, int E)
{
    int e = blockIdx.x * blockDim.x + threadIdx.x;
    if (e < E) atomicAdd(&deg2[dst[e]], attr[e]);
}

__global__ void enorm_kernel(const int* __restrict__ src, const int* __restrict__ dst,
                             const float* __restrict__ attr, const float* __restrict__ dis2,
                             float* __restrict__ enorm, int E)
{
    int e = blockIdx.x * blockDim.x + threadIdx.x;
    if (e < E) enorm[e] = dis2[src[e]] * attr[e] * dis2[dst[e]];
}

// warp per edge: agg[dst] += enorm * xw[src]
__global__ void scatter_kernel(const float* __restrict__ xw, const int* __restrict__ src,
                               const int* __restrict__ dst, const float* __restrict__ enorm,
                               float* __restrict__ agg, int E, int d)
{
    int warp = (blockIdx.x * blockDim.x + threadIdx.x) >> 5;
    int lane = threadIdx.x & 31;
    if (warp >= E) return;
    int s = src[warp], t = dst[warp];
    float w = enorm[warp];
    const float* xr = xw + (size_t)s * d;
    float* ar = agg + (size_t)t * d;
    for (int f = lane; f < d; f += 32)
        atomicAdd(&ar[f], w * xr[f]);
}

// temp = 0.9*(agg + dis2[c]^2*xw + b) + 0.1*temp
__global__ void sparse_combine_kernel(float* __restrict__ temp, const float* __restrict__ agg,
                                      const float* __restrict__ xw, const float* __restrict__ dis2,
                                      const float* __restrict__ b, int n, int d)
{
    int i = blockIdx.x * blockDim.x + threadIdx.x;
    if (i >= n * d) return;
    int c = i / d, dd = i - c * d;
    float s = dis2[c];
    float out = agg[i] + s * s * xw[i] + b[dd];
    temp[i] = (1.0f - PRESERVE_F) * out + PRESERVE_F * temp[i];
}

__global__ void add_kernel(float* __restrict__ out, const float* __restrict__ a,
                           const float* __restrict__ b, int n)
{
    int i = blockIdx.x * blockDim.x + threadIdx.x;
    if (i < n) out[i] = a[i] + b[i];
}

// ---------------- host orchestration ---------------------------------------------

extern "C" void kernel_launch(void* const* d_in, const int* in_sizes, int n_in,
                              void* d_out, int out_size)
{
    const float* demand  = (const float*)d_in[0];
    const float* supply  = (const float*)d_in[1];
    const int*   eidx    = (const int*)  d_in[2];
    const float* eattr   = (const float*)d_in[3];
    const float* emb1    = (const float*)d_in[4];
    const float* fuse_W  = (const float*)d_in[5];
    const float* fuse_b  = (const float*)d_in[6];
    const float* gnn0_W  = (const float*)d_in[7];
    const float* gnn0_b  = (const float*)d_in[8];
    const float* gnn1_W  = (const float*)d_in[9];
    const float* gnn1_b  = (const float*)d_in[10];

    const int n = in_sizes[4] / DDIM;             // 8000
    const int E = in_sizes[3];                    // 256000
    const int T = in_sizes[0] / (n * DDIM);       // 16

    float* out_emb1  = (float*)d_out;
    float* out_skill = out_emb1 + (size_t)n * DDIM;
    float* out_pred  = out_skill + (size_t)n * DDIM;   // also logits scratch

    float *pX3, *pU, *ptD, *ptS, *pxw, *pZ2, *pdeg, *pdis, *pdeg2, *pdis2, *pen, *psv;
    int *pnnz, *psr, *psc;
    cudaGetSymbolAddress((void**)&pX3,  g_X3);
    cudaGetSymbolAddress((void**)&pU,   g_U);
    cudaGetSymbolAddress((void**)&ptD,  g_tmpD);
    cudaGetSymbolAddress((void**)&ptS,  g_tmpS);
    cudaGetSymbolAddress((void**)&pxw,  g_xw);
    cudaGetSymbolAddress((void**)&pZ2,  g_Z2);
    cudaGetSymbolAddress((void**)&pdeg, g_deg);
    cudaGetSymbolAddress((void**)&pdis, g_dis);
    cudaGetSymbolAddress((void**)&pdeg2,g_deg2);
    cudaGetSymbolAddress((void**)&pdis2,g_dis2);
    cudaGetSymbolAddress((void**)&pen,  g_enorm);
    cudaGetSymbolAddress((void**)&pnnz, g_nnz);
    cudaGetSymbolAddress((void**)&psr,  g_sp_r);
    cudaGetSymbolAddress((void**)&psc,  g_sp_c);
    cudaGetSymbolAddress((void**)&psv,  g_sp_v);

    const int ND = n * DDIM;
    const int TPB = 256;
    dim3 blk(TPB);

    // 1) gather [emb1 | demand_last | supply_last]
    gather_x3_kernel<<<(ND + TPB - 1) / TPB, blk>>>(emb1, demand, supply, pX3, n, T);

    // 2) update_emb = X3 @ fuse_W + fuse_b     [n, 256]
    {
        dim3 grid((DDIM + BN - 1) / BN, (n + BM - 1) / BM);
        sgemm_kernel<0, 0, true><<<grid, blk>>>(pX3, fuse_W, pU, fuse_b,
                                                n, DDIM, K3, K3, DDIM, DDIM);
    }

    // 3) logits Z = U @ U^T  -> out_pred (scratch); symmetric: lower blocks + mirror
    {
        dim3 grid((n + BN - 1) / BN, (n + BM - 1) / BM);
        syrk_kernel<<<grid, blk>>>(pU, out_pred, n, DDIM);
    }

    // 4) prep for sparse emit: deg=1 (self loop), nnz=0
    fill_kernel<<<(n + TPB - 1) / TPB, blk>>>(pdeg, 1.0f, n);
    zero_int_kernel<<<1, 1>>>(pnnz);

    // 5) in-place row softmax + relu(.-0.2) -> pred_g; emits nonzeros + degrees
    softmax_relu_kernel<<<n, blk>>>(out_pred, n, pnnz, psr, psc, psv, pdeg);
    rsqrt_kernel<<<(n + TPB - 1) / TPB, blk>>>(pdis, pdeg, n);

    // 6) temps start at update_emb
    cudaMemcpyAsync(ptD, pU, (size_t)ND * sizeof(float), cudaMemcpyDeviceToDevice);
    cudaMemcpyAsync(ptS, pU, (size_t)ND * sizeof(float), cudaMemcpyDeviceToDevice);

    // 7) dense GCN layers via the (provably <= 4n nonzero) sparse form of pred_g
    for (int l = 0; l < LLAYERS; l++) {
        dim3 gsmall((DDIM + BN - 1) / BN, (n + BM - 1) / BM);
        sgemm_kernel<0, 0, false><<<gsmall, blk>>>(ptD, gnn0_W + (size_t)l * DDIM * DDIM,
                                                   pxw, nullptr, n, DDIM, DDIM,
                                                   DDIM, DDIM, DDIM);
        fill_kernel<<<(ND + TPB - 1) / TPB, blk>>>(pZ2, 0.0f, ND);
        {
            int blocks = (MAXNNZ * 32 + TPB - 1) / TPB;
            dense_scatter_kernel<<<blocks, blk>>>(pxw, psr, psc, psv, pdis, pZ2, pnnz);
        }
        dense_combine_kernel<<<(ND + TPB - 1) / TPB, blk>>>(ptD, pZ2, pxw, pdis,
                                                            gnn0_b + (size_t)l * DDIM,
                                                            n, DDIM);
    }

    // 8) sparse graph normalization
    fill_kernel<<<(n + TPB - 1) / TPB, blk>>>(pdeg2, 1.0f, n);
    edge_deg_kernel<<<(E + TPB - 1) / TPB, blk>>>(eidx + E, eattr, pdeg2, E);
    rsqrt_kernel<<<(n + TPB - 1) / TPB, blk>>>(pdis2, pdeg2, n);
    enorm_kernel<<<(E + TPB - 1) / TPB, blk>>>(eidx, eidx + E, eattr, pdis2, pen, E);

    // 9) sparse GCN layers
    for (int l = 0; l < LLAYERS; l++) {
        dim3 gsmall((DDIM + BN - 1) / BN, (n + BM - 1) / BM);
        sgemm_kernel<0, 0, false><<<gsmall, blk>>>(ptS, gnn1_W + (size_t)l * DDIM * DDIM,
                                                   pxw, nullptr, n, DDIM, DDIM,
                                                   DDIM, DDIM, DDIM);
        fill_kernel<<<(ND + TPB - 1) / TPB, blk>>>(pZ2, 0.0f, ND);
        {
            int blocks = (E * 32 + TPB - 1) / TPB;
            scatter_kernel<<<blocks, blk>>>(pxw, eidx, eidx + E, pen, pZ2, E, DDIM);
        }
        sparse_combine_kernel<<<(ND + TPB - 1) / TPB, blk>>>(ptS, pZ2, pxw, pdis2,
                                                             gnn1_b + (size_t)l * DDIM,
                                                             n, DDIM);
    }

    // 10) outputs: emb1 passthrough, skill = dense + sparse
    cudaMemcpyAsync(out_emb1, emb1, (size_t)ND * sizeof(float), cudaMemcpyDeviceToDevice);
    add_kernel<<<(ND + TPB - 1) / TPB, blk>>>(out_skill, ptD, ptS, ND);
}

// round 4
// speedup vs baseline: 3.8135x; 1.0285x over previous
#include <cuda_runtime.h>
#include <cuda_bf16.h>
#include <math.h>
#include <stdint.h>

// Problem constants (shapes fixed by the dataset)
#define NNODE 8000
#define DDIM  256
#define K3    768      // 3*D for the fuse GEMM
#define EMAX  256000
#define LLAYERS 2
#define PRESERVE_F 0.1f
// softmax rows sum to 1 => at most 4 entries per row exceed 0.2 => nnz <= 4*N
#define MAXNNZ (4 * NNODE)

// ---------------- scratch (static device memory; no allocation allowed) ---------
__device__ float g_X3[NNODE * K3];
__device__ float g_U [NNODE * DDIM];
__device__ float g_tmpD[NNODE * DDIM];
__device__ float g_tmpS[NNODE * DDIM];
__device__ float g_xw [NNODE * DDIM];
__device__ float g_Z2 [NNODE * DDIM];
__device__ float g_deg [NNODE];
__device__ float g_dis [NNODE];
__device__ float g_deg2[NNODE];
__device__ float g_dis2[NNODE];
__device__ float g_enorm[EMAX];
__device__ int   g_nnz;
__device__ int   g_sp_r[MAXNNZ];
__device__ int   g_sp_c[MAXNNZ];
__device__ float g_sp_v[MAXNNZ];
// 3-way bf16 split of U for tensor-core syrk
__device__ __nv_bfloat16 g_Uh[NNODE * DDIM];
__device__ __nv_bfloat16 g_Um[NNODE * DDIM];
__device__ __nv_bfloat16 g_Ul[NNODE * DDIM];

__device__ __forceinline__ uint32_t smem_u32(const void* p) {
    uint32_t a;
    asm("{ .reg .u64 t; cvta.to.shared.u64 t, %1; cvt.u32.u64 %0, t; }" : "=r"(a) : "l"(p));
    return a;
}

#define LDSM_X4(r0, r1, r2, r3, addr) \
    asm volatile("ldmatrix.sync.aligned.m8n8.x4.shared.b16 {%0,%1,%2,%3}, [%4];" \
                 : "=r"(r0), "=r"(r1), "=r"(r2), "=r"(r3) : "r"(addr))
#define LDSM_X2(r0, r1, addr) \
    asm volatile("ldmatrix.sync.aligned.m8n8.x2.shared.b16 {%0,%1}, [%2];" \
                 : "=r"(r0), "=r"(r1) : "r"(addr))
#define MMA_BF16(c, a0, a1, a2, a3, b0, b1) \
    asm volatile("mma.sync.aligned.m16n8k16.row.col.f32.bf16.bf16.f32 " \
                 "{%0,%1,%2,%3}, {%4,%5,%6,%7}, {%8,%9}, {%0,%1,%2,%3};" \
                 : "+f"((c)[0]), "+f"((c)[1]), "+f"((c)[2]), "+f"((c)[3]) \
                 : "r"(a0), "r"(a1), "r"(a2), "r"(a3), "r"(b0), "r"(b1))

// =================== warp-MMA symmetric logits GEMM ===============================
// C = U @ U^T via 3-way bf16 split (hi/mid/lo), 6 split-pair segments accumulated
// in fp32 warp-mma accumulators. Lower-triangular 128x128 tiles only; off-diagonal
// tiles are mirrored through an smem transpose so all global writes coalesce.
#define LDT 40                                   // smem tile stride in bf16 (80 B)
#define SYRK_TILE_BYTES (128 * LDT * 2)          // one tile buffer
#define SYRK_SMEM_DYN   (128 * 129 * 4)          // 66048 B (>= 2*tile bytes)

__global__ __launch_bounds__(256)
void syrk_mma_kernel(const __nv_bfloat16* __restrict__ Uh,
                     const __nv_bfloat16* __restrict__ Um,
                     const __nv_bfloat16* __restrict__ Ul,
                     float* __restrict__ C, int n)
{
    extern __shared__ char smem[];
    __nv_bfloat16* As = (__nv_bfloat16*)smem;
    __nv_bfloat16* Bs = As + 128 * LDT;
    float* epi = (float*)smem;                   // reused after mainloop

    const int tid  = threadIdx.x;
    const int wid  = tid >> 5;
    const int lane = tid & 31;
    const int wm   = wid & 1;                    // warp row (2 x 64)
    const int wn   = wid >> 1;                   // warp col (4 x 32)
    const int group = lane >> 2;
    const int tig   = lane & 3;

    // decode linear lower-tri tile index -> (bi, bj), bi >= bj
    int t = blockIdx.x;
    int bi = (int)((sqrtf(8.0f * (float)t + 1.0f) - 1.0f) * 0.5f);
    while ((bi + 1) * (bi + 2) / 2 <= t) bi++;
    while (bi * (bi + 1) / 2 > t) bi--;
    int bj = t - bi * (bi + 1) / 2;
    const int m0 = bi * 128;
    const int n0 = bj * 128;

    float acc[4][4][4];
#pragma unroll
    for (int a = 0; a < 4; a++)
#pragma unroll
        for (int b = 0; b < 4; b++)
#pragma unroll
            for (int c = 0; c < 4; c++) acc[a][b][c] = 0.f;

    const __nv_bfloat16* segA[6] = { Uh, Uh, Um, Uh, Ul, Um };
    const __nv_bfloat16* segB[6] = { Uh, Um, Uh, Ul, Uh, Um };

    const uint32_t sA = smem_u32(As);
    const uint32_t sB = smem_u32(Bs);

    // precomputed ldmatrix lane addressing
    const int a_row = (lane & 15);
    const int a_col = (lane >> 4) * 8;
    const int b_row = (lane & 7);
    const int b_col = ((lane >> 3) & 1) * 8;

#pragma unroll 1
    for (int p = 0; p < 6; p++) {
        const __nv_bfloat16* Aseg = segA[p];
        const __nv_bfloat16* Bseg = segB[p];
#pragma unroll 1
        for (int k0 = 0; k0 < DDIM; k0 += 32) {
            // ---- load 128x32 A and B tiles (16B per thread per buffer per iter)
#pragma unroll
            for (int it = 0; it < 2; it++) {
                int lin = it * 256 + tid;          // 0..511
                int r   = lin >> 2;
                int c8  = (lin & 3) * 8;
                int ga  = m0 + r;
                uint4 va = make_uint4(0u, 0u, 0u, 0u);
                if (ga < n)
                    va = *reinterpret_cast<const uint4*>(Aseg + (size_t)ga * DDIM + k0 + c8);
                *reinterpret_cast<uint4*>(As + r * LDT + c8) = va;
                int gb  = n0 + r;
                uint4 vb = make_uint4(0u, 0u, 0u, 0u);
                if (gb < n)
                    vb = *reinterpret_cast<const uint4*>(Bseg + (size_t)gb * DDIM + k0 + c8);
                *reinterpret_cast<uint4*>(Bs + r * LDT + c8) = vb;
            }
            __syncthreads();

#pragma unroll
            for (int ks = 0; ks < 2; ks++) {
                const int kk = ks * 16;
                uint32_t a[4][4], b[4][2];
#pragma unroll
                for (int mt = 0; mt < 4; mt++) {
                    int row = wm * 64 + mt * 16 + a_row;
                    uint32_t addr = sA + (uint32_t)(row * LDT + kk + a_col) * 2;
                    LDSM_X4(a[mt][0], a[mt][1], a[mt][2], a[mt][3], addr);
                }
#pragma unroll
                for (int nt = 0; nt < 4; nt++) {
                    int row = wn * 32 + nt * 8 + b_row;
                    uint32_t addr = sB + (uint32_t)(row * LDT + kk + b_col) * 2;
                    LDSM_X2(b[nt][0], b[nt][1], addr);
                }
#pragma unroll
                for (int mt = 0; mt < 4; mt++)
#pragma unroll
                    for (int nt = 0; nt < 4; nt++)
                        MMA_BF16(acc[mt][nt], a[mt][0], a[mt][1], a[mt][2], a[mt][3],
                                 b[nt][0], b[nt][1]);
            }
            __syncthreads();
        }
    }

    // ---- direct write C[m0.., n0..] (float2, coalesced in 32B groups)
#pragma unroll
    for (int mt = 0; mt < 4; mt++) {
#pragma unroll
        for (int nt = 0; nt < 4; nt++) {
            int lm = wm * 64 + mt * 16 + group;
            int ln = wn * 32 + nt * 8 + tig * 2;
            int gm = m0 + lm, gn = n0 + ln;
            if (gn + 1 < n) {
                if (gm < n)
                    *reinterpret_cast<float2*>(C + (size_t)gm * n + gn) =
                        make_float2(acc[mt][nt][0], acc[mt][nt][1]);
                if (gm + 8 < n)
                    *reinterpret_cast<float2*>(C + (size_t)(gm + 8) * n + gn) =
                        make_float2(acc[mt][nt][2], acc[mt][nt][3]);
            }
        }
    }

    // ---- mirrored write via smem transpose (off-diagonal tiles only)
    if (bi != bj) {
        __syncthreads();   // done with As/Bs, reuse as epi
#pragma unroll
        for (int mt = 0; mt < 4; mt++) {
#pragma unroll
            for (int nt = 0; nt < 4; nt++) {
                int lm = wm * 64 + mt * 16 + group;
                int ln = wn * 32 + nt * 8 + tig * 2;
                epi[lm * 129 + ln]           = acc[mt][nt][0];
                epi[lm * 129 + ln + 1]       = acc[mt][nt][1];
                epi[(lm + 8) * 129 + ln]     = acc[mt][nt][2];
                epi[(lm + 8) * 129 + ln + 1] = acc[mt][nt][3];
            }
        }
        __syncthreads();
        const int c_row = tid >> 1;          // 0..127 -> mirror output row n0+c_row
        const int half  = tid & 1;
        const int grow  = n0 + c_row;
        if (grow < n) {
            float* outrow = C + (size_t)grow * n;
#pragma unroll
            for (int i = 0; i < 16; i++) {
                int ml = half * 64 + i * 4;
                if (m0 + ml + 3 < n) {
                    float4 v = make_float4(epi[(ml + 0) * 129 + c_row],
                                           epi[(ml + 1) * 129 + c_row],
                                           epi[(ml + 2) * 129 + c_row],
                                           epi[(ml + 3) * 129 + c_row]);
                    *reinterpret_cast<float4*>(outrow + m0 + ml) = v;
                } else {
                    for (int q = 0; q < 4; q++)
                        if (m0 + ml + q < n)
                            outrow[m0 + ml + q] = epi[(ml + q) * 129 + c_row];
                }
            }
        }
    }
}

// split U (fp32) into 3 bf16 components: x ~= hi + mid + lo
__global__ void split_bf16_kernel(const float* __restrict__ U,
                                  __nv_bfloat16* __restrict__ Uh,
                                  __nv_bfloat16* __restrict__ Um,
                                  __nv_bfloat16* __restrict__ Ul, int total)
{
    int i = blockIdx.x * blockDim.x + threadIdx.x;
    if (i >= total) return;
    float x = U[i];
    __nv_bfloat16 h = __float2bfloat16(x);
    float r = x - __bfloat162float(h);
    __nv_bfloat16 m = __float2bfloat16(r);
    float r2 = r - __bfloat162float(m);
    __nv_bfloat16 l = __float2bfloat16(r2);
    Uh[i] = h; Um[i] = m; Ul[i] = l;
}

// ---------------- generic fp32 SGEMM: 128x128x8, 8x8 per thread -----------------
#define BM 128
#define BN 128
#define BK 8
#define TM 8
#define TN 8

template<int TRA, int TRB, bool BIAS>
__global__ __launch_bounds__(256, 2)
void sgemm_kernel(const float* __restrict__ A, const float* __restrict__ B,
                  float* __restrict__ C, const float* __restrict__ bias,
                  int M, int N, int K, int lda, int ldb, int ldc)
{
    __shared__ float As[BK][BM];
    __shared__ float Bs[BK][BN];

    const int tid = threadIdx.x;
    const int m0  = blockIdx.y * BM;
    const int n0  = blockIdx.x * BN;
    const int ty  = tid >> 4;
    const int tx  = tid & 15;

    float acc[TM][TN];
#pragma unroll
    for (int i = 0; i < TM; i++)
#pragma unroll
        for (int j = 0; j < TN; j++) acc[i][j] = 0.f;

    for (int k0 = 0; k0 < K; k0 += BK) {
        if (TRA == 0) {
            int r  = tid >> 1;
            int c4 = (tid & 1) * 4;
            int gm = m0 + r;
            float4 v = make_float4(0.f, 0.f, 0.f, 0.f);
            if (gm < M)
                v = *reinterpret_cast<const float4*>(A + (size_t)gm * lda + k0 + c4);
            As[c4 + 0][r] = v.x; As[c4 + 1][r] = v.y;
            As[c4 + 2][r] = v.z; As[c4 + 3][r] = v.w;
        } else {
            int rr  = tid >> 5;
            int cc4 = (tid & 31) * 4;
            int gm  = m0 + cc4;
            float4 v = make_float4(0.f, 0.f, 0.f, 0.f);
            if (gm < M)
                v = *reinterpret_cast<const float4*>(A + (size_t)(k0 + rr) * lda + gm);
            As[rr][cc4 + 0] = v.x; As[rr][cc4 + 1] = v.y;
            As[rr][cc4 + 2] = v.z; As[rr][cc4 + 3] = v.w;
        }
        if (TRB == 0) {
            int rr  = tid >> 5;
            int cc4 = (tid & 31) * 4;
            int gn  = n0 + cc4;
            float4 v = make_float4(0.f, 0.f, 0.f, 0.f);
            if (gn < N)
                v = *reinterpret_cast<const float4*>(B + (size_t)(k0 + rr) * ldb + gn);
            Bs[rr][cc4 + 0] = v.x; Bs[rr][cc4 + 1] = v.y;
            Bs[rr][cc4 + 2] = v.z; Bs[rr][cc4 + 3] = v.w;
        } else {
            int r  = tid >> 1;
            int c4 = (tid & 1) * 4;
            int gn = n0 + r;
            float4 v = make_float4(0.f, 0.f, 0.f, 0.f);
            if (gn < N)
                v = *reinterpret_cast<const float4*>(B + (size_t)gn * ldb + k0 + c4);
            Bs[c4 + 0][r] = v.x; Bs[c4 + 1][r] = v.y;
            Bs[c4 + 2][r] = v.z; Bs[c4 + 3][r] = v.w;
        }
        __syncthreads();

#pragma unroll
        for (int kk = 0; kk < BK; kk++) {
            float a[TM], b[TN];
#pragma unroll
            for (int i = 0; i < TM; i++) a[i] = As[kk][ty * TM + i];
#pragma unroll
            for (int j = 0; j < TN; j++) b[j] = Bs[kk][tx * TN + j];
#pragma unroll
            for (int i = 0; i < TM; i++)
#pragma unroll
                for (int j = 0; j < TN; j++)
                    acc[i][j] = fmaf(a[i], b[j], acc[i][j]);
        }
        __syncthreads();
    }

#pragma unroll
    for (int i = 0; i < TM; i++) {
        int gm = m0 + ty * TM + i;
        if (gm >= M) continue;
#pragma unroll
        for (int j = 0; j < TN; j++) {
            int gn = n0 + tx * TN + j;
            if (gn < N) {
                float v = acc[i][j];
                if (BIAS) v += bias[gn];
                C[(size_t)gm * ldc + gn] = v;
            }
        }
    }
}

// ---------------- small kernels --------------------------------------------------

__global__ void gather_x3_kernel(const float* __restrict__ emb1,
                                 const float* __restrict__ demand,
                                 const float* __restrict__ supply,
                                 float* __restrict__ X3, int n, int T)
{
    int i = blockIdx.x * blockDim.x + threadIdx.x;
    int total = n * DDIM;
    if (i >= total) return;
    int node = i / DDIM, d = i % DDIM;
    float* row = X3 + (size_t)node * K3;
    row[d]            = emb1[(size_t)node * DDIM + d];
    row[DDIM + d]     = demand[((size_t)node * T + (T - 1)) * DDIM + d];
    row[2 * DDIM + d] = supply[((size_t)node * T + (T - 1)) * DDIM + d];
}

// one block per row: in-place  Z -> relu(softmax(Z) - 0.2), and emit nonzeros
__global__ void softmax_relu_kernel(float* __restrict__ Z, int n,
                                    int* __restrict__ nnz,
                                    int* __restrict__ sr, int* __restrict__ sc,
                                    float* __restrict__ sv,
                                    float* __restrict__ deg)
{
    __shared__ float row[NNODE];
    __shared__ float red[256];
    int r = blockIdx.x;
    int t = threadIdx.x;
    float* zr = Z + (size_t)r * n;

    float mx = -3.4e38f;
    for (int c = t; c < n; c += 256) {
        float v = zr[c];
        row[c] = v;
        mx = fmaxf(mx, v);
    }
    red[t] = mx; __syncthreads();
    for (int s = 128; s > 0; s >>= 1) {
        if (t < s) red[t] = fmaxf(red[t], red[t + s]);
        __syncthreads();
    }
    mx = red[0];
    __syncthreads();

    float sm = 0.f;
    for (int c = t; c < n; c += 256) {
        float e = expf(row[c] - mx);
        row[c] = e;
        sm += e;
    }
    red[t] = sm; __syncthreads();
    for (int s = 128; s > 0; s >>= 1) {
        if (t < s) red[t] += red[t + s];
        __syncthreads();
    }
    float inv = 1.0f / red[0];
    for (int c = t; c < n; c += 256) {
        float p = row[c] * inv - 0.2f;
        p = p > 0.f ? p : 0.f;
        zr[c] = p;
        if (p > 0.f) {
            int idx = atomicAdd(nnz, 1);
            if (idx < MAXNNZ) {
                sr[idx] = r; sc[idx] = c; sv[idx] = p;
            }
            atomicAdd(&deg[c], p);
        }
    }
}

__global__ void fill_kernel(float* p, float v, int n)
{
    int i = blockIdx.x * blockDim.x + threadIdx.x;
    if (i < n) p[i] = v;
}

__global__ void zero_int_kernel(int* p) { *p = 0; }

__global__ void rsqrt_kernel(float* __restrict__ dst, const float* __restrict__ src, int n)
{
    int i = blockIdx.x * blockDim.x + threadIdx.x;
    if (i < n) dst[i] = rsqrtf(src[i]);
}

// warp per nonzero of G: agg[c] += G[r,c] * dis[r] * xw[r]
__global__ void dense_scatter_kernel(const float* __restrict__ xw,
                                     const int* __restrict__ sr,
                                     const int* __restrict__ sc,
                                     const float* __restrict__ sv,
                                     const float* __restrict__ dis,
                                     float* __restrict__ agg,
                                     const int* __restrict__ nnz)
{
    int warp = (blockIdx.x * blockDim.x + threadIdx.x) >> 5;
    int lane = threadIdx.x & 31;
    int m = *nnz; if (m > MAXNNZ) m = MAXNNZ;
    if (warp >= m) return;
    int r = sr[warp], c = sc[warp];
    float w = sv[warp] * dis[r];
    const float* xr = xw + (size_t)r * DDIM;
    float* ar = agg + (size_t)c * DDIM;
    for (int f = lane; f < DDIM; f += 32)
        atomicAdd(&ar[f], w * xr[f]);
}

// temp = 0.9*(dis[c]*Z2 + dis[c]^2*xw + b) + 0.1*temp
__global__ void dense_combine_kernel(float* __restrict__ temp, const float* __restrict__ Z2,
                                     const float* __restrict__ xw, const float* __restrict__ dis,
                                     const float* __restrict__ b, int n, int d)
{
    int i = blockIdx.x * blockDim.x + threadIdx.x;
    if (i >= n * d) return;
    int c = i / d, dd = i - c * d;
    float s = dis[c];
    float out = s * Z2[i] + s * s * xw[i] + b[dd];
    temp[i] = (1.0f - PRESERVE_F) * out + PRESERVE_F * temp[i];
}

__global__ void edge_deg_kernel(const int* __restrict__ dst, const float* __restrict__ attr,
                                float* __restrict__ deg2, int E)
{
    int e = blockIdx.x * blockDim.x + threadIdx.x;
    if (e < E) atomicAdd(&deg2[dst[e]], attr[e]);
}

__global__ void enorm_kernel(const int* __restrict__ src, const int* __restrict__ dst,
                             const float* __restrict__ attr, const float* __restrict__ dis2,
                             float* __restrict__ enorm, int E)
{
    int e = blockIdx.x * blockDim.x + threadIdx.x;
    if (e < E) enorm[e] = dis2[src[e]] * attr[e] * dis2[dst[e]];
}

// warp per edge: agg[dst] += enorm * xw[src]
__global__ void scatter_kernel(const float* __restrict__ xw, const int* __restrict__ src,
                               const int* __restrict__ dst, const float* __restrict__ enorm,
                               float* __restrict__ agg, int E, int d)
{
    int warp = (blockIdx.x * blockDim.x + threadIdx.x) >> 5;
    int lane = threadIdx.x & 31;
    if (warp >= E) return;
    int s = src[warp], t = dst[warp];
    float w = enorm[warp];
    const float* xr = xw + (size_t)s * d;
    float* ar = agg + (size_t)t * d;
    for (int f = lane; f < d; f += 32)
        atomicAdd(&ar[f], w * xr[f]);
}

// temp = 0.9*(agg + dis2[c]^2*xw + b) + 0.1*temp
__global__ void sparse_combine_kernel(float* __restrict__ temp, const float* __restrict__ agg,
                                      const float* __restrict__ xw, const float* __restrict__ dis2,
                                      const float* __restrict__ b, int n, int d)
{
    int i = blockIdx.x * blockDim.x + threadIdx.x;
    if (i >= n * d) return;
    int c = i / d, dd = i - c * d;
    float s = dis2[c];
    float out = agg[i] + s * s * xw[i] + b[dd];
    temp[i] = (1.0f - PRESERVE_F) * out + PRESERVE_F * temp[i];
}

__global__ void add_kernel(float* __restrict__ out, const float* __restrict__ a,
                           const float* __restrict__ b, int n)
{
    int i = blockIdx.x * blockDim.x + threadIdx.x;
    if (i < n) out[i] = a[i] + b[i];
}

// ---------------- host orchestration ---------------------------------------------

extern "C" void kernel_launch(void* const* d_in, const int* in_sizes, int n_in,
                              void* d_out, int out_size)
{
    const float* demand  = (const float*)d_in[0];
    const float* supply  = (const float*)d_in[1];
    const int*   eidx    = (const int*)  d_in[2];
    const float* eattr   = (const float*)d_in[3];
    const float* emb1    = (const float*)d_in[4];
    const float* fuse_W  = (const float*)d_in[5];
    const float* fuse_b  = (const float*)d_in[6];
    const float* gnn0_W  = (const float*)d_in[7];
    const float* gnn0_b  = (const float*)d_in[8];
    const float* gnn1_W  = (const float*)d_in[9];
    const float* gnn1_b  = (const float*)d_in[10];

    const int n = in_sizes[4] / DDIM;             // 8000
    const int E = in_sizes[3];                    // 256000
    const int T = in_sizes[0] / (n * DDIM);       // 16

    float* out_emb1  = (float*)d_out;
    float* out_skill = out_emb1 + (size_t)n * DDIM;
    float* out_pred  = out_skill + (size_t)n * DDIM;   // also logits scratch

    float *pX3, *pU, *ptD, *ptS, *pxw, *pZ2, *pdeg, *pdis, *pdeg2, *pdis2, *pen, *psv;
    int *pnnz, *psr, *psc;
    __nv_bfloat16 *pUh, *pUm, *pUl;
    cudaGetSymbolAddress((void**)&pX3,  g_X3);
    cudaGetSymbolAddress((void**)&pU,   g_U);
    cudaGetSymbolAddress((void**)&ptD,  g_tmpD);
    cudaGetSymbolAddress((void**)&ptS,  g_tmpS);
    cudaGetSymbolAddress((void**)&pxw,  g_xw);
    cudaGetSymbolAddress((void**)&pZ2,  g_Z2);
    cudaGetSymbolAddress((void**)&pdeg, g_deg);
    cudaGetSymbolAddress((void**)&pdis, g_dis);
    cudaGetSymbolAddress((void**)&pdeg2,g_deg2);
    cudaGetSymbolAddress((void**)&pdis2,g_dis2);
    cudaGetSymbolAddress((void**)&pen,  g_enorm);
    cudaGetSymbolAddress((void**)&pnnz, g_nnz);
    cudaGetSymbolAddress((void**)&psr,  g_sp_r);
    cudaGetSymbolAddress((void**)&psc,  g_sp_c);
    cudaGetSymbolAddress((void**)&psv,  g_sp_v);
    cudaGetSymbolAddress((void**)&pUh,  g_Uh);
    cudaGetSymbolAddress((void**)&pUm,  g_Um);
    cudaGetSymbolAddress((void**)&pUl,  g_Ul);

    cudaFuncSetAttribute(syrk_mma_kernel,
                         cudaFuncAttributeMaxDynamicSharedMemorySize, SYRK_SMEM_DYN);

    const int ND = n * DDIM;
    const int TPB = 256;
    dim3 blk(TPB);

    // 1) gather [emb1 | demand_last | supply_last]
    gather_x3_kernel<<<(ND + TPB - 1) / TPB, blk>>>(emb1, demand, supply, pX3, n, T);

    // 2) update_emb = X3 @ fuse_W + fuse_b     [n, 256]
    {
        dim3 grid((DDIM + BN - 1) / BN, (n + BM - 1) / BM);
        sgemm_kernel<0, 0, true><<<grid, blk>>>(pX3, fuse_W, pU, fuse_b,
                                                n, DDIM, K3, K3, DDIM, DDIM);
    }

    // 3) logits Z = U @ U^T on tensor cores (3-way bf16 split, 6 accumulated segs)
    split_bf16_kernel<<<(ND + TPB - 1) / TPB, blk>>>(pU, pUh, pUm, pUl, ND);
    {
        int nblk = (n + 127) / 128;             // 63
        int ntiles = nblk * (nblk + 1) / 2;     // 2016
        syrk_mma_kernel<<<ntiles, 256, SYRK_SMEM_DYN>>>(pUh, pUm, pUl, out_pred, n);
    }

    // 4) prep for sparse emit: deg=1 (self loop), nnz=0
    fill_kernel<<<(n + TPB - 1) / TPB, blk>>>(pdeg, 1.0f, n);
    zero_int_kernel<<<1, 1>>>(pnnz);

    // 5) in-place row softmax + relu(.-0.2) -> pred_g; emits nonzeros + degrees
    softmax_relu_kernel<<<n, blk>>>(out_pred, n, pnnz, psr, psc, psv, pdeg);
    rsqrt_kernel<<<(n + TPB - 1) / TPB, blk>>>(pdis, pdeg, n);

    // 6) temps start at update_emb
    cudaMemcpyAsync(ptD, pU, (size_t)ND * sizeof(float), cudaMemcpyDeviceToDevice);
    cudaMemcpyAsync(ptS, pU, (size_t)ND * sizeof(float), cudaMemcpyDeviceToDevice);

    // 7) dense GCN layers via the (provably <= 4n nonzero) sparse form of pred_g
    for (int l = 0; l < LLAYERS; l++) {
        dim3 gsmall((DDIM + BN - 1) / BN, (n + BM - 1) / BM);
        sgemm_kernel<0, 0, false><<<gsmall, blk>>>(ptD, gnn0_W + (size_t)l * DDIM * DDIM,
                                                   pxw, nullptr, n, DDIM, DDIM,
                                                   DDIM, DDIM, DDIM);
        fill_kernel<<<(ND + TPB - 1) / TPB, blk>>>(pZ2, 0.0f, ND);
        {
            int blocks = (MAXNNZ * 32 + TPB - 1) / TPB;
            dense_scatter_kernel<<<blocks, blk>>>(pxw, psr, psc, psv, pdis, pZ2, pnnz);
        }
        dense_combine_kernel<<<(ND + TPB - 1) / TPB, blk>>>(ptD, pZ2, pxw, pdis,
                                                            gnn0_b + (size_t)l * DDIM,
                                                            n, DDIM);
    }

    // 8) sparse graph normalization
    fill_kernel<<<(n + TPB - 1) / TPB, blk>>>(pdeg2, 1.0f, n);
    edge_deg_kernel<<<(E + TPB - 1) / TPB, blk>>>(eidx + E, eattr, pdeg2, E);
    rsqrt_kernel<<<(n + TPB - 1) / TPB, blk>>>(pdis2, pdeg2, n);
    enorm_kernel<<<(E + TPB - 1) / TPB, blk>>>(eidx, eidx + E, eattr, pdis2, pen, E);

    // 9) sparse GCN layers
    for (int l = 0; l < LLAYERS; l++) {
        dim3 gsmall((DDIM + BN - 1) / BN, (n + BM - 1) / BM);
        sgemm_kernel<0, 0, false><<<gsmall, blk>>>(ptS, gnn1_W + (size_t)l * DDIM * DDIM,
                                                   pxw, nullptr, n, DDIM, DDIM,
                                                   DDIM, DDIM, DDIM);
        fill_kernel<<<(ND + TPB - 1) / TPB, blk>>>(pZ2, 0.0f, ND);
        {
            int blocks = (E * 32 + TPB - 1) / TPB;
            scatter_kernel<<<blocks, blk>>>(pxw, eidx, eidx + E, pen, pZ2, E, DDIM);
        }
        sparse_combine_kernel<<<(ND + TPB - 1) / TPB, blk>>>(ptS, pZ2, pxw, pdis2,
                                                             gnn1_b + (size_t)l * DDIM,
                                                             n, DDIM);
    }

    // 10) outputs: emb1 passthrough, skill = dense + sparse
    cudaMemcpyAsync(out_emb1, emb1, (size_t)ND * sizeof(float), cudaMemcpyDeviceToDevice);
    add_kernel<<<(ND + TPB - 1) / TPB, blk>>>(out_skill, ptD, ptS, ND);
}

// round 5
// speedup vs baseline: 4.2661x; 1.1187x over previous
#include <cuda_runtime.h>
#include <cuda_bf16.h>
#include <math.h>
#include <stdint.h>

// Problem constants (shapes fixed by the dataset)
#define NNODE 8000
#define DDIM  256
#define K3    768      // 3*D for the fuse GEMM
#define EMAX  256000
#define LLAYERS 2
#define PRESERVE_F 0.1f
// softmax rows sum to 1 => at most 4 entries per row exceed 0.2 => nnz <= 4*N
#define MAXNNZ (4 * NNODE)

// ---------------- scratch (static device memory; no allocation allowed) ---------
__device__ float g_X3[NNODE * K3];
__device__ float g_U [NNODE * DDIM];
__device__ float g_tmpD[NNODE * DDIM];
__device__ float g_tmpS[NNODE * DDIM];
__device__ float g_xw [NNODE * DDIM];
__device__ float g_Z2 [NNODE * DDIM];
__device__ float g_deg [NNODE];
__device__ float g_dis [NNODE];
__device__ float g_deg2[NNODE];
__device__ float g_dis2[NNODE];
__device__ float g_enorm[EMAX];
__device__ int   g_nnz;
__device__ int   g_sp_r[MAXNNZ];
__device__ int   g_sp_c[MAXNNZ];
__device__ float g_sp_v[MAXNNZ];
// 3-way bf16 split of U for tensor-core syrk
__device__ __nv_bfloat16 g_Uh[NNODE * DDIM];
__device__ __nv_bfloat16 g_Um[NNODE * DDIM];
__device__ __nv_bfloat16 g_Ul[NNODE * DDIM];

__device__ __forceinline__ uint32_t smem_u32(const void* p) {
    uint32_t a;
    asm("{ .reg .u64 t; cvta.to.shared.u64 t, %1; cvt.u32.u64 %0, t; }" : "=r"(a) : "l"(p));
    return a;
}

#define LDSM_X4(r0, r1, r2, r3, addr) \
    asm volatile("ldmatrix.sync.aligned.m8n8.x4.shared.b16 {%0,%1,%2,%3}, [%4];" \
                 : "=r"(r0), "=r"(r1), "=r"(r2), "=r"(r3) : "r"(addr))
#define LDSM_X2(r0, r1, addr) \
    asm volatile("ldmatrix.sync.aligned.m8n8.x2.shared.b16 {%0,%1}, [%2];" \
                 : "=r"(r0), "=r"(r1) : "r"(addr))
#define MMA_BF16(c, a0, a1, a2, a3, b0, b1) \
    asm volatile("mma.sync.aligned.m16n8k16.row.col.f32.bf16.bf16.f32 " \
                 "{%0,%1,%2,%3}, {%4,%5,%6,%7}, {%8,%9}, {%0,%1,%2,%3};" \
                 : "+f"((c)[0]), "+f"((c)[1]), "+f"((c)[2]), "+f"((c)[3]) \
                 : "r"(a0), "r"(a1), "r"(a2), "r"(a3), "r"(b0), "r"(b1))

// =================== warp-MMA symmetric logits GEMM (fused splits) ================
// C = U @ U^T via 3-way bf16 split. Single K pass: all 3 splits of the A and B
// tiles staged in smem per k-chunk; 6 split-pair MMA combos issued from registers
// into shared fp32 accumulators. Lower-tri tiles only; mirror via smem transpose.
#define LDT 40                                   // smem tile stride in bf16 (80 B)
#define SYRK_TILE_ELEMS (128 * LDT)              // per split tile
#define SYRK_SMEM_DYN   (128 * 129 * 4)          // 66048 B (>= 6 tiles = 61440 B)

__global__ __launch_bounds__(256)
void syrk_mma_kernel(const __nv_bfloat16* __restrict__ Uh,
                     const __nv_bfloat16* __restrict__ Um,
                     const __nv_bfloat16* __restrict__ Ul,
                     float* __restrict__ C, int n)
{
    extern __shared__ char smem[];
    __nv_bfloat16* tiles = (__nv_bfloat16*)smem;   // [6][128][LDT]: Ah Am Al Bh Bm Bl
    float* epi = (float*)smem;                     // reused after mainloop

    const int tid  = threadIdx.x;
    const int wid  = tid >> 5;
    const int lane = tid & 31;
    const int wm   = wid & 1;                    // warp row (2 x 64)
    const int wn   = wid >> 1;                   // warp col (4 x 32)
    const int group = lane >> 2;
    const int tig   = lane & 3;

    // decode linear lower-tri tile index -> (bi, bj), bi >= bj
    int t = blockIdx.x;
    int bi = (int)((sqrtf(8.0f * (float)t + 1.0f) - 1.0f) * 0.5f);
    while ((bi + 1) * (bi + 2) / 2 <= t) bi++;
    while (bi * (bi + 1) / 2 > t) bi--;
    int bj = t - bi * (bi + 1) / 2;
    const int m0 = bi * 128;
    const int n0 = bj * 128;

    float acc[4][4][4];
#pragma unroll
    for (int a = 0; a < 4; a++)
#pragma unroll
        for (int b = 0; b < 4; b++)
#pragma unroll
            for (int c = 0; c < 4; c++) acc[a][b][c] = 0.f;

    const __nv_bfloat16* srcs[6] = { Uh, Um, Ul, Uh, Um, Ul };

    const uint32_t sT = smem_u32(tiles);
    const uint32_t sA[3] = { sT, sT + SYRK_TILE_ELEMS * 2u, sT + SYRK_TILE_ELEMS * 4u };
    const uint32_t sB[3] = { sT + SYRK_TILE_ELEMS * 6u, sT + SYRK_TILE_ELEMS * 8u,
                             sT + SYRK_TILE_ELEMS * 10u };

    // precomputed ldmatrix lane addressing
    const int a_row = (lane & 15);
    const int a_col = (lane >> 4) * 8;
    const int b_row = (lane & 7);
    const int b_col = ((lane >> 3) & 1) * 8;
    const uint32_t a_base = (uint32_t)((wm * 64 + a_row) * LDT + a_col) * 2;
    const uint32_t b_base = (uint32_t)((wn * 32 + b_row) * LDT + b_col) * 2;

#pragma unroll 1
    for (int k0 = 0; k0 < DDIM; k0 += 32) {
        // ---- stage all 6 split tiles (128x32 each); 2 uint4 per thread per tile
#pragma unroll
        for (int s = 0; s < 6; s++) {
            const __nv_bfloat16* src = srcs[s];
            const int rowbase = (s < 3) ? m0 : n0;
            __nv_bfloat16* dst = tiles + s * SYRK_TILE_ELEMS;
#pragma unroll
            for (int it = 0; it < 2; it++) {
                int lin = it * 256 + tid;          // 0..511
                int r   = lin >> 2;
                int c8  = (lin & 3) * 8;
                int g   = rowbase + r;
                uint4 v = make_uint4(0u, 0u, 0u, 0u);
                if (g < n)
                    v = *reinterpret_cast<const uint4*>(src + (size_t)g * DDIM + k0 + c8);
                *reinterpret_cast<uint4*>(dst + r * LDT + c8) = v;
            }
        }
        __syncthreads();

#pragma unroll
        for (int ks = 0; ks < 2; ks++) {
            const uint32_t koff = (uint32_t)(ks * 16) * 2;
            uint32_t ah[4][4], bh[4][2];
#pragma unroll
            for (int mt = 0; mt < 4; mt++)
                LDSM_X4(ah[mt][0], ah[mt][1], ah[mt][2], ah[mt][3],
                        sA[0] + a_base + koff + (uint32_t)(mt * 16 * LDT) * 2);
#pragma unroll
            for (int nt = 0; nt < 4; nt++)
                LDSM_X2(bh[nt][0], bh[nt][1],
                        sB[0] + b_base + koff + (uint32_t)(nt * 8 * LDT) * 2);
            // hh
#pragma unroll
            for (int mt = 0; mt < 4; mt++)
#pragma unroll
                for (int nt = 0; nt < 4; nt++)
                    MMA_BF16(acc[mt][nt], ah[mt][0], ah[mt][1], ah[mt][2], ah[mt][3],
                             bh[nt][0], bh[nt][1]);
            {
                uint32_t bm[4][2], am[4][4];
#pragma unroll
                for (int nt = 0; nt < 4; nt++)
                    LDSM_X2(bm[nt][0], bm[nt][1],
                            sB[1] + b_base + koff + (uint32_t)(nt * 8 * LDT) * 2);
                // hm
#pragma unroll
                for (int mt = 0; mt < 4; mt++)
#pragma unroll
                    for (int nt = 0; nt < 4; nt++)
                        MMA_BF16(acc[mt][nt], ah[mt][0], ah[mt][1], ah[mt][2], ah[mt][3],
                                 bm[nt][0], bm[nt][1]);
#pragma unroll
                for (int mt = 0; mt < 4; mt++)
                    LDSM_X4(am[mt][0], am[mt][1], am[mt][2], am[mt][3],
                            sA[1] + a_base + koff + (uint32_t)(mt * 16 * LDT) * 2);
                // mh + mm
#pragma unroll
                for (int mt = 0; mt < 4; mt++)
#pragma unroll
                    for (int nt = 0; nt < 4; nt++) {
                        MMA_BF16(acc[mt][nt], am[mt][0], am[mt][1], am[mt][2], am[mt][3],
                                 bh[nt][0], bh[nt][1]);
                        MMA_BF16(acc[mt][nt], am[mt][0], am[mt][1], am[mt][2], am[mt][3],
                                 bm[nt][0], bm[nt][1]);
                    }
            }
            {
                uint32_t bl[4][2];
#pragma unroll
                for (int nt = 0; nt < 4; nt++)
                    LDSM_X2(bl[nt][0], bl[nt][1],
                            sB[2] + b_base + koff + (uint32_t)(nt * 8 * LDT) * 2);
                // hl
#pragma unroll
                for (int mt = 0; mt < 4; mt++)
#pragma unroll
                    for (int nt = 0; nt < 4; nt++)
                        MMA_BF16(acc[mt][nt], ah[mt][0], ah[mt][1], ah[mt][2], ah[mt][3],
                                 bl[nt][0], bl[nt][1]);
            }
            {
                uint32_t al[4][4];
#pragma unroll
                for (int mt = 0; mt < 4; mt++)
                    LDSM_X4(al[mt][0], al[mt][1], al[mt][2], al[mt][3],
                            sA[2] + a_base + koff + (uint32_t)(mt * 16 * LDT) * 2);
                // lh
#pragma unroll
                for (int mt = 0; mt < 4; mt++)
#pragma unroll
                    for (int nt = 0; nt < 4; nt++)
                        MMA_BF16(acc[mt][nt], al[mt][0], al[mt][1], al[mt][2], al[mt][3],
                                 bh[nt][0], bh[nt][1]);
            }
        }
        __syncthreads();
    }

    // ---- direct write C[m0.., n0..] (float2, coalesced in 32B groups)
#pragma unroll
    for (int mt = 0; mt < 4; mt++) {
#pragma unroll
        for (int nt = 0; nt < 4; nt++) {
            int lm = wm * 64 + mt * 16 + group;
            int ln = wn * 32 + nt * 8 + tig * 2;
            int gm = m0 + lm, gn = n0 + ln;
            if (gn + 1 < n) {
                if (gm < n)
                    *reinterpret_cast<float2*>(C + (size_t)gm * n + gn) =
                        make_float2(acc[mt][nt][0], acc[mt][nt][1]);
                if (gm + 8 < n)
                    *reinterpret_cast<float2*>(C + (size_t)(gm + 8) * n + gn) =
                        make_float2(acc[mt][nt][2], acc[mt][nt][3]);
            }
        }
    }

    // ---- mirrored write via smem transpose (off-diagonal tiles only)
    if (bi != bj) {
        __syncthreads();   // done with tiles, reuse as epi
#pragma unroll
        for (int mt = 0; mt < 4; mt++) {
#pragma unroll
            for (int nt = 0; nt < 4; nt++) {
                int lm = wm * 64 + mt * 16 + group;
                int ln = wn * 32 + nt * 8 + tig * 2;
                epi[lm * 129 + ln]           = acc[mt][nt][0];
                epi[lm * 129 + ln + 1]       = acc[mt][nt][1];
                epi[(lm + 8) * 129 + ln]     = acc[mt][nt][2];
                epi[(lm + 8) * 129 + ln + 1] = acc[mt][nt][3];
            }
        }
        __syncthreads();
        const int c_row = tid >> 1;
        const int half  = tid & 1;
        const int grow  = n0 + c_row;
        if (grow < n) {
            float* outrow = C + (size_t)grow * n;
#pragma unroll
            for (int i = 0; i < 16; i++) {
                int ml = half * 64 + i * 4;
                if (m0 + ml + 3 < n) {
                    float4 v = make_float4(epi[(ml + 0) * 129 + c_row],
                                           epi[(ml + 1) * 129 + c_row],
                                           epi[(ml + 2) * 129 + c_row],
                                           epi[(ml + 3) * 129 + c_row]);
                    *reinterpret_cast<float4*>(outrow + m0 + ml) = v;
                } else {
                    for (int q = 0; q < 4; q++)
                        if (m0 + ml + q < n)
                            outrow[m0 + ml + q] = epi[(ml + q) * 129 + c_row];
                }
            }
        }
    }
}

// split U (fp32) into 3 bf16 components: x ~= hi + mid + lo
__global__ void split_bf16_kernel(const float* __restrict__ U,
                                  __nv_bfloat16* __restrict__ Uh,
                                  __nv_bfloat16* __restrict__ Um,
                                  __nv_bfloat16* __restrict__ Ul, int total)
{
    int i = blockIdx.x * blockDim.x + threadIdx.x;
    if (i >= total) return;
    float x = U[i];
    __nv_bfloat16 h = __float2bfloat16(x);
    float r = x - __bfloat162float(h);
    __nv_bfloat16 m = __float2bfloat16(r);
    float r2 = r - __bfloat162float(m);
    __nv_bfloat16 l = __float2bfloat16(r2);
    Uh[i] = h; Um[i] = m; Ul[i] = l;
}

// ---------------- generic fp32 SGEMM: 128x128x8, 8x8 per thread -----------------
#define BM 128
#define BN 128
#define BK 8
#define TM 8
#define TN 8

template<int TRA, int TRB, bool BIAS>
__global__ __launch_bounds__(256, 2)
void sgemm_kernel(const float* __restrict__ A, const float* __restrict__ B,
                  float* __restrict__ C, const float* __restrict__ bias,
                  int M, int N, int K, int lda, int ldb, int ldc)
{
    __shared__ float As[BK][BM];
    __shared__ float Bs[BK][BN];

    const int tid = threadIdx.x;
    const int m0  = blockIdx.y * BM;
    const int n0  = blockIdx.x * BN;
    const int ty  = tid >> 4;
    const int tx  = tid & 15;

    float acc[TM][TN];
#pragma unroll
    for (int i = 0; i < TM; i++)
#pragma unroll
        for (int j = 0; j < TN; j++) acc[i][j] = 0.f;

    for (int k0 = 0; k0 < K; k0 += BK) {
        if (TRA == 0) {
            int r  = tid >> 1;
            int c4 = (tid & 1) * 4;
            int gm = m0 + r;
            float4 v = make_float4(0.f, 0.f, 0.f, 0.f);
            if (gm < M)
                v = *reinterpret_cast<const float4*>(A + (size_t)gm * lda + k0 + c4);
            As[c4 + 0][r] = v.x; As[c4 + 1][r] = v.y;
            As[c4 + 2][r] = v.z; As[c4 + 3][r] = v.w;
        } else {
            int rr  = tid >> 5;
            int cc4 = (tid & 31) * 4;
            int gm  = m0 + cc4;
            float4 v = make_float4(0.f, 0.f, 0.f, 0.f);
            if (gm < M)
                v = *reinterpret_cast<const float4*>(A + (size_t)(k0 + rr) * lda + gm);
            As[rr][cc4 + 0] = v.x; As[rr][cc4 + 1] = v.y;
            As[rr][cc4 + 2] = v.z; As[rr][cc4 + 3] = v.w;
        }
        if (TRB == 0) {
            int rr  = tid >> 5;
            int cc4 = (tid & 31) * 4;
            int gn  = n0 + cc4;
            float4 v = make_float4(0.f, 0.f, 0.f, 0.f);
            if (gn < N)
                v = *reinterpret_cast<const float4*>(B + (size_t)(k0 + rr) * ldb + gn);
            Bs[rr][cc4 + 0] = v.x; Bs[rr][cc4 + 1] = v.y;
            Bs[rr][cc4 + 2] = v.z; Bs[rr][cc4 + 3] = v.w;
        } else {
            int r  = tid >> 1;
            int c4 = (tid & 1) * 4;
            int gn = n0 + r;
            float4 v = make_float4(0.f, 0.f, 0.f, 0.f);
            if (gn < N)
                v = *reinterpret_cast<const float4*>(B + (size_t)gn * ldb + k0 + c4);
            Bs[c4 + 0][r] = v.x; Bs[c4 + 1][r] = v.y;
            Bs[c4 + 2][r] = v.z; Bs[c4 + 3][r] = v.w;
        }
        __syncthreads();

#pragma unroll
        for (int kk = 0; kk < BK; kk++) {
            float a[TM], b[TN];
#pragma unroll
            for (int i = 0; i < TM; i++) a[i] = As[kk][ty * TM + i];
#pragma unroll
            for (int j = 0; j < TN; j++) b[j] = Bs[kk][tx * TN + j];
#pragma unroll
            for (int i = 0; i < TM; i++)
#pragma unroll
                for (int j = 0; j < TN; j++)
                    acc[i][j] = fmaf(a[i], b[j], acc[i][j]);
        }
        __syncthreads();
    }

#pragma unroll
    for (int i = 0; i < TM; i++) {
        int gm = m0 + ty * TM + i;
        if (gm >= M) continue;
#pragma unroll
        for (int j = 0; j < TN; j++) {
            int gn = n0 + tx * TN + j;
            if (gn < N) {
                float v = acc[i][j];
                if (BIAS) v += bias[gn];
                C[(size_t)gm * ldc + gn] = v;
            }
        }
    }
}

// ---------------- small kernels --------------------------------------------------

__global__ void gather_x3_kernel(const float* __restrict__ emb1,
                                 const float* __restrict__ demand,
                                 const float* __restrict__ supply,
                                 float* __restrict__ X3, int n, int T)
{
    int i = blockIdx.x * blockDim.x + threadIdx.x;
    int total = n * DDIM;
    if (i >= total) return;
    int node = i / DDIM, d = i % DDIM;
    float* row = X3 + (size_t)node * K3;
    row[d]            = emb1[(size_t)node * DDIM + d];
    row[DDIM + d]     = demand[((size_t)node * T + (T - 1)) * DDIM + d];
    row[2 * DDIM + d] = supply[((size_t)node * T + (T - 1)) * DDIM + d];
}

// one block per row: in-place  Z -> relu(softmax(Z) - 0.2), and emit nonzeros
__global__ void softmax_relu_kernel(float* __restrict__ Z, int n,
                                    int* __restrict__ nnz,
                                    int* __restrict__ sr, int* __restrict__ sc,
                                    float* __restrict__ sv,
                                    float* __restrict__ deg)
{
    __shared__ float row[NNODE];
    __shared__ float red[256];
    int r = blockIdx.x;
    int t = threadIdx.x;
    float* zr = Z + (size_t)r * n;

    float mx = -3.4e38f;
    for (int c = t; c < n; c += 256) {
        float v = zr[c];
        row[c] = v;
        mx = fmaxf(mx, v);
    }
    red[t] = mx; __syncthreads();
    for (int s = 128; s > 0; s >>= 1) {
        if (t < s) red[t] = fmaxf(red[t], red[t + s]);
        __syncthreads();
    }
    mx = red[0];
    __syncthreads();

    float sm = 0.f;
    for (int c = t; c < n; c += 256) {
        float e = expf(row[c] - mx);
        row[c] = e;
        sm += e;
    }
    red[t] = sm; __syncthreads();
    for (int s = 128; s > 0; s >>= 1) {
        if (t < s) red[t] += red[t + s];
        __syncthreads();
    }
    float inv = 1.0f / red[0];
    for (int c = t; c < n; c += 256) {
        float p = row[c] * inv - 0.2f;
        p = p > 0.f ? p : 0.f;
        zr[c] = p;
        if (p > 0.f) {
            int idx = atomicAdd(nnz, 1);
            if (idx < MAXNNZ) {
                sr[idx] = r; sc[idx] = c; sv[idx] = p;
            }
            atomicAdd(&deg[c], p);
        }
    }
}

__global__ void fill_kernel(float* p, float v, int n)
{
    int i = blockIdx.x * blockDim.x + threadIdx.x;
    if (i < n) p[i] = v;
}

__global__ void zero_int_kernel(int* p) { *p = 0; }

__global__ void rsqrt_kernel(float* __restrict__ dst, const float* __restrict__ src, int n)
{
    int i = blockIdx.x * blockDim.x + threadIdx.x;
    if (i < n) dst[i] = rsqrtf(src[i]);
}

// warp per nonzero of G: agg[c] += G[r,c] * dis[r] * xw[r]
__global__ void dense_scatter_kernel(const float* __restrict__ xw,
                                     const int* __restrict__ sr,
                                     const int* __restrict__ sc,
                                     const float* __restrict__ sv,
                                     const float* __restrict__ dis,
                                     float* __restrict__ agg,
                                     const int* __restrict__ nnz)
{
    int warp = (blockIdx.x * blockDim.x + threadIdx.x) >> 5;
    int lane = threadIdx.x & 31;
    int m = *nnz; if (m > MAXNNZ) m = MAXNNZ;
    if (warp >= m) return;
    int r = sr[warp], c = sc[warp];
    float w = sv[warp] * dis[r];
    const float* xr = xw + (size_t)r * DDIM;
    float* ar = agg + (size_t)c * DDIM;
    for (int f = lane; f < DDIM; f += 32)
        atomicAdd(&ar[f], w * xr[f]);
}

// temp = 0.9*(dis[c]*Z2 + dis[c]^2*xw + b) + 0.1*temp
__global__ void dense_combine_kernel(float* __restrict__ temp, const float* __restrict__ Z2,
                                     const float* __restrict__ xw, const float* __restrict__ dis,
                                     const float* __restrict__ b, int n, int d)
{
    int i = blockIdx.x * blockDim.x + threadIdx.x;
    if (i >= n * d) return;
    int c = i / d, dd = i - c * d;
    float s = dis[c];
    float out = s * Z2[i] + s * s * xw[i] + b[dd];
    temp[i] = (1.0f - PRESERVE_F) * out + PRESERVE_F * temp[i];
}

__global__ void edge_deg_kernel(const int* __restrict__ dst, const float* __restrict__ attr,
                                float* __restrict__ deg2, int E)
{
    int e = blockIdx.x * blockDim.x + threadIdx.x;
    if (e < E) atomicAdd(&deg2[dst[e]], attr[e]);
}

__global__ void enorm_kernel(const int* __restrict__ src, const int* __restrict__ dst,
                             const float* __restrict__ attr, const float* __restrict__ dis2,
                             float* __restrict__ enorm, int E)
{
    int e = blockIdx.x * blockDim.x + threadIdx.x;
    if (e < E) enorm[e] = dis2[src[e]] * attr[e] * dis2[dst[e]];
}

// warp per edge: agg[dst] += enorm * xw[src]
__global__ void scatter_kernel(const float* __restrict__ xw, const int* __restrict__ src,
                               const int* __restrict__ dst, const float* __restrict__ enorm,
                               float* __restrict__ agg, int E, int d)
{
    int warp = (blockIdx.x * blockDim.x + threadIdx.x) >> 5;
    int lane = threadIdx.x & 31;
    if (warp >= E) return;
    int s = src[warp], t = dst[warp];
    float w = enorm[warp];
    const float* xr = xw + (size_t)s * d;
    float* ar = agg + (size_t)t * d;
    for (int f = lane; f < d; f += 32)
        atomicAdd(&ar[f], w * xr[f]);
}

// temp = 0.9*(agg + dis2[c]^2*xw + b) + 0.1*temp
__global__ void sparse_combine_kernel(float* __restrict__ temp, const float* __restrict__ agg,
                                      const float* __restrict__ xw, const float* __restrict__ dis2,
                                      const float* __restrict__ b, int n, int d)
{
    int i = blockIdx.x * blockDim.x + threadIdx.x;
    if (i >= n * d) return;
    int c = i / d, dd = i - c * d;
    float s = dis2[c];
    float out = agg[i] + s * s * xw[i] + b[dd];
    temp[i] = (1.0f - PRESERVE_F) * out + PRESERVE_F * temp[i];
}

__global__ void add_kernel(float* __restrict__ out, const float* __restrict__ a,
                           const float* __restrict__ b, int n)
{
    int i = blockIdx.x * blockDim.x + threadIdx.x;
    if (i < n) out[i] = a[i] + b[i];
}

// ---------------- host orchestration ---------------------------------------------

extern "C" void kernel_launch(void* const* d_in, const int* in_sizes, int n_in,
                              void* d_out, int out_size)
{
    const float* demand  = (const float*)d_in[0];
    const float* supply  = (const float*)d_in[1];
    const int*   eidx    = (const int*)  d_in[2];
    const float* eattr   = (const float*)d_in[3];
    const float* emb1    = (const float*)d_in[4];
    const float* fuse_W  = (const float*)d_in[5];
    const float* fuse_b  = (const float*)d_in[6];
    const float* gnn0_W  = (const float*)d_in[7];
    const float* gnn0_b  = (const float*)d_in[8];
    const float* gnn1_W  = (const float*)d_in[9];
    const float* gnn1_b  = (const float*)d_in[10];

    const int n = in_sizes[4] / DDIM;             // 8000
    const int E = in_sizes[3];                    // 256000
    const int T = in_sizes[0] / (n * DDIM);       // 16

    float* out_emb1  = (float*)d_out;
    float* out_skill = out_emb1 + (size_t)n * DDIM;
    float* out_pred  = out_skill + (size_t)n * DDIM;   // also logits scratch

    float *pX3, *pU, *ptD, *ptS, *pxw, *pZ2, *pdeg, *pdis, *pdeg2, *pdis2, *pen, *psv;
    int *pnnz, *psr, *psc;
    __nv_bfloat16 *pUh, *pUm, *pUl;
    cudaGetSymbolAddress((void**)&pX3,  g_X3);
    cudaGetSymbolAddress((void**)&pU,   g_U);
    cudaGetSymbolAddress((void**)&ptD,  g_tmpD);
    cudaGetSymbolAddress((void**)&ptS,  g_tmpS);
    cudaGetSymbolAddress((void**)&pxw,  g_xw);
    cudaGetSymbolAddress((void**)&pZ2,  g_Z2);
    cudaGetSymbolAddress((void**)&pdeg, g_deg);
    cudaGetSymbolAddress((void**)&pdis, g_dis);
    cudaGetSymbolAddress((void**)&pdeg2,g_deg2);
    cudaGetSymbolAddress((void**)&pdis2,g_dis2);
    cudaGetSymbolAddress((void**)&pen,  g_enorm);
    cudaGetSymbolAddress((void**)&pnnz, g_nnz);
    cudaGetSymbolAddress((void**)&psr,  g_sp_r);
    cudaGetSymbolAddress((void**)&psc,  g_sp_c);
    cudaGetSymbolAddress((void**)&psv,  g_sp_v);
    cudaGetSymbolAddress((void**)&pUh,  g_Uh);
    cudaGetSymbolAddress((void**)&pUm,  g_Um);
    cudaGetSymbolAddress((void**)&pUl,  g_Ul);

    cudaFuncSetAttribute(syrk_mma_kernel,
                         cudaFuncAttributeMaxDynamicSharedMemorySize, SYRK_SMEM_DYN);

    const int ND = n * DDIM;
    const int TPB = 256;
    dim3 blk(TPB);

    // 1) gather [emb1 | demand_last | supply_last]
    gather_x3_kernel<<<(ND + TPB - 1) / TPB, blk>>>(emb1, demand, supply, pX3, n, T);

    // 2) update_emb = X3 @ fuse_W + fuse_b     [n, 256]
    {
        dim3 grid((DDIM + BN - 1) / BN, (n + BM - 1) / BM);
        sgemm_kernel<0, 0, true><<<grid, blk>>>(pX3, fuse_W, pU, fuse_b,
                                                n, DDIM, K3, K3, DDIM, DDIM);
    }

    // 3) logits Z = U @ U^T on tensor cores (3-way bf16 split, fused single pass)
    split_bf16_kernel<<<(ND + TPB - 1) / TPB, blk>>>(pU, pUh, pUm, pUl, ND);
    {
        int nblk = (n + 127) / 128;             // 63
        int ntiles = nblk * (nblk + 1) / 2;     // 2016
        syrk_mma_kernel<<<ntiles, 256, SYRK_SMEM_DYN>>>(pUh, pUm, pUl, out_pred, n);
    }

    // 4) prep for sparse emit: deg=1 (self loop), nnz=0
    fill_kernel<<<(n + TPB - 1) / TPB, blk>>>(pdeg, 1.0f, n);
    zero_int_kernel<<<1, 1>>>(pnnz);

    // 5) in-place row softmax + relu(.-0.2) -> pred_g; emits nonzeros + degrees
    softmax_relu_kernel<<<n, blk>>>(out_pred, n, pnnz, psr, psc, psv, pdeg);
    rsqrt_kernel<<<(n + TPB - 1) / TPB, blk>>>(pdis, pdeg, n);

    // 6) temps start at update_emb
    cudaMemcpyAsync(ptD, pU, (size_t)ND * sizeof(float), cudaMemcpyDeviceToDevice);
    cudaMemcpyAsync(ptS, pU, (size_t)ND * sizeof(float), cudaMemcpyDeviceToDevice);

    // 7) dense GCN layers via the (provably <= 4n nonzero) sparse form of pred_g
    for (int l = 0; l < LLAYERS; l++) {
        dim3 gsmall((DDIM + BN - 1) / BN, (n + BM - 1) / BM);
        sgemm_kernel<0, 0, false><<<gsmall, blk>>>(ptD, gnn0_W + (size_t)l * DDIM * DDIM,
                                                   pxw, nullptr, n, DDIM, DDIM,
                                                   DDIM, DDIM, DDIM);
        fill_kernel<<<(ND + TPB - 1) / TPB, blk>>>(pZ2, 0.0f, ND);
        {
            int blocks = (MAXNNZ * 32 + TPB - 1) / TPB;
            dense_scatter_kernel<<<blocks, blk>>>(pxw, psr, psc, psv, pdis, pZ2, pnnz);
        }
        dense_combine_kernel<<<(ND + TPB - 1) / TPB, blk>>>(ptD, pZ2, pxw, pdis,
                                                            gnn0_b + (size_t)l * DDIM,
                                                            n, DDIM);
    }

    // 8) sparse graph normalization
    fill_kernel<<<(n + TPB - 1) / TPB, blk>>>(pdeg2, 1.0f, n);
    edge_deg_kernel<<<(E + TPB - 1) / TPB, blk>>>(eidx + E, eattr, pdeg2, E);
    rsqrt_kernel<<<(n + TPB - 1) / TPB, blk>>>(pdis2, pdeg2, n);
    enorm_kernel<<<(E + TPB - 1) / TPB, blk>>>(eidx, eidx + E, eattr, pdis2, pen, E);

    // 9) sparse GCN layers
    for (int l = 0; l < LLAYERS; l++) {
        dim3 gsmall((DDIM + BN - 1) / BN, (n + BM - 1) / BM);
        sgemm_kernel<0, 0, false><<<gsmall, blk>>>(ptS, gnn1_W + (size_t)l * DDIM * DDIM,
                                                   pxw, nullptr, n, DDIM, DDIM,
                                                   DDIM, DDIM, DDIM);
        fill_kernel<<<(ND + TPB - 1) / TPB, blk>>>(pZ2, 0.0f, ND);
        {
            int blocks = (E * 32 + TPB - 1) / TPB;
            scatter_kernel<<<blocks, blk>>>(pxw, eidx, eidx + E, pen, pZ2, E, DDIM);
        }
        sparse_combine_kernel<<<(ND + TPB - 1) / TPB, blk>>>(ptS, pZ2, pxw, pdis2,
                                                             gnn1_b + (size_t)l * DDIM,
                                                             n, DDIM);
    }

    // 10) outputs: emb1 passthrough, skill = dense + sparse
    cudaMemcpyAsync(out_emb1, emb1, (size_t)ND * sizeof(float), cudaMemcpyDeviceToDevice);
    add_kernel<<<(ND + TPB - 1) / TPB, blk>>>(out_skill, ptD, ptS, ND);
}

// round 6
// speedup vs baseline: 5.5642x; 1.3043x over previous
#include <cuda_runtime.h>
#include <cuda_bf16.h>
#include <math.h>
#include <stdint.h>

#define NNODE 8000
#define DDIM  256
#define K3    768
#define EMAX  256000
#define LLAYERS 2
#define PRESERVE_F 0.1f
#define MAXNNZ (4 * NNODE)   // softmax rows sum to 1 => <=4 entries/row exceed 0.2

// ---------------- scratch (static device memory) ---------------------------------
__device__ float g_U [NNODE * DDIM];
__device__ float g_tmpD[NNODE * DDIM];
__device__ float g_tmpS[NNODE * DDIM];
__device__ float g_xw [NNODE * DDIM];
__device__ float g_Z2 [NNODE * DDIM];
__device__ float g_deg [NNODE];
__device__ float g_dis [NNODE];
__device__ float g_deg2[NNODE];
__device__ float g_dis2[NNODE];
__device__ float g_enorm[EMAX];
__device__ int   g_nnz;
__device__ int   g_sp_r[MAXNNZ];
__device__ int   g_sp_c[MAXNNZ];
__device__ float g_sp_v[MAXNNZ];
// bf16 splits
__device__ __nv_bfloat16 g_X3h[NNODE * K3];
__device__ __nv_bfloat16 g_X3m[NNODE * K3];
__device__ __nv_bfloat16 g_X3l[NNODE * K3];
__device__ __nv_bfloat16 g_Uh[NNODE * DDIM];
__device__ __nv_bfloat16 g_Um[NNODE * DDIM];
__device__ __nv_bfloat16 g_Ul[NNODE * DDIM];
__device__ __nv_bfloat16 g_tDh[NNODE * DDIM];
__device__ __nv_bfloat16 g_tDm[NNODE * DDIM];
__device__ __nv_bfloat16 g_tSh[NNODE * DDIM];
__device__ __nv_bfloat16 g_tSm[NNODE * DDIM];
__device__ __nv_bfloat16 g_Wfh[K3 * DDIM];
__device__ __nv_bfloat16 g_Wfm[K3 * DDIM];
__device__ __nv_bfloat16 g_Wfl[K3 * DDIM];
__device__ __nv_bfloat16 g_W0h[LLAYERS * DDIM * DDIM];
__device__ __nv_bfloat16 g_W0m[LLAYERS * DDIM * DDIM];
__device__ __nv_bfloat16 g_W1h[LLAYERS * DDIM * DDIM];
__device__ __nv_bfloat16 g_W1m[LLAYERS * DDIM * DDIM];

__device__ __forceinline__ uint32_t smem_u32(const void* p) {
    uint32_t a;
    asm("{ .reg .u64 t; cvta.to.shared.u64 t, %1; cvt.u32.u64 %0, t; }" : "=r"(a) : "l"(p));
    return a;
}

#define LDSM_X4(r0, r1, r2, r3, addr) \
    asm volatile("ldmatrix.sync.aligned.m8n8.x4.shared.b16 {%0,%1,%2,%3}, [%4];" \
                 : "=r"(r0), "=r"(r1), "=r"(r2), "=r"(r3) : "r"(addr))
#define LDSM_X2(r0, r1, addr) \
    asm volatile("ldmatrix.sync.aligned.m8n8.x2.shared.b16 {%0,%1}, [%2];" \
                 : "=r"(r0), "=r"(r1) : "r"(addr))
#define LDSM_X2_T(r0, r1, addr) \
    asm volatile("ldmatrix.sync.aligned.m8n8.x2.trans.shared.b16 {%0,%1}, [%2];" \
                 : "=r"(r0), "=r"(r1) : "r"(addr))
#define MMA_BF16(c, a0, a1, a2, a3, b0, b1) \
    asm volatile("mma.sync.aligned.m16n8k16.row.col.f32.bf16.bf16.f32 " \
                 "{%0,%1,%2,%3}, {%4,%5,%6,%7}, {%8,%9}, {%0,%1,%2,%3};" \
                 : "+f"((c)[0]), "+f"((c)[1]), "+f"((c)[2]), "+f"((c)[3]) \
                 : "r"(a0), "r"(a1), "r"(a2), "r"(a3), "r"(b0), "r"(b1))
#define CP_ASYNC16(saddr, gptr, sz) \
    asm volatile("cp.async.cg.shared.global [%0], [%1], 16, %2;" \
                 :: "r"(saddr), "l"(gptr), "r"(sz))
#define CP_COMMIT() asm volatile("cp.async.commit_group;")
#define CP_WAIT1()  asm volatile("cp.async.wait_group 1;")
#define CP_WAIT0()  asm volatile("cp.async.wait_group 0;")

#define LDT 40   // A-tile smem stride (bf16), 80 B
#define LDB 136  // B-tile smem stride (bf16), 272 B

// =================== syrk: C = U @ U^T (3-way bf16 split, fused, pipelined) ======
#define SYRK_TILE_ELEMS (128 * LDT)
#define SYRK_STAGE_ELEMS (6 * SYRK_TILE_ELEMS)
#define SYRK_SMEM_DYN (2 * SYRK_STAGE_ELEMS * 2)   // 122880 B (>= epi 66048)

__global__ __launch_bounds__(256)
void syrk_mma_kernel(const __nv_bfloat16* __restrict__ Uh,
                     const __nv_bfloat16* __restrict__ Um,
                     const __nv_bfloat16* __restrict__ Ul,
                     float* __restrict__ C, int n)
{
    extern __shared__ char smem[];
    __nv_bfloat16* tiles = (__nv_bfloat16*)smem;
    float* epi = (float*)smem;

    const int tid  = threadIdx.x;
    const int wid  = tid >> 5;
    const int lane = tid & 31;
    const int wm   = wid & 1;
    const int wn   = wid >> 1;
    const int group = lane >> 2;
    const int tig   = lane & 3;

    int t = blockIdx.x;
    int bi = (int)((sqrtf(8.0f * (float)t + 1.0f) - 1.0f) * 0.5f);
    while ((bi + 1) * (bi + 2) / 2 <= t) bi++;
    while (bi * (bi + 1) / 2 > t) bi--;
    int bj = t - bi * (bi + 1) / 2;
    const int m0 = bi * 128;
    const int n0 = bj * 128;

    float acc[4][4][4];
#pragma unroll
    for (int a = 0; a < 4; a++)
#pragma unroll
        for (int b = 0; b < 4; b++)
#pragma unroll
            for (int c = 0; c < 4; c++) acc[a][b][c] = 0.f;

    const __nv_bfloat16* srcs[6] = { Uh, Um, Ul, Uh, Um, Ul };
    const uint32_t sT = smem_u32(tiles);

    const int a_row = (lane & 15);
    const int a_col = (lane >> 4) * 8;
    const int b_row = (lane & 7);
    const int b_col = ((lane >> 3) & 1) * 8;
    const uint32_t a_base = (uint32_t)((wm * 64 + a_row) * LDT + a_col) * 2;
    const uint32_t b_base = (uint32_t)((wn * 32 + b_row) * LDT + b_col) * 2;

    // per-chunk async staging
    auto load_chunk = [&](int k0, int stage) {
        uint32_t dst0 = sT + (uint32_t)(stage * SYRK_STAGE_ELEMS) * 2;
#pragma unroll
        for (int s = 0; s < 6; s++) {
            const __nv_bfloat16* src = srcs[s];
            const int rowbase = (s < 3) ? m0 : n0;
            uint32_t dts = dst0 + (uint32_t)(s * SYRK_TILE_ELEMS) * 2;
#pragma unroll
            for (int it = 0; it < 2; it++) {
                int lin = it * 256 + tid;
                int r   = lin >> 2;
                int c8  = (lin & 3) * 8;
                int g   = rowbase + r;
                uint32_t sz = (g < n) ? 16u : 0u;
                int g2 = (g < n) ? g : 0;
                const __nv_bfloat16* gp = src + (size_t)g2 * DDIM + k0 + c8;
                CP_ASYNC16(dts + (uint32_t)(r * LDT + c8) * 2, gp, sz);
            }
        }
    };

    load_chunk(0, 0);
    CP_COMMIT();

#pragma unroll 1
    for (int kc = 0; kc < 8; kc++) {
        const int cur = kc & 1;
        if (kc < 7) {
            load_chunk((kc + 1) * 32, cur ^ 1);
            CP_COMMIT();
            CP_WAIT1();
        } else {
            CP_WAIT0();
        }
        __syncthreads();

        const uint32_t stg = sT + (uint32_t)(cur * SYRK_STAGE_ELEMS) * 2;
        const uint32_t sA0 = stg;
        const uint32_t sA1 = stg + SYRK_TILE_ELEMS * 2u;
        const uint32_t sA2 = stg + SYRK_TILE_ELEMS * 4u;
        const uint32_t sB0 = stg + SYRK_TILE_ELEMS * 6u;
        const uint32_t sB1 = stg + SYRK_TILE_ELEMS * 8u;
        const uint32_t sB2 = stg + SYRK_TILE_ELEMS * 10u;

#pragma unroll
        for (int ks = 0; ks < 2; ks++) {
            const uint32_t koff = (uint32_t)(ks * 16) * 2;
            uint32_t ah[4][4], bh[4][2];
#pragma unroll
            for (int mt = 0; mt < 4; mt++)
                LDSM_X4(ah[mt][0], ah[mt][1], ah[mt][2], ah[mt][3],
                        sA0 + a_base + koff + (uint32_t)(mt * 16 * LDT) * 2);
#pragma unroll
            for (int nt = 0; nt < 4; nt++)
                LDSM_X2(bh[nt][0], bh[nt][1],
                        sB0 + b_base + koff + (uint32_t)(nt * 8 * LDT) * 2);
#pragma unroll
            for (int mt = 0; mt < 4; mt++)
#pragma unroll
                for (int nt = 0; nt < 4; nt++)
                    MMA_BF16(acc[mt][nt], ah[mt][0], ah[mt][1], ah[mt][2], ah[mt][3],
                             bh[nt][0], bh[nt][1]);
            {
                uint32_t bm[4][2], am[4][4];
#pragma unroll
                for (int nt = 0; nt < 4; nt++)
                    LDSM_X2(bm[nt][0], bm[nt][1],
                            sB1 + b_base + koff + (uint32_t)(nt * 8 * LDT) * 2);
#pragma unroll
                for (int mt = 0; mt < 4; mt++)
#pragma unroll
                    for (int nt = 0; nt < 4; nt++)
                        MMA_BF16(acc[mt][nt], ah[mt][0], ah[mt][1], ah[mt][2], ah[mt][3],
                                 bm[nt][0], bm[nt][1]);
#pragma unroll
                for (int mt = 0; mt < 4; mt++)
                    LDSM_X4(am[mt][0], am[mt][1], am[mt][2], am[mt][3],
                            sA1 + a_base + koff + (uint32_t)(mt * 16 * LDT) * 2);
#pragma unroll
                for (int mt = 0; mt < 4; mt++)
#pragma unroll
                    for (int nt = 0; nt < 4; nt++) {
                        MMA_BF16(acc[mt][nt], am[mt][0], am[mt][1], am[mt][2], am[mt][3],
                                 bh[nt][0], bh[nt][1]);
                        MMA_BF16(acc[mt][nt], am[mt][0], am[mt][1], am[mt][2], am[mt][3],
                                 bm[nt][0], bm[nt][1]);
                    }
            }
            {
                uint32_t bl[4][2];
#pragma unroll
                for (int nt = 0; nt < 4; nt++)
                    LDSM_X2(bl[nt][0], bl[nt][1],
                            sB2 + b_base + koff + (uint32_t)(nt * 8 * LDT) * 2);
#pragma unroll
                for (int mt = 0; mt < 4; mt++)
#pragma unroll
                    for (int nt = 0; nt < 4; nt++)
                        MMA_BF16(acc[mt][nt], ah[mt][0], ah[mt][1], ah[mt][2], ah[mt][3],
                                 bl[nt][0], bl[nt][1]);
            }
            {
                uint32_t al[4][4];
#pragma unroll
                for (int mt = 0; mt < 4; mt++)
                    LDSM_X4(al[mt][0], al[mt][1], al[mt][2], al[mt][3],
                            sA2 + a_base + koff + (uint32_t)(mt * 16 * LDT) * 2);
#pragma unroll
                for (int mt = 0; mt < 4; mt++)
#pragma unroll
                    for (int nt = 0; nt < 4; nt++)
                        MMA_BF16(acc[mt][nt], al[mt][0], al[mt][1], al[mt][2], al[mt][3],
                                 bh[nt][0], bh[nt][1]);
            }
        }
        __syncthreads();
    }

    // direct write
#pragma unroll
    for (int mt = 0; mt < 4; mt++) {
#pragma unroll
        for (int nt = 0; nt < 4; nt++) {
            int lm = wm * 64 + mt * 16 + group;
            int ln = wn * 32 + nt * 8 + tig * 2;
            int gm = m0 + lm, gn = n0 + ln;
            if (gn + 1 < n) {
                if (gm < n)
                    *reinterpret_cast<float2*>(C + (size_t)gm * n + gn) =
                        make_float2(acc[mt][nt][0], acc[mt][nt][1]);
                if (gm + 8 < n)
                    *reinterpret_cast<float2*>(C + (size_t)(gm + 8) * n + gn) =
                        make_float2(acc[mt][nt][2], acc[mt][nt][3]);
            }
        }
    }

    // mirrored write via smem transpose
    if (bi != bj) {
        __syncthreads();
#pragma unroll
        for (int mt = 0; mt < 4; mt++) {
#pragma unroll
            for (int nt = 0; nt < 4; nt++) {
                int lm = wm * 64 + mt * 16 + group;
                int ln = wn * 32 + nt * 8 + tig * 2;
                epi[lm * 129 + ln]           = acc[mt][nt][0];
                epi[lm * 129 + ln + 1]       = acc[mt][nt][1];
                epi[(lm + 8) * 129 + ln]     = acc[mt][nt][2];
                epi[(lm + 8) * 129 + ln + 1] = acc[mt][nt][3];
            }
        }
        __syncthreads();
        const int c_row = tid >> 1;
        const int half  = tid & 1;
        const int grow  = n0 + c_row;
        if (grow < n) {
            float* outrow = C + (size_t)grow * n;
#pragma unroll
            for (int i = 0; i < 16; i++) {
                int ml = half * 64 + i * 4;
                if (m0 + ml + 3 < n) {
                    float4 v = make_float4(epi[(ml + 0) * 129 + c_row],
                                           epi[(ml + 1) * 129 + c_row],
                                           epi[(ml + 2) * 129 + c_row],
                                           epi[(ml + 3) * 129 + c_row]);
                    *reinterpret_cast<float4*>(outrow + m0 + ml) = v;
                } else {
                    for (int q = 0; q < 4; q++)
                        if (m0 + ml + q < n)
                            outrow[m0 + ml + q] = epi[(ml + q) * 129 + c_row];
                }
            }
        }
    }
}

// =================== general MMA GEMM: C = A @ B (+bias) =========================
// A [M,K] given as SP bf16 splits; B [K,N] as SP splits (trans-ldmatrix).
// SP=3: products hh,hm,mh,hl,lh,mm (fp32-grade). SP=2: hh,hm,mh.
#define GEMM_AT_ELEMS (128 * LDT)
#define GEMM_BT_ELEMS (32 * LDB)

template<int SP, bool BIAS>
__global__ __launch_bounds__(256)
void gemm_mma_kernel(const __nv_bfloat16* __restrict__ Ah_,
                     const __nv_bfloat16* __restrict__ Am_,
                     const __nv_bfloat16* __restrict__ Al_,
                     const __nv_bfloat16* __restrict__ Bh_,
                     const __nv_bfloat16* __restrict__ Bm_,
                     const __nv_bfloat16* __restrict__ Bl_,
                     float* __restrict__ C, const float* __restrict__ bias,
                     int M, int N, int K)
{
    extern __shared__ char smem[];
    __nv_bfloat16* tiles = (__nv_bfloat16*)smem;
    const int STAGE_ELEMS = SP * (GEMM_AT_ELEMS + GEMM_BT_ELEMS);

    const int tid  = threadIdx.x;
    const int wid  = tid >> 5;
    const int lane = tid & 31;
    const int wm   = wid & 1;
    const int wn   = wid >> 1;
    const int group = lane >> 2;
    const int tig   = lane & 3;

    const int n0 = blockIdx.x * 128;
    const int m0 = blockIdx.y * 128;

    float acc[4][4][4];
#pragma unroll
    for (int a = 0; a < 4; a++)
#pragma unroll
        for (int b = 0; b < 4; b++)
#pragma unroll
            for (int c = 0; c < 4; c++) acc[a][b][c] = 0.f;

    const __nv_bfloat16* Asrc[3] = { Ah_, Am_, Al_ };
    const __nv_bfloat16* Bsrc[3] = { Bh_, Bm_, Bl_ };
    const uint32_t sT = smem_u32(tiles);

    const int a_row = (lane & 15);
    const int a_col = (lane >> 4) * 8;
    const uint32_t a_base = (uint32_t)((wm * 64 + a_row) * LDT + a_col) * 2;
    const uint32_t bt_base = (uint32_t)((lane & 15) * LDB + wn * 32) * 2;

    auto load_chunk = [&](int k0, int stage) {
        uint32_t dst0 = sT + (uint32_t)(stage * STAGE_ELEMS) * 2;
#pragma unroll
        for (int s = 0; s < SP; s++) {
            uint32_t dts = dst0 + (uint32_t)(s * GEMM_AT_ELEMS) * 2;
#pragma unroll
            for (int it = 0; it < 2; it++) {
                int lin = it * 256 + tid;
                int r   = lin >> 2;
                int c8  = (lin & 3) * 8;
                int g   = m0 + r;
                uint32_t sz = (g < M) ? 16u : 0u;
                int g2 = (g < M) ? g : 0;
                const __nv_bfloat16* gp = Asrc[s] + (size_t)g2 * K + k0 + c8;
                CP_ASYNC16(dts + (uint32_t)(r * LDT + c8) * 2, gp, sz);
            }
        }
        uint32_t dstB = dst0 + (uint32_t)(SP * GEMM_AT_ELEMS) * 2;
#pragma unroll
        for (int s = 0; s < SP; s++) {
            uint32_t dts = dstB + (uint32_t)(s * GEMM_BT_ELEMS) * 2;
#pragma unroll
            for (int it = 0; it < 2; it++) {
                int lin = it * 256 + tid;
                int r   = lin >> 4;            // 0..31 (k row)
                int c8  = (lin & 15) * 8;      // 0..120
                const __nv_bfloat16* gp = Bsrc[s] + (size_t)(k0 + r) * N + n0 + c8;
                CP_ASYNC16(dts + (uint32_t)(r * LDB + c8) * 2, gp, 16u);
            }
        }
    };

    const int NC = K / 32;
    load_chunk(0, 0);
    CP_COMMIT();

#pragma unroll 1
    for (int kc = 0; kc < NC; kc++) {
        const int cur = kc & 1;
        if (kc < NC - 1) {
            load_chunk((kc + 1) * 32, cur ^ 1);
            CP_COMMIT();
            CP_WAIT1();
        } else {
            CP_WAIT0();
        }
        __syncthreads();

        const uint32_t stg = sT + (uint32_t)(cur * STAGE_ELEMS) * 2;
        const uint32_t sA0 = stg;
        const uint32_t sA1 = stg + GEMM_AT_ELEMS * 2u;
        const uint32_t sA2 = stg + GEMM_AT_ELEMS * 4u;
        const uint32_t sBb = stg + (uint32_t)(SP * GEMM_AT_ELEMS) * 2u;
        const uint32_t sB0 = sBb;
        const uint32_t sB1 = sBb + GEMM_BT_ELEMS * 2u;
        const uint32_t sB2 = sBb + GEMM_BT_ELEMS * 4u;

#pragma unroll
        for (int ks = 0; ks < 2; ks++) {
            const uint32_t akoff = (uint32_t)(ks * 16) * 2;
            const uint32_t bkoff = (uint32_t)(ks * 16 * LDB) * 2;
            uint32_t ah[4][4], bh[4][2];
#pragma unroll
            for (int mt = 0; mt < 4; mt++)
                LDSM_X4(ah[mt][0], ah[mt][1], ah[mt][2], ah[mt][3],
                        sA0 + a_base + akoff + (uint32_t)(mt * 16 * LDT) * 2);
#pragma unroll
            for (int nt = 0; nt < 4; nt++)
                LDSM_X2_T(bh[nt][0], bh[nt][1],
                          sB0 + bt_base + bkoff + (uint32_t)(nt * 8) * 2);
#pragma unroll
            for (int mt = 0; mt < 4; mt++)
#pragma unroll
                for (int nt = 0; nt < 4; nt++)
                    MMA_BF16(acc[mt][nt], ah[mt][0], ah[mt][1], ah[mt][2], ah[mt][3],
                             bh[nt][0], bh[nt][1]);
            {
                uint32_t bm[4][2], am[4][4];
#pragma unroll
                for (int nt = 0; nt < 4; nt++)
                    LDSM_X2_T(bm[nt][0], bm[nt][1],
                              sB1 + bt_base + bkoff + (uint32_t)(nt * 8) * 2);
#pragma unroll
                for (int mt = 0; mt < 4; mt++)
#pragma unroll
                    for (int nt = 0; nt < 4; nt++)
                        MMA_BF16(acc[mt][nt], ah[mt][0], ah[mt][1], ah[mt][2], ah[mt][3],
                                 bm[nt][0], bm[nt][1]);
#pragma unroll
                for (int mt = 0; mt < 4; mt++)
                    LDSM_X4(am[mt][0], am[mt][1], am[mt][2], am[mt][3],
                            sA1 + a_base + akoff + (uint32_t)(mt * 16 * LDT) * 2);
#pragma unroll
                for (int mt = 0; mt < 4; mt++)
#pragma unroll
                    for (int nt = 0; nt < 4; nt++) {
                        MMA_BF16(acc[mt][nt], am[mt][0], am[mt][1], am[mt][2], am[mt][3],
                                 bh[nt][0], bh[nt][1]);
                        if (SP == 3)
                            MMA_BF16(acc[mt][nt], am[mt][0], am[mt][1], am[mt][2], am[mt][3],
                                     bm[nt][0], bm[nt][1]);
                    }
            }
            if (SP == 3) {
                {
                    uint32_t bl[4][2];
#pragma unroll
                    for (int nt = 0; nt < 4; nt++)
                        LDSM_X2_T(bl[nt][0], bl[nt][1],
                                  sB2 + bt_base + bkoff + (uint32_t)(nt * 8) * 2);
#pragma unroll
                    for (int mt = 0; mt < 4; mt++)
#pragma unroll
                        for (int nt = 0; nt < 4; nt++)
                            MMA_BF16(acc[mt][nt], ah[mt][0], ah[mt][1], ah[mt][2], ah[mt][3],
                                     bl[nt][0], bl[nt][1]);
                }
                {
                    uint32_t al[4][4];
#pragma unroll
                    for (int mt = 0; mt < 4; mt++)
                        LDSM_X4(al[mt][0], al[mt][1], al[mt][2], al[mt][3],
                                sA2 + a_base + akoff + (uint32_t)(mt * 16 * LDT) * 2);
#pragma unroll
                    for (int mt = 0; mt < 4; mt++)
#pragma unroll
                        for (int nt = 0; nt < 4; nt++)
                            MMA_BF16(acc[mt][nt], al[mt][0], al[mt][1], al[mt][2], al[mt][3],
                                     bh[nt][0], bh[nt][1]);
                }
            }
        }
        __syncthreads();
    }

    // epilogue
#pragma unroll
    for (int mt = 0; mt < 4; mt++) {
#pragma unroll
        for (int nt = 0; nt < 4; nt++) {
            int lm = wm * 64 + mt * 16 + group;
            int ln = wn * 32 + nt * 8 + tig * 2;
            int gm = m0 + lm, gn = n0 + ln;
            float b0 = 0.f, b1 = 0.f;
            if (BIAS) { b0 = bias[gn]; b1 = bias[gn + 1]; }
            if (gm < M)
                *reinterpret_cast<float2*>(C + (size_t)gm * N + gn) =
                    make_float2(acc[mt][nt][0] + b0, acc[mt][nt][1] + b1);
            if (gm + 8 < M)
                *reinterpret_cast<float2*>(C + (size_t)(gm + 8) * N + gn) =
                    make_float2(acc[mt][nt][2] + b0, acc[mt][nt][3] + b1);
        }
    }
}

// ---------------- split kernels ---------------------------------------------------
__global__ void split3_kernel(const float* __restrict__ U,
                              __nv_bfloat16* __restrict__ Uh,
                              __nv_bfloat16* __restrict__ Um,
                              __nv_bfloat16* __restrict__ Ul, int total)
{
    int i = blockIdx.x * blockDim.x + threadIdx.x;
    if (i >= total) return;
    float x = U[i];
    __nv_bfloat16 h = __float2bfloat16(x);
    float r = x - __bfloat162float(h);
    __nv_bfloat16 m = __float2bfloat16(r);
    float r2 = r - __bfloat162float(m);
    Uh[i] = h; Um[i] = m; Ul[i] = __float2bfloat16(r2);
}

__global__ void split2_kernel(const float* __restrict__ U,
                              __nv_bfloat16* __restrict__ Uh,
                              __nv_bfloat16* __restrict__ Um, int total)
{
    int i = blockIdx.x * blockDim.x + threadIdx.x;
    if (i >= total) return;
    float x = U[i];
    __nv_bfloat16 h = __float2bfloat16(x);
    float r = x - __bfloat162float(h);
    Uh[i] = h; Um[i] = __float2bfloat16(r);
}

// gather concat -> 3-way bf16 splits directly
__global__ void gather_split3_kernel(const float* __restrict__ emb1,
                                     const float* __restrict__ demand,
                                     const float* __restrict__ supply,
                                     __nv_bfloat16* __restrict__ Xh,
                                     __nv_bfloat16* __restrict__ Xm,
                                     __nv_bfloat16* __restrict__ Xl, int n, int T)
{
    int i = blockIdx.x * blockDim.x + threadIdx.x;
    int total = n * DDIM;
    if (i >= total) return;
    int node = i / DDIM, d = i % DDIM;
    float v[3];
    v[0] = emb1[(size_t)node * DDIM + d];
    v[1] = demand[((size_t)node * T + (T - 1)) * DDIM + d];
    v[2] = supply[((size_t)node * T + (T - 1)) * DDIM + d];
#pragma unroll
    for (int s = 0; s < 3; s++) {
        size_t idx = (size_t)node * K3 + s * DDIM + d;
        float x = v[s];
        __nv_bfloat16 h = __float2bfloat16(x);
        float r = x - __bfloat162float(h);
        __nv_bfloat16 m = __float2bfloat16(r);
        float r2 = r - __bfloat162float(m);
        Xh[idx] = h; Xm[idx] = m; Xl[idx] = __float2bfloat16(r2);
    }
}

// ---------------- small kernels ---------------------------------------------------
__global__ void softmax_relu_kernel(float* __restrict__ Z, int n,
                                    int* __restrict__ nnz,
                                    int* __restrict__ sr, int* __restrict__ sc,
                                    float* __restrict__ sv,
                                    float* __restrict__ deg)
{
    __shared__ float row[NNODE];
    __shared__ float red[256];
    int r = blockIdx.x;
    int t = threadIdx.x;
    float* zr = Z + (size_t)r * n;

    float mx = -3.4e38f;
    for (int c = t; c < n; c += 256) {
        float v = zr[c];
        row[c] = v;
        mx = fmaxf(mx, v);
    }
    red[t] = mx; __syncthreads();
    for (int s = 128; s > 0; s >>= 1) {
        if (t < s) red[t] = fmaxf(red[t], red[t + s]);
        __syncthreads();
    }
    mx = red[0];
    __syncthreads();

    float sm = 0.f;
    for (int c = t; c < n; c += 256) {
        float e = expf(row[c] - mx);
        row[c] = e;
        sm += e;
    }
    red[t] = sm; __syncthreads();
    for (int s = 128; s > 0; s >>= 1) {
        if (t < s) red[t] += red[t + s];
        __syncthreads();
    }
    float inv = 1.0f / red[0];
    for (int c = t; c < n; c += 256) {
        float p = row[c] * inv - 0.2f;
        p = p > 0.f ? p : 0.f;
        zr[c] = p;
        if (p > 0.f) {
            int idx = atomicAdd(nnz, 1);
            if (idx < MAXNNZ) {
                sr[idx] = r; sc[idx] = c; sv[idx] = p;
            }
            atomicAdd(&deg[c], p);
        }
    }
}

__global__ void fill_kernel(float* p, float v, int n)
{
    int i = blockIdx.x * blockDim.x + threadIdx.x;
    if (i < n) p[i] = v;
}

__global__ void zero_int_kernel(int* p) { *p = 0; }

__global__ void rsqrt_kernel(float* __restrict__ dst, const float* __restrict__ src, int n)
{
    int i = blockIdx.x * blockDim.x + threadIdx.x;
    if (i < n) dst[i] = rsqrtf(src[i]);
}

__global__ void dense_scatter_kernel(const float* __restrict__ xw,
                                     const int* __restrict__ sr,
                                     const int* __restrict__ sc,
                                     const float* __restrict__ sv,
                                     const float* __restrict__ dis,
                                     float* __restrict__ agg,
                                     const int* __restrict__ nnz)
{
    int warp = (blockIdx.x * blockDim.x + threadIdx.x) >> 5;
    int lane = threadIdx.x & 31;
    int m = *nnz; if (m > MAXNNZ) m = MAXNNZ;
    if (warp >= m) return;
    int r = sr[warp], c = sc[warp];
    float w = sv[warp] * dis[r];
    const float* xr = xw + (size_t)r * DDIM;
    float* ar = agg + (size_t)c * DDIM;
    for (int f = lane; f < DDIM; f += 32)
        atomicAdd(&ar[f], w * xr[f]);
}

// temp = 0.9*(dis[c]*Z2 + dis[c]^2*xw + b) + 0.1*temp ; also emit h/m splits
__global__ void dense_combine_kernel(float* __restrict__ temp, const float* __restrict__ Z2,
                                     const float* __restrict__ xw, const float* __restrict__ dis,
                                     const float* __restrict__ b, int n, int d,
                                     __nv_bfloat16* __restrict__ th,
                                     __nv_bfloat16* __restrict__ tm)
{
    int i = blockIdx.x * blockDim.x + threadIdx.x;
    if (i >= n * d) return;
    int c = i / d, dd = i - c * d;
    float s = dis[c];
    float out = s * Z2[i] + s * s * xw[i] + b[dd];
    float v = (1.0f - PRESERVE_F) * out + PRESERVE_F * temp[i];
    temp[i] = v;
    __nv_bfloat16 h = __float2bfloat16(v);
    th[i] = h; tm[i] = __float2bfloat16(v - __bfloat162float(h));
}

__global__ void edge_deg_kernel(const int* __restrict__ dst, const float* __restrict__ attr,
                                float* __restrict__ deg2, int E)
{
    int e = blockIdx.x * blockDim.x + threadIdx.x;
    if (e < E) atomicAdd(&deg2[dst[e]], attr[e]);
}

__global__ void enorm_kernel(const int* __restrict__ src, const int* __restrict__ dst,
                             const float* __restrict__ attr, const float* __restrict__ dis2,
                             float* __restrict__ enorm, int E)
{
    int e = blockIdx.x * blockDim.x + threadIdx.x;
    if (e < E) enorm[e] = dis2[src[e]] * attr[e] * dis2[dst[e]];
}

__global__ void scatter_kernel(const float* __restrict__ xw, const int* __restrict__ src,
                               const int* __restrict__ dst, const float* __restrict__ enorm,
                               float* __restrict__ agg, int E, int d)
{
    int warp = (blockIdx.x * blockDim.x + threadIdx.x) >> 5;
    int lane = threadIdx.x & 31;
    if (warp >= E) return;
    int s = src[warp], t = dst[warp];
    float w = enorm[warp];
    const float* xr = xw + (size_t)s * d;
    float* ar = agg + (size_t)t * d;
    for (int f = lane; f < d; f += 32)
        atomicAdd(&ar[f], w * xr[f]);
}

__global__ void sparse_combine_kernel(float* __restrict__ temp, const float* __restrict__ agg,
                                      const float* __restrict__ xw, const float* __restrict__ dis2,
                                      const float* __restrict__ b, int n, int d,
                                      __nv_bfloat16* __restrict__ th,
                                      __nv_bfloat16* __restrict__ tm)
{
    int i = blockIdx.x * blockDim.x + threadIdx.x;
    if (i >= n * d) return;
    int c = i / d, dd = i - c * d;
    float s = dis2[c];
    float out = agg[i] + s * s * xw[i] + b[dd];
    float v = (1.0f - PRESERVE_F) * out + PRESERVE_F * temp[i];
    temp[i] = v;
    __nv_bfloat16 h = __float2bfloat16(v);
    th[i] = h; tm[i] = __float2bfloat16(v - __bfloat162float(h));
}

__global__ void add_kernel(float* __restrict__ out, const float* __restrict__ a,
                           const float* __restrict__ b, int n)
{
    int i = blockIdx.x * blockDim.x + threadIdx.x;
    if (i < n) out[i] = a[i] + b[i];
}

// ---------------- host orchestration ----------------------------------------------
extern "C" void kernel_launch(void* const* d_in, const int* in_sizes, int n_in,
                              void* d_out, int out_size)
{
    const float* demand  = (const float*)d_in[0];
    const float* supply  = (const float*)d_in[1];
    const int*   eidx    = (const int*)  d_in[2];
    const float* eattr   = (const float*)d_in[3];
    const float* emb1    = (const float*)d_in[4];
    const float* fuse_W  = (const float*)d_in[5];
    const float* fuse_b  = (const float*)d_in[6];
    const float* gnn0_W  = (const float*)d_in[7];
    const float* gnn0_b  = (const float*)d_in[8];
    const float* gnn1_W  = (const float*)d_in[9];
    const float* gnn1_b  = (const float*)d_in[10];

    const int n = in_sizes[4] / DDIM;             // 8000
    const int E = in_sizes[3];                    // 256000
    const int T = in_sizes[0] / (n * DDIM);       // 16

    float* out_emb1  = (float*)d_out;
    float* out_skill = out_emb1 + (size_t)n * DDIM;
    float* out_pred  = out_skill + (size_t)n * DDIM;

    float *pU, *ptD, *ptS, *pxw, *pZ2, *pdeg, *pdis, *pdeg2, *pdis2, *pen, *psv;
    int *pnnz, *psr, *psc;
    __nv_bfloat16 *pX3h, *pX3m, *pX3l, *pUh, *pUm, *pUl;
    __nv_bfloat16 *ptDh, *ptDm, *ptSh, *ptSm;
    __nv_bfloat16 *pWfh, *pWfm, *pWfl, *pW0h, *pW0m, *pW1h, *pW1m;
    cudaGetSymbolAddress((void**)&pU,   g_U);
    cudaGetSymbolAddress((void**)&ptD,  g_tmpD);
    cudaGetSymbolAddress((void**)&ptS,  g_tmpS);
    cudaGetSymbolAddress((void**)&pxw,  g_xw);
    cudaGetSymbolAddress((void**)&pZ2,  g_Z2);
    cudaGetSymbolAddress((void**)&pdeg, g_deg);
    cudaGetSymbolAddress((void**)&pdis, g_dis);
    cudaGetSymbolAddress((void**)&pdeg2,g_deg2);
    cudaGetSymbolAddress((void**)&pdis2,g_dis2);
    cudaGetSymbolAddress((void**)&pen,  g_enorm);
    cudaGetSymbolAddress((void**)&pnnz, g_nnz);
    cudaGetSymbolAddress((void**)&psr,  g_sp_r);
    cudaGetSymbolAddress((void**)&psc,  g_sp_c);
    cudaGetSymbolAddress((void**)&psv,  g_sp_v);
    cudaGetSymbolAddress((void**)&pX3h, g_X3h);
    cudaGetSymbolAddress((void**)&pX3m, g_X3m);
    cudaGetSymbolAddress((void**)&pX3l, g_X3l);
    cudaGetSymbolAddress((void**)&pUh,  g_Uh);
    cudaGetSymbolAddress((void**)&pUm,  g_Um);
    cudaGetSymbolAddress((void**)&pUl,  g_Ul);
    cudaGetSymbolAddress((void**)&ptDh, g_tDh);
    cudaGetSymbolAddress((void**)&ptDm, g_tDm);
    cudaGetSymbolAddress((void**)&ptSh, g_tSh);
    cudaGetSymbolAddress((void**)&ptSm, g_tSm);
    cudaGetSymbolAddress((void**)&pWfh, g_Wfh);
    cudaGetSymbolAddress((void**)&pWfm, g_Wfm);
    cudaGetSymbolAddress((void**)&pWfl, g_Wfl);
    cudaGetSymbolAddress((void**)&pW0h, g_W0h);
    cudaGetSymbolAddress((void**)&pW0m, g_W0m);
    cudaGetSymbolAddress((void**)&pW1h, g_W1h);
    cudaGetSymbolAddress((void**)&pW1m, g_W1m);

    static int attr_set = 0;
    if (!attr_set) {
        cudaFuncSetAttribute(syrk_mma_kernel,
                             cudaFuncAttributeMaxDynamicSharedMemorySize, SYRK_SMEM_DYN);
        cudaFuncSetAttribute(gemm_mma_kernel<3, true>,
                             cudaFuncAttributeMaxDynamicSharedMemorySize, 113664);
        cudaFuncSetAttribute(gemm_mma_kernel<2, false>,
                             cudaFuncAttributeMaxDynamicSharedMemorySize, 75776);
        attr_set = 1;
    }

    const int ND = n * DDIM;
    const int TPB = 256;
    dim3 blk(TPB);

    // 1) gather + split X3; split weights
    gather_split3_kernel<<<(ND + TPB - 1) / TPB, blk>>>(emb1, demand, supply,
                                                        pX3h, pX3m, pX3l, n, T);
    split3_kernel<<<(K3 * DDIM + TPB - 1) / TPB, blk>>>(fuse_W, pWfh, pWfm, pWfl, K3 * DDIM);
    split2_kernel<<<(LLAYERS * DDIM * DDIM + TPB - 1) / TPB, blk>>>(gnn0_W, pW0h, pW0m,
                                                                    LLAYERS * DDIM * DDIM);
    split2_kernel<<<(LLAYERS * DDIM * DDIM + TPB - 1) / TPB, blk>>>(gnn1_W, pW1h, pW1m,
                                                                    LLAYERS * DDIM * DDIM);

    // 2) update_emb = X3 @ fuse_W + fuse_b  (MMA, 3-split)
    {
        dim3 grid(DDIM / 128, (n + 127) / 128);
        gemm_mma_kernel<3, true><<<grid, blk, 113664>>>(pX3h, pX3m, pX3l,
                                                        pWfh, pWfm, pWfl,
                                                        pU, fuse_b, n, DDIM, K3);
    }

    // 3) split U; logits syrk (pipelined)
    split3_kernel<<<(ND + TPB - 1) / TPB, blk>>>(pU, pUh, pUm, pUl, ND);
    {
        int nblk = (n + 127) / 128;
        int ntiles = nblk * (nblk + 1) / 2;
        syrk_mma_kernel<<<ntiles, 256, SYRK_SMEM_DYN>>>(pUh, pUm, pUl, out_pred, n);
    }

    // 4) softmax prep + run
    fill_kernel<<<(n + TPB - 1) / TPB, blk>>>(pdeg, 1.0f, n);
    zero_int_kernel<<<1, 1>>>(pnnz);
    softmax_relu_kernel<<<n, blk>>>(out_pred, n, pnnz, psr, psc, psv, pdeg);
    rsqrt_kernel<<<(n + TPB - 1) / TPB, blk>>>(pdis, pdeg, n);

    // 5) temps start at update_emb
    cudaMemcpyAsync(ptD, pU, (size_t)ND * sizeof(float), cudaMemcpyDeviceToDevice);
    cudaMemcpyAsync(ptS, pU, (size_t)ND * sizeof(float), cudaMemcpyDeviceToDevice);

    // 6) dense GCN layers (sparse-form propagation)
    for (int l = 0; l < LLAYERS; l++) {
        const __nv_bfloat16* Ah = (l == 0) ? pUh : ptDh;
        const __nv_bfloat16* Am = (l == 0) ? pUm : ptDm;
        dim3 grid(DDIM / 128, (n + 127) / 128);
        gemm_mma_kernel<2, false><<<grid, blk, 75776>>>(Ah, Am, nullptr,
                                                        pW0h + (size_t)l * DDIM * DDIM,
                                                        pW0m + (size_t)l * DDIM * DDIM,
                                                        nullptr, pxw, nullptr,
                                                        n, DDIM, DDIM);
        fill_kernel<<<(ND + TPB - 1) / TPB, blk>>>(pZ2, 0.0f, ND);
        {
            int blocks = (MAXNNZ * 32 + TPB - 1) / TPB;
            dense_scatter_kernel<<<blocks, blk>>>(pxw, psr, psc, psv, pdis, pZ2, pnnz);
        }
        dense_combine_kernel<<<(ND + TPB - 1) / TPB, blk>>>(ptD, pZ2, pxw, pdis,
                                                            gnn0_b + (size_t)l * DDIM,
                                                            n, DDIM, ptDh, ptDm);
    }

    // 7) sparse graph normalization
    fill_kernel<<<(n + TPB - 1) / TPB, blk>>>(pdeg2, 1.0f, n);
    edge_deg_kernel<<<(E + TPB - 1) / TPB, blk>>>(eidx + E, eattr, pdeg2, E);
    rsqrt_kernel<<<(n + TPB - 1) / TPB, blk>>>(pdis2, pdeg2, n);
    enorm_kernel<<<(E + TPB - 1) / TPB, blk>>>(eidx, eidx + E, eattr, pdis2, pen, E);

    // 8) sparse GCN layers
    for (int l = 0; l < LLAYERS; l++) {
        const __nv_bfloat16* Ah = (l == 0) ? pUh : ptSh;
        const __nv_bfloat16* Am = (l == 0) ? pUm : ptSm;
        dim3 grid(DDIM / 128, (n + 127) / 128);
        gemm_mma_kernel<2, false><<<grid, blk, 75776>>>(Ah, Am, nullptr,
                                                        pW1h + (size_t)l * DDIM * DDIM,
                                                        pW1m + (size_t)l * DDIM * DDIM,
                                                        nullptr, pxw, nullptr,
                                                        n, DDIM, DDIM);
        fill_kernel<<<(ND + TPB - 1) / TPB, blk>>>(pZ2, 0.0f, ND);
        {
            int blocks = (E * 32 + TPB - 1) / TPB;
            scatter_kernel<<<blocks, blk>>>(pxw, eidx, eidx + E, pen, pZ2, E, DDIM);
        }
        sparse_combine_kernel<<<(ND + TPB - 1) / TPB, blk>>>(ptS, pZ2, pxw, pdis2,
                                                             gnn1_b + (size_t)l * DDIM,
                                                             n, DDIM, ptSh, ptSm);
    }

    // 9) outputs
    cudaMemcpyAsync(out_emb1, emb1, (size_t)ND * sizeof(float), cudaMemcpyDeviceToDevice);
    add_kernel<<<(ND + TPB - 1) / TPB, blk>>>(out_skill, ptD, ptS, ND);
}

// round 7
// speedup vs baseline: 5.5897x; 1.0046x over previous
#include <cuda_runtime.h>
#include <cuda_bf16.h>
#include <math.h>
#include <stdint.h>

#define NNODE 8000
#define DDIM  256
#define K3    768
#define EMAX  256000
#define LLAYERS 2
#define PRESERVE_F 0.1f
#define MAXNNZ (4 * NNODE)   // softmax rows sum to 1 => <=4 entries/row exceed 0.2

// ---------------- scratch (static device memory) ---------------------------------
__device__ float g_U [NNODE * DDIM];
__device__ float g_tmpD[NNODE * DDIM];
__device__ float g_tmpS[NNODE * DDIM];
__device__ float g_xw [NNODE * DDIM];
__device__ float g_Z2 [NNODE * DDIM];
__device__ float g_deg [NNODE];
__device__ float g_dis [NNODE];
__device__ float g_deg2[NNODE];
__device__ float g_dis2[NNODE];
__device__ float g_enorm[EMAX];
__device__ int   g_nnz;
__device__ int   g_sp_r[MAXNNZ];
__device__ int   g_sp_c[MAXNNZ];
__device__ float g_sp_v[MAXNNZ];
// bf16 splits
__device__ __nv_bfloat16 g_X3h[NNODE * K3];
__device__ __nv_bfloat16 g_X3m[NNODE * K3];
__device__ __nv_bfloat16 g_X3l[NNODE * K3];
__device__ __nv_bfloat16 g_Uh[NNODE * DDIM];
__device__ __nv_bfloat16 g_Um[NNODE * DDIM];
__device__ __nv_bfloat16 g_Ul[NNODE * DDIM];
__device__ __nv_bfloat16 g_tDh[NNODE * DDIM];
__device__ __nv_bfloat16 g_tDm[NNODE * DDIM];
__device__ __nv_bfloat16 g_tSh[NNODE * DDIM];
__device__ __nv_bfloat16 g_tSm[NNODE * DDIM];
__device__ __nv_bfloat16 g_Wfh[K3 * DDIM];
__device__ __nv_bfloat16 g_Wfm[K3 * DDIM];
__device__ __nv_bfloat16 g_Wfl[K3 * DDIM];
__device__ __nv_bfloat16 g_W0h[LLAYERS * DDIM * DDIM];
__device__ __nv_bfloat16 g_W0m[LLAYERS * DDIM * DDIM];
__device__ __nv_bfloat16 g_W1h[LLAYERS * DDIM * DDIM];
__device__ __nv_bfloat16 g_W1m[LLAYERS * DDIM * DDIM];

__device__ __forceinline__ uint32_t smem_u32(const void* p) {
    uint32_t a;
    asm("{ .reg .u64 t; cvta.to.shared.u64 t, %1; cvt.u32.u64 %0, t; }" : "=r"(a) : "l"(p));
    return a;
}

__device__ __forceinline__ void red_add_v4(float* addr, float4 v) {
    asm volatile("red.global.add.v4.f32 [%0], {%1,%2,%3,%4};"
                 :: "l"(addr), "f"(v.x), "f"(v.y), "f"(v.z), "f"(v.w) : "memory");
}

#define LDSM_X4(r0, r1, r2, r3, addr) \
    asm volatile("ldmatrix.sync.aligned.m8n8.x4.shared.b16 {%0,%1,%2,%3}, [%4];" \
                 : "=r"(r0), "=r"(r1), "=r"(r2), "=r"(r3) : "r"(addr))
#define LDSM_X2(r0, r1, addr) \
    asm volatile("ldmatrix.sync.aligned.m8n8.x2.shared.b16 {%0,%1}, [%2];" \
                 : "=r"(r0), "=r"(r1) : "r"(addr))
#define LDSM_X2_T(r0, r1, addr) \
    asm volatile("ldmatrix.sync.aligned.m8n8.x2.trans.shared.b16 {%0,%1}, [%2];" \
                 : "=r"(r0), "=r"(r1) : "r"(addr))
#define MMA_BF16(c, a0, a1, a2, a3, b0, b1) \
    asm volatile("mma.sync.aligned.m16n8k16.row.col.f32.bf16.bf16.f32 " \
                 "{%0,%1,%2,%3}, {%4,%5,%6,%7}, {%8,%9}, {%0,%1,%2,%3};" \
                 : "+f"((c)[0]), "+f"((c)[1]), "+f"((c)[2]), "+f"((c)[3]) \
                 : "r"(a0), "r"(a1), "r"(a2), "r"(a3), "r"(b0), "r"(b1))
#define CP_ASYNC16(saddr, gptr, sz) \
    asm volatile("cp.async.cg.shared.global [%0], [%1], 16, %2;" \
                 :: "r"(saddr), "l"(gptr), "r"(sz))
#define CP_COMMIT() asm volatile("cp.async.commit_group;")
#define CP_WAIT2()  asm volatile("cp.async.wait_group 2;")
#define CP_WAIT1()  asm volatile("cp.async.wait_group 1;")
#define CP_WAIT0()  asm volatile("cp.async.wait_group 0;")

#define LDT 40   // A-tile smem stride (bf16), 80 B  (conflict-free for ldmatrix)
#define LDB 136  // B-tile smem stride (bf16), 272 B

// =================== syrk: C = U @ U^T (3-way bf16 split, 3-stage pipeline) ======
#define SYRK_TILE_ELEMS (128 * LDT)
#define SYRK_STAGE_ELEMS (6 * SYRK_TILE_ELEMS)
#define SYRK_SMEM_DYN (3 * SYRK_STAGE_ELEMS * 2)   // 184320 B

__global__ __launch_bounds__(256)
void syrk_mma_kernel(const __nv_bfloat16* __restrict__ Uh,
                     const __nv_bfloat16* __restrict__ Um,
                     const __nv_bfloat16* __restrict__ Ul,
                     float* __restrict__ C, int n)
{
    extern __shared__ char smem[];
    __nv_bfloat16* tiles = (__nv_bfloat16*)smem;
    float* epi = (float*)smem;

    const int tid  = threadIdx.x;
    const int wid  = tid >> 5;
    const int lane = tid & 31;
    const int wm   = wid & 1;
    const int wn   = wid >> 1;
    const int group = lane >> 2;
    const int tig   = lane & 3;

    int t = blockIdx.x;
    int bi = (int)((sqrtf(8.0f * (float)t + 1.0f) - 1.0f) * 0.5f);
    while ((bi + 1) * (bi + 2) / 2 <= t) bi++;
    while (bi * (bi + 1) / 2 > t) bi--;
    int bj = t - bi * (bi + 1) / 2;
    const int m0 = bi * 128;
    const int n0 = bj * 128;

    float acc[4][4][4];
#pragma unroll
    for (int a = 0; a < 4; a++)
#pragma unroll
        for (int b = 0; b < 4; b++)
#pragma unroll
            for (int c = 0; c < 4; c++) acc[a][b][c] = 0.f;

    const __nv_bfloat16* srcs[6] = { Uh, Um, Ul, Uh, Um, Ul };
    const uint32_t sT = smem_u32(tiles);

    const int a_row = (lane & 15);
    const int a_col = (lane >> 4) * 8;
    const int b_row = (lane & 7);
    const int b_col = ((lane >> 3) & 1) * 8;
    const uint32_t a_base = (uint32_t)((wm * 64 + a_row) * LDT + a_col) * 2;
    const uint32_t b_base = (uint32_t)((wn * 32 + b_row) * LDT + b_col) * 2;

    auto load_chunk = [&](int k0, int stage) {
        uint32_t dst0 = sT + (uint32_t)(stage * SYRK_STAGE_ELEMS) * 2;
#pragma unroll
        for (int s = 0; s < 6; s++) {
            const __nv_bfloat16* src = srcs[s];
            const int rowbase = (s < 3) ? m0 : n0;
            uint32_t dts = dst0 + (uint32_t)(s * SYRK_TILE_ELEMS) * 2;
#pragma unroll
            for (int it = 0; it < 2; it++) {
                int lin = it * 256 + tid;
                int r   = lin >> 2;
                int c8  = (lin & 3) * 8;
                int g   = rowbase + r;
                uint32_t sz = (g < n) ? 16u : 0u;
                int g2 = (g < n) ? g : 0;
                const __nv_bfloat16* gp = src + (size_t)g2 * DDIM + k0 + c8;
                CP_ASYNC16(dts + (uint32_t)(r * LDT + c8) * 2, gp, sz);
            }
        }
    };

    load_chunk(0, 0);
    CP_COMMIT();
    load_chunk(32, 1);
    CP_COMMIT();

#pragma unroll 1
    for (int kc = 0; kc < 8; kc++) {
        const int cur = kc % 3;
        if (kc + 2 < 8) {
            load_chunk((kc + 2) * 32, (kc + 2) % 3);
            CP_COMMIT();
            CP_WAIT2();
        } else if (kc + 1 < 8) {
            CP_WAIT1();
        } else {
            CP_WAIT0();
        }
        __syncthreads();

        const uint32_t stg = sT + (uint32_t)(cur * SYRK_STAGE_ELEMS) * 2;
        const uint32_t sA0 = stg;
        const uint32_t sA1 = stg + SYRK_TILE_ELEMS * 2u;
        const uint32_t sA2 = stg + SYRK_TILE_ELEMS * 4u;
        const uint32_t sB0 = stg + SYRK_TILE_ELEMS * 6u;
        const uint32_t sB1 = stg + SYRK_TILE_ELEMS * 8u;
        const uint32_t sB2 = stg + SYRK_TILE_ELEMS * 10u;

#pragma unroll
        for (int ks = 0; ks < 2; ks++) {
            const uint32_t koff = (uint32_t)(ks * 16) * 2;
            uint32_t ah[4][4], bh[4][2];
#pragma unroll
            for (int mt = 0; mt < 4; mt++)
                LDSM_X4(ah[mt][0], ah[mt][1], ah[mt][2], ah[mt][3],
                        sA0 + a_base + koff + (uint32_t)(mt * 16 * LDT) * 2);
#pragma unroll
            for (int nt = 0; nt < 4; nt++)
                LDSM_X2(bh[nt][0], bh[nt][1],
                        sB0 + b_base + koff + (uint32_t)(nt * 8 * LDT) * 2);
#pragma unroll
            for (int mt = 0; mt < 4; mt++)
#pragma unroll
                for (int nt = 0; nt < 4; nt++)
                    MMA_BF16(acc[mt][nt], ah[mt][0], ah[mt][1], ah[mt][2], ah[mt][3],
                             bh[nt][0], bh[nt][1]);
            {
                uint32_t bm[4][2], am[4][4];
#pragma unroll
                for (int nt = 0; nt < 4; nt++)
                    LDSM_X2(bm[nt][0], bm[nt][1],
                            sB1 + b_base + koff + (uint32_t)(nt * 8 * LDT) * 2);
#pragma unroll
                for (int mt = 0; mt < 4; mt++)
#pragma unroll
                    for (int nt = 0; nt < 4; nt++)
                        MMA_BF16(acc[mt][nt], ah[mt][0], ah[mt][1], ah[mt][2], ah[mt][3],
                                 bm[nt][0], bm[nt][1]);
#pragma unroll
                for (int mt = 0; mt < 4; mt++)
                    LDSM_X4(am[mt][0], am[mt][1], am[mt][2], am[mt][3],
                            sA1 + a_base + koff + (uint32_t)(mt * 16 * LDT) * 2);
#pragma unroll
                for (int mt = 0; mt < 4; mt++)
#pragma unroll
                    for (int nt = 0; nt < 4; nt++) {
                        MMA_BF16(acc[mt][nt], am[mt][0], am[mt][1], am[mt][2], am[mt][3],
                                 bh[nt][0], bh[nt][1]);
                        MMA_BF16(acc[mt][nt], am[mt][0], am[mt][1], am[mt][2], am[mt][3],
                                 bm[nt][0], bm[nt][1]);
                    }
            }
            {
                uint32_t bl[4][2];
#pragma unroll
                for (int nt = 0; nt < 4; nt++)
                    LDSM_X2(bl[nt][0], bl[nt][1],
                            sB2 + b_base + koff + (uint32_t)(nt * 8 * LDT) * 2);
#pragma unroll
                for (int mt = 0; mt < 4; mt++)
#pragma unroll
                    for (int nt = 0; nt < 4; nt++)
                        MMA_BF16(acc[mt][nt], ah[mt][0], ah[mt][1], ah[mt][2], ah[mt][3],
                                 bl[nt][0], bl[nt][1]);
            }
            {
                uint32_t al[4][4];
#pragma unroll
                for (int mt = 0; mt < 4; mt++)
                    LDSM_X4(al[mt][0], al[mt][1], al[mt][2], al[mt][3],
                            sA2 + a_base + koff + (uint32_t)(mt * 16 * LDT) * 2);
#pragma unroll
                for (int mt = 0; mt < 4; mt++)
#pragma unroll
                    for (int nt = 0; nt < 4; nt++)
                        MMA_BF16(acc[mt][nt], al[mt][0], al[mt][1], al[mt][2], al[mt][3],
                                 bh[nt][0], bh[nt][1]);
            }
        }
        __syncthreads();
    }

    // direct write
#pragma unroll
    for (int mt = 0; mt < 4; mt++) {
#pragma unroll
        for (int nt = 0; nt < 4; nt++) {
            int lm = wm * 64 + mt * 16 + group;
            int ln = wn * 32 + nt * 8 + tig * 2;
            int gm = m0 + lm, gn = n0 + ln;
            if (gn + 1 < n) {
                if (gm < n)
                    *reinterpret_cast<float2*>(C + (size_t)gm * n + gn) =
                        make_float2(acc[mt][nt][0], acc[mt][nt][1]);
                if (gm + 8 < n)
                    *reinterpret_cast<float2*>(C + (size_t)(gm + 8) * n + gn) =
                        make_float2(acc[mt][nt][2], acc[mt][nt][3]);
            }
        }
    }

    // mirrored write via smem transpose
    if (bi != bj) {
        __syncthreads();
#pragma unroll
        for (int mt = 0; mt < 4; mt++) {
#pragma unroll
            for (int nt = 0; nt < 4; nt++) {
                int lm = wm * 64 + mt * 16 + group;
                int ln = wn * 32 + nt * 8 + tig * 2;
                epi[lm * 129 + ln]           = acc[mt][nt][0];
                epi[lm * 129 + ln + 1]       = acc[mt][nt][1];
                epi[(lm + 8) * 129 + ln]     = acc[mt][nt][2];
                epi[(lm + 8) * 129 + ln + 1] = acc[mt][nt][3];
            }
        }
        __syncthreads();
        const int c_row = tid >> 1;
        const int half  = tid & 1;
        const int grow  = n0 + c_row;
        if (grow < n) {
            float* outrow = C + (size_t)grow * n;
#pragma unroll
            for (int i = 0; i < 16; i++) {
                int ml = half * 64 + i * 4;
                if (m0 + ml + 3 < n) {
                    float4 v = make_float4(epi[(ml + 0) * 129 + c_row],
                                           epi[(ml + 1) * 129 + c_row],
                                           epi[(ml + 2) * 129 + c_row],
                                           epi[(ml + 3) * 129 + c_row]);
                    *reinterpret_cast<float4*>(outrow + m0 + ml) = v;
                } else {
                    for (int q = 0; q < 4; q++)
                        if (m0 + ml + q < n)
                            outrow[m0 + ml + q] = epi[(ml + q) * 129 + c_row];
                }
            }
        }
    }
}

// =================== general MMA GEMM: C = A @ B (+bias), 3-stage ================
#define GEMM_AT_ELEMS (128 * LDT)
#define GEMM_BT_ELEMS (32 * LDB)

template<int SP, bool BIAS>
__global__ __launch_bounds__(256)
void gemm_mma_kernel(const __nv_bfloat16* __restrict__ Ah_,
                     const __nv_bfloat16* __restrict__ Am_,
                     const __nv_bfloat16* __restrict__ Al_,
                     const __nv_bfloat16* __restrict__ Bh_,
                     const __nv_bfloat16* __restrict__ Bm_,
                     const __nv_bfloat16* __restrict__ Bl_,
                     float* __restrict__ C, const float* __restrict__ bias,
                     int M, int N, int K)
{
    extern __shared__ char smem[];
    __nv_bfloat16* tiles = (__nv_bfloat16*)smem;
    const int STAGE_ELEMS = SP * (GEMM_AT_ELEMS + GEMM_BT_ELEMS);

    const int tid  = threadIdx.x;
    const int wid  = tid >> 5;
    const int lane = tid & 31;
    const int wm   = wid & 1;
    const int wn   = wid >> 1;
    const int group = lane >> 2;
    const int tig   = lane & 3;

    const int n0 = blockIdx.x * 128;
    const int m0 = blockIdx.y * 128;

    float acc[4][4][4];
#pragma unroll
    for (int a = 0; a < 4; a++)
#pragma unroll
        for (int b = 0; b < 4; b++)
#pragma unroll
            for (int c = 0; c < 4; c++) acc[a][b][c] = 0.f;

    const __nv_bfloat16* Asrc[3] = { Ah_, Am_, Al_ };
    const __nv_bfloat16* Bsrc[3] = { Bh_, Bm_, Bl_ };
    const uint32_t sT = smem_u32(tiles);

    const int a_row = (lane & 15);
    const int a_col = (lane >> 4) * 8;
    const uint32_t a_base = (uint32_t)((wm * 64 + a_row) * LDT + a_col) * 2;
    const uint32_t bt_base = (uint32_t)((lane & 15) * LDB + wn * 32) * 2;

    auto load_chunk = [&](int k0, int stage) {
        uint32_t dst0 = sT + (uint32_t)(stage * STAGE_ELEMS) * 2;
#pragma unroll
        for (int s = 0; s < SP; s++) {
            uint32_t dts = dst0 + (uint32_t)(s * GEMM_AT_ELEMS) * 2;
#pragma unroll
            for (int it = 0; it < 2; it++) {
                int lin = it * 256 + tid;
                int r   = lin >> 2;
                int c8  = (lin & 3) * 8;
                int g   = m0 + r;
                uint32_t sz = (g < M) ? 16u : 0u;
                int g2 = (g < M) ? g : 0;
                const __nv_bfloat16* gp = Asrc[s] + (size_t)g2 * K + k0 + c8;
                CP_ASYNC16(dts + (uint32_t)(r * LDT + c8) * 2, gp, sz);
            }
        }
        uint32_t dstB = dst0 + (uint32_t)(SP * GEMM_AT_ELEMS) * 2;
#pragma unroll
        for (int s = 0; s < SP; s++) {
            uint32_t dts = dstB + (uint32_t)(s * GEMM_BT_ELEMS) * 2;
#pragma unroll
            for (int it = 0; it < 2; it++) {
                int lin = it * 256 + tid;
                int r   = lin >> 4;
                int c8  = (lin & 15) * 8;
                const __nv_bfloat16* gp = Bsrc[s] + (size_t)(k0 + r) * N + n0 + c8;
                CP_ASYNC16(dts + (uint32_t)(r * LDB + c8) * 2, gp, 16u);
            }
        }
    };

    const int NC = K / 32;
    load_chunk(0, 0);
    CP_COMMIT();
    if (NC > 1) { load_chunk(32, 1); CP_COMMIT(); }

#pragma unroll 1
    for (int kc = 0; kc < NC; kc++) {
        const int cur = kc % 3;
        if (kc + 2 < NC) {
            load_chunk((kc + 2) * 32, (kc + 2) % 3);
            CP_COMMIT();
            CP_WAIT2();
        } else if (kc + 1 < NC) {
            CP_WAIT1();
        } else {
            CP_WAIT0();
        }
        __syncthreads();

        const uint32_t stg = sT + (uint32_t)(cur * STAGE_ELEMS) * 2;
        const uint32_t sA0 = stg;
        const uint32_t sA1 = stg + GEMM_AT_ELEMS * 2u;
        const uint32_t sA2 = stg + GEMM_AT_ELEMS * 4u;
        const uint32_t sBb = stg + (uint32_t)(SP * GEMM_AT_ELEMS) * 2u;
        const uint32_t sB0 = sBb;
        const uint32_t sB1 = sBb + GEMM_BT_ELEMS * 2u;
        const uint32_t sB2 = sBb + GEMM_BT_ELEMS * 4u;

#pragma unroll
        for (int ks = 0; ks < 2; ks++) {
            const uint32_t akoff = (uint32_t)(ks * 16) * 2;
            const uint32_t bkoff = (uint32_t)(ks * 16 * LDB) * 2;
            uint32_t ah[4][4], bh[4][2];
#pragma unroll
            for (int mt = 0; mt < 4; mt++)
                LDSM_X4(ah[mt][0], ah[mt][1], ah[mt][2], ah[mt][3],
                        sA0 + a_base + akoff + (uint32_t)(mt * 16 * LDT) * 2);
#pragma unroll
            for (int nt = 0; nt < 4; nt++)
                LDSM_X2_T(bh[nt][0], bh[nt][1],
                          sB0 + bt_base + bkoff + (uint32_t)(nt * 8) * 2);
#pragma unroll
            for (int mt = 0; mt < 4; mt++)
#pragma unroll
                for (int nt = 0; nt < 4; nt++)
                    MMA_BF16(acc[mt][nt], ah[mt][0], ah[mt][1], ah[mt][2], ah[mt][3],
                             bh[nt][0], bh[nt][1]);
            {
                uint32_t bm[4][2], am[4][4];
#pragma unroll
                for (int nt = 0; nt < 4; nt++)
                    LDSM_X2_T(bm[nt][0], bm[nt][1],
                              sB1 + bt_base + bkoff + (uint32_t)(nt * 8) * 2);
#pragma unroll
                for (int mt = 0; mt < 4; mt++)
#pragma unroll
                    for (int nt = 0; nt < 4; nt++)
                        MMA_BF16(acc[mt][nt], ah[mt][0], ah[mt][1], ah[mt][2], ah[mt][3],
                                 bm[nt][0], bm[nt][1]);
#pragma unroll
                for (int mt = 0; mt < 4; mt++)
                    LDSM_X4(am[mt][0], am[mt][1], am[mt][2], am[mt][3],
                            sA1 + a_base + akoff + (uint32_t)(mt * 16 * LDT) * 2);
#pragma unroll
                for (int mt = 0; mt < 4; mt++)
#pragma unroll
                    for (int nt = 0; nt < 4; nt++) {
                        MMA_BF16(acc[mt][nt], am[mt][0], am[mt][1], am[mt][2], am[mt][3],
                                 bh[nt][0], bh[nt][1]);
                        if (SP == 3)
                            MMA_BF16(acc[mt][nt], am[mt][0], am[mt][1], am[mt][2], am[mt][3],
                                     bm[nt][0], bm[nt][1]);
                    }
            }
            if (SP == 3) {
                {
                    uint32_t bl[4][2];
#pragma unroll
                    for (int nt = 0; nt < 4; nt++)
                        LDSM_X2_T(bl[nt][0], bl[nt][1],
                                  sB2 + bt_base + bkoff + (uint32_t)(nt * 8) * 2);
#pragma unroll
                    for (int mt = 0; mt < 4; mt++)
#pragma unroll
                        for (int nt = 0; nt < 4; nt++)
                            MMA_BF16(acc[mt][nt], ah[mt][0], ah[mt][1], ah[mt][2], ah[mt][3],
                                     bl[nt][0], bl[nt][1]);
                }
                {
                    uint32_t al[4][4];
#pragma unroll
                    for (int mt = 0; mt < 4; mt++)
                        LDSM_X4(al[mt][0], al[mt][1], al[mt][2], al[mt][3],
                                sA2 + a_base + akoff + (uint32_t)(mt * 16 * LDT) * 2);
#pragma unroll
                    for (int mt = 0; mt < 4; mt++)
#pragma unroll
                        for (int nt = 0; nt < 4; nt++)
                            MMA_BF16(acc[mt][nt], al[mt][0], al[mt][1], al[mt][2], al[mt][3],
                                     bh[nt][0], bh[nt][1]);
                }
            }
        }
        __syncthreads();
    }

    // epilogue
#pragma unroll
    for (int mt = 0; mt < 4; mt++) {
#pragma unroll
        for (int nt = 0; nt < 4; nt++) {
            int lm = wm * 64 + mt * 16 + group;
            int ln = wn * 32 + nt * 8 + tig * 2;
            int gm = m0 + lm, gn = n0 + ln;
            float b0 = 0.f, b1 = 0.f;
            if (BIAS) { b0 = bias[gn]; b1 = bias[gn + 1]; }
            if (gm < M)
                *reinterpret_cast<float2*>(C + (size_t)gm * N + gn) =
                    make_float2(acc[mt][nt][0] + b0, acc[mt][nt][1] + b1);
            if (gm + 8 < M)
                *reinterpret_cast<float2*>(C + (size_t)(gm + 8) * N + gn) =
                    make_float2(acc[mt][nt][2] + b0, acc[mt][nt][3] + b1);
        }
    }
}

// ---------------- split kernels ---------------------------------------------------
__global__ void split3_kernel(const float* __restrict__ U,
                              __nv_bfloat16* __restrict__ Uh,
                              __nv_bfloat16* __restrict__ Um,
                              __nv_bfloat16* __restrict__ Ul, int total)
{
    int i = blockIdx.x * blockDim.x + threadIdx.x;
    if (i >= total) return;
    float x = U[i];
    __nv_bfloat16 h = __float2bfloat16(x);
    float r = x - __bfloat162float(h);
    __nv_bfloat16 m = __float2bfloat16(r);
    float r2 = r - __bfloat162float(m);
    Uh[i] = h; Um[i] = m; Ul[i] = __float2bfloat16(r2);
}

__global__ void split2_kernel(const float* __restrict__ U,
                              __nv_bfloat16* __restrict__ Uh,
                              __nv_bfloat16* __restrict__ Um, int total)
{
    int i = blockIdx.x * blockDim.x + threadIdx.x;
    if (i >= total) return;
    float x = U[i];
    __nv_bfloat16 h = __float2bfloat16(x);
    float r = x - __bfloat162float(h);
    Uh[i] = h; Um[i] = __float2bfloat16(r);
}

__global__ void gather_split3_kernel(const float* __restrict__ emb1,
                                     const float* __restrict__ demand,
                                     const float* __restrict__ supply,
                                     __nv_bfloat16* __restrict__ Xh,
                                     __nv_bfloat16* __restrict__ Xm,
                                     __nv_bfloat16* __restrict__ Xl, int n, int T)
{
    int i = blockIdx.x * blockDim.x + threadIdx.x;
    int total = n * DDIM;
    if (i >= total) return;
    int node = i / DDIM, d = i % DDIM;
    float v[3];
    v[0] = emb1[(size_t)node * DDIM + d];
    v[1] = demand[((size_t)node * T + (T - 1)) * DDIM + d];
    v[2] = supply[((size_t)node * T + (T - 1)) * DDIM + d];
#pragma unroll
    for (int s = 0; s < 3; s++) {
        size_t idx = (size_t)node * K3 + s * DDIM + d;
        float x = v[s];
        __nv_bfloat16 h = __float2bfloat16(x);
        float r = x - __bfloat162float(h);
        __nv_bfloat16 m = __float2bfloat16(r);
        float r2 = r - __bfloat162float(m);
        Xh[idx] = h; Xm[idx] = m; Xl[idx] = __float2bfloat16(r2);
    }
}

// ---------------- small kernels ---------------------------------------------------
__global__ void softmax_relu_kernel(float* __restrict__ Z, int n,
                                    int* __restrict__ nnz,
                                    int* __restrict__ sr, int* __restrict__ sc,
                                    float* __restrict__ sv,
                                    float* __restrict__ deg)
{
    __shared__ float row[NNODE];
    __shared__ float red[256];
    int r = blockIdx.x;
    int t = threadIdx.x;
    float* zr = Z + (size_t)r * n;

    float mx = -3.4e38f;
    for (int c = t; c < n; c += 256) {
        float v = zr[c];
        row[c] = v;
        mx = fmaxf(mx, v);
    }
    red[t] = mx; __syncthreads();
    for (int s = 128; s > 0; s >>= 1) {
        if (t < s) red[t] = fmaxf(red[t], red[t + s]);
        __syncthreads();
    }
    mx = red[0];
    __syncthreads();

    float sm = 0.f;
    for (int c = t; c < n; c += 256) {
        float e = expf(row[c] - mx);
        row[c] = e;
        sm += e;
    }
    red[t] = sm; __syncthreads();
    for (int s = 128; s > 0; s >>= 1) {
        if (t < s) red[t] += red[t + s];
        __syncthreads();
    }
    float inv = 1.0f / red[0];
    for (int c = t; c < n; c += 256) {
        float p = row[c] * inv - 0.2f;
        p = p > 0.f ? p : 0.f;
        zr[c] = p;
        if (p > 0.f) {
            int idx = atomicAdd(nnz, 1);
            if (idx < MAXNNZ) {
                sr[idx] = r; sc[idx] = c; sv[idx] = p;
            }
            atomicAdd(&deg[c], p);
        }
    }
}

__global__ void fill_kernel(float* p, float v, int n)
{
    int i = blockIdx.x * blockDim.x + threadIdx.x;
    if (i < n) p[i] = v;
}

__global__ void zero_int_kernel(int* p) { *p = 0; }

__global__ void rsqrt_kernel(float* __restrict__ dst, const float* __restrict__ src, int n)
{
    int i = blockIdx.x * blockDim.x + threadIdx.x;
    if (i < n) dst[i] = rsqrtf(src[i]);
}

// warp per nonzero: agg[c] += v*dis[r] * xw[r]  (v4 vector reductions)
__global__ void dense_scatter_kernel(const float* __restrict__ xw,
                                     const int* __restrict__ sr,
                                     const int* __restrict__ sc,
                                     const float* __restrict__ sv,
                                     const float* __restrict__ dis,
                                     float* __restrict__ agg,
                                     const int* __restrict__ nnz)
{
    int warp = (blockIdx.x * blockDim.x + threadIdx.x) >> 5;
    int lane = threadIdx.x & 31;
    int m = *nnz; if (m > MAXNNZ) m = MAXNNZ;
    if (warp >= m) return;
    int r = sr[warp], c = sc[warp];
    float w = sv[warp] * dis[r];
    const float4* xr = reinterpret_cast<const float4*>(xw + (size_t)r * DDIM);
    float* ar = agg + (size_t)c * DDIM;
#pragma unroll
    for (int h = 0; h < 2; h++) {
        int f4 = h * 32 + lane;              // 0..63
        float4 x = xr[f4];
        red_add_v4(ar + f4 * 4, make_float4(w * x.x, w * x.y, w * x.z, w * x.w));
    }
}

// temp = 0.9*(dis[c]*Z2 + dis[c]^2*xw + b) + 0.1*temp ; also emit h/m splits
__global__ void dense_combine_kernel(float* __restrict__ temp, const float* __restrict__ Z2,
                                     const float* __restrict__ xw, const float* __restrict__ dis,
                                     const float* __restrict__ b, int n, int d,
                                     __nv_bfloat16* __restrict__ th,
                                     __nv_bfloat16* __restrict__ tm)
{
    int i = blockIdx.x * blockDim.x + threadIdx.x;
    if (i >= n * d) return;
    int c = i / d, dd = i - c * d;
    float s = dis[c];
    float out = s * Z2[i] + s * s * xw[i] + b[dd];
    float v = (1.0f - PRESERVE_F) * out + PRESERVE_F * temp[i];
    temp[i] = v;
    __nv_bfloat16 h = __float2bfloat16(v);
    th[i] = h; tm[i] = __float2bfloat16(v - __bfloat162float(h));
}

__global__ void edge_deg_kernel(const int* __restrict__ dst, const float* __restrict__ attr,
                                float* __restrict__ deg2, int E)
{
    int e = blockIdx.x * blockDim.x + threadIdx.x;
    if (e < E) atomicAdd(&deg2[dst[e]], attr[e]);
}

__global__ void enorm_kernel(const int* __restrict__ src, const int* __restrict__ dst,
                             const float* __restrict__ attr, const float* __restrict__ dis2,
                             float* __restrict__ enorm, int E)
{
    int e = blockIdx.x * blockDim.x + threadIdx.x;
    if (e < E) enorm[e] = dis2[src[e]] * attr[e] * dis2[dst[e]];
}

// warp per edge: agg[dst] += enorm * xw[src]  (v4 vector reductions)
__global__ void scatter_kernel(const float* __restrict__ xw, const int* __restrict__ src,
                               const int* __restrict__ dst, const float* __restrict__ enorm,
                               float* __restrict__ agg, int E, int d)
{
    int warp = (blockIdx.x * blockDim.x + threadIdx.x) >> 5;
    int lane = threadIdx.x & 31;
    if (warp >= E) return;
    int s = src[warp], t = dst[warp];
    float w = enorm[warp];
    const float4* xr = reinterpret_cast<const float4*>(xw + (size_t)s * DDIM);
    float* ar = agg + (size_t)t * DDIM;
#pragma unroll
    for (int h = 0; h < 2; h++) {
        int f4 = h * 32 + lane;
        float4 x = xr[f4];
        red_add_v4(ar + f4 * 4, make_float4(w * x.x, w * x.y, w * x.z, w * x.w));
    }
}

__global__ void sparse_combine_kernel(float* __restrict__ temp, const float* __restrict__ agg,
                                      const float* __restrict__ xw, const float* __restrict__ dis2,
                                      const float* __restrict__ b, int n, int d,
                                      __nv_bfloat16* __restrict__ th,
                                      __nv_bfloat16* __restrict__ tm)
{
    int i = blockIdx.x * blockDim.x + threadIdx.x;
    if (i >= n * d) return;
    int c = i / d, dd = i - c * d;
    float s = dis2[c];
    float out = agg[i] + s * s * xw[i] + b[dd];
    float v = (1.0f - PRESERVE_F) * out + PRESERVE_F * temp[i];
    temp[i] = v;
    __nv_bfloat16 h = __float2bfloat16(v);
    th[i] = h; tm[i] = __float2bfloat16(v - __bfloat162float(h));
}

__global__ void add_kernel(float* __restrict__ out, const float* __restrict__ a,
                           const float* __restrict__ b, int n)
{
    int i = blockIdx.x * blockDim.x + threadIdx.x;
    if (i < n) out[i] = a[i] + b[i];
}

// ---------------- host orchestration ----------------------------------------------
extern "C" void kernel_launch(void* const* d_in, const int* in_sizes, int n_in,
                              void* d_out, int out_size)
{
    const float* demand  = (const float*)d_in[0];
    const float* supply  = (const float*)d_in[1];
    const int*   eidx    = (const int*)  d_in[2];
    const float* eattr   = (const float*)d_in[3];
    const float* emb1    = (const float*)d_in[4];
    const float* fuse_W  = (const float*)d_in[5];
    const float* fuse_b  = (const float*)d_in[6];
    const float* gnn0_W  = (const float*)d_in[7];
    const float* gnn0_b  = (const float*)d_in[8];
    const float* gnn1_W  = (const float*)d_in[9];
    const float* gnn1_b  = (const float*)d_in[10];

    const int n = in_sizes[4] / DDIM;
    const int E = in_sizes[3];
    const int T = in_sizes[0] / (n * DDIM);

    float* out_emb1  = (float*)d_out;
    float* out_skill = out_emb1 + (size_t)n * DDIM;
    float* out_pred  = out_skill + (size_t)n * DDIM;

    float *pU, *ptD, *ptS, *pxw, *pZ2, *pdeg, *pdis, *pdeg2, *pdis2, *pen, *psv;
    int *pnnz, *psr, *psc;
    __nv_bfloat16 *pX3h, *pX3m, *pX3l, *pUh, *pUm, *pUl;
    __nv_bfloat16 *ptDh, *ptDm, *ptSh, *ptSm;
    __nv_bfloat16 *pWfh, *pWfm, *pWfl, *pW0h, *pW0m, *pW1h, *pW1m;
    cudaGetSymbolAddress((void**)&pU,   g_U);
    cudaGetSymbolAddress((void**)&ptD,  g_tmpD);
    cudaGetSymbolAddress((void**)&ptS,  g_tmpS);
    cudaGetSymbolAddress((void**)&pxw,  g_xw);
    cudaGetSymbolAddress((void**)&pZ2,  g_Z2);
    cudaGetSymbolAddress((void**)&pdeg, g_deg);
    cudaGetSymbolAddress((void**)&pdis, g_dis);
    cudaGetSymbolAddress((void**)&pdeg2,g_deg2);
    cudaGetSymbolAddress((void**)&pdis2,g_dis2);
    cudaGetSymbolAddress((void**)&pen,  g_enorm);
    cudaGetSymbolAddress((void**)&pnnz, g_nnz);
    cudaGetSymbolAddress((void**)&psr,  g_sp_r);
    cudaGetSymbolAddress((void**)&psc,  g_sp_c);
    cudaGetSymbolAddress((void**)&psv,  g_sp_v);
    cudaGetSymbolAddress((void**)&pX3h, g_X3h);
    cudaGetSymbolAddress((void**)&pX3m, g_X3m);
    cudaGetSymbolAddress((void**)&pX3l, g_X3l);
    cudaGetSymbolAddress((void**)&pUh,  g_Uh);
    cudaGetSymbolAddress((void**)&pUm,  g_Um);
    cudaGetSymbolAddress((void**)&pUl,  g_Ul);
    cudaGetSymbolAddress((void**)&ptDh, g_tDh);
    cudaGetSymbolAddress((void**)&ptDm, g_tDm);
    cudaGetSymbolAddress((void**)&ptSh, g_tSh);
    cudaGetSymbolAddress((void**)&ptSm, g_tSm);
    cudaGetSymbolAddress((void**)&pWfh, g_Wfh);
    cudaGetSymbolAddress((void**)&pWfm, g_Wfm);
    cudaGetSymbolAddress((void**)&pWfl, g_Wfl);
    cudaGetSymbolAddress((void**)&pW0h, g_W0h);
    cudaGetSymbolAddress((void**)&pW0m, g_W0m);
    cudaGetSymbolAddress((void**)&pW1h, g_W1h);
    cudaGetSymbolAddress((void**)&pW1m, g_W1m);

    static int attr_set = 0;
    if (!attr_set) {
        cudaFuncSetAttribute(syrk_mma_kernel,
                             cudaFuncAttributeMaxDynamicSharedMemorySize, SYRK_SMEM_DYN);
        cudaFuncSetAttribute(gemm_mma_kernel<3, true>,
                             cudaFuncAttributeMaxDynamicSharedMemorySize, 170496);
        cudaFuncSetAttribute(gemm_mma_kernel<2, false>,
                             cudaFuncAttributeMaxDynamicSharedMemorySize, 113664);
        attr_set = 1;
    }

    const int ND = n * DDIM;
    const int TPB = 256;
    dim3 blk(TPB);

    // 1) gather + split X3; split weights
    gather_split3_kernel<<<(ND + TPB - 1) / TPB, blk>>>(emb1, demand, supply,
                                                        pX3h, pX3m, pX3l, n, T);
    split3_kernel<<<(K3 * DDIM + TPB - 1) / TPB, blk>>>(fuse_W, pWfh, pWfm, pWfl, K3 * DDIM);
    split2_kernel<<<(LLAYERS * DDIM * DDIM + TPB - 1) / TPB, blk>>>(gnn0_W, pW0h, pW0m,
                                                                    LLAYERS * DDIM * DDIM);
    split2_kernel<<<(LLAYERS * DDIM * DDIM + TPB - 1) / TPB, blk>>>(gnn1_W, pW1h, pW1m,
                                                                    LLAYERS * DDIM * DDIM);

    // 2) update_emb = X3 @ fuse_W + fuse_b
    {
        dim3 grid(DDIM / 128, (n + 127) / 128);
        gemm_mma_kernel<3, true><<<grid, blk, 170496>>>(pX3h, pX3m, pX3l,
                                                        pWfh, pWfm, pWfl,
                                                        pU, fuse_b, n, DDIM, K3);
    }

    // 3) split U; logits syrk
    split3_kernel<<<(ND + TPB - 1) / TPB, blk>>>(pU, pUh, pUm, pUl, ND);
    {
        int nblk = (n + 127) / 128;
        int ntiles = nblk * (nblk + 1) / 2;
        syrk_mma_kernel<<<ntiles, 256, SYRK_SMEM_DYN>>>(pUh, pUm, pUl, out_pred, n);
    }

    // 4) softmax prep + run
    fill_kernel<<<(n + TPB - 1) / TPB, blk>>>(pdeg, 1.0f, n);
    zero_int_kernel<<<1, 1>>>(pnnz);
    softmax_relu_kernel<<<n, blk>>>(out_pred, n, pnnz, psr, psc, psv, pdeg);
    rsqrt_kernel<<<(n + TPB - 1) / TPB, blk>>>(pdis, pdeg, n);

    // 5) temps start at update_emb
    cudaMemcpyAsync(ptD, pU, (size_t)ND * sizeof(float), cudaMemcpyDeviceToDevice);
    cudaMemcpyAsync(ptS, pU, (size_t)ND * sizeof(float), cudaMemcpyDeviceToDevice);

    // 6) dense GCN layers
    for (int l = 0; l < LLAYERS; l++) {
        const __nv_bfloat16* Ah = (l == 0) ? pUh : ptDh;
        const __nv_bfloat16* Am = (l == 0) ? pUm : ptDm;
        dim3 grid(DDIM / 128, (n + 127) / 128);
        gemm_mma_kernel<2, false><<<grid, blk, 113664>>>(Ah, Am, nullptr,
                                                         pW0h + (size_t)l * DDIM * DDIM,
                                                         pW0m + (size_t)l * DDIM * DDIM,
                                                         nullptr, pxw, nullptr,
                                                         n, DDIM, DDIM);
        fill_kernel<<<(ND + TPB - 1) / TPB, blk>>>(pZ2, 0.0f, ND);
        {
            int blocks = (MAXNNZ * 32 + TPB - 1) / TPB;
            dense_scatter_kernel<<<blocks, blk>>>(pxw, psr, psc, psv, pdis, pZ2, pnnz);
        }
        dense_combine_kernel<<<(ND + TPB - 1) / TPB, blk>>>(ptD, pZ2, pxw, pdis,
                                                            gnn0_b + (size_t)l * DDIM,
                                                            n, DDIM, ptDh, ptDm);
    }

    // 7) sparse graph normalization
    fill_kernel<<<(n + TPB - 1) / TPB, blk>>>(pdeg2, 1.0f, n);
    edge_deg_kernel<<<(E + TPB - 1) / TPB, blk>>>(eidx + E, eattr, pdeg2, E);
    rsqrt_kernel<<<(n + TPB - 1) / TPB, blk>>>(pdis2, pdeg2, n);
    enorm_kernel<<<(E + TPB - 1) / TPB, blk>>>(eidx, eidx + E, eattr, pdis2, pen, E);

    // 8) sparse GCN layers
    for (int l = 0; l < LLAYERS; l++) {
        const __nv_bfloat16* Ah = (l == 0) ? pUh : ptSh;
        const __nv_bfloat16* Am = (l == 0) ? pUm : ptSm;
        dim3 grid(DDIM / 128, (n + 127) / 128);
        gemm_mma_kernel<2, false><<<grid, blk, 113664>>>(Ah, Am, nullptr,
                                                         pW1h + (size_t)l * DDIM * DDIM,
                                                         pW1m + (size_t)l * DDIM * DDIM,
                                                         nullptr, pxw, nullptr,
                                                         n, DDIM, DDIM);
        fill_kernel<<<(ND + TPB - 1) / TPB, blk>>>(pZ2, 0.0f, ND);
        {
            int blocks = (E * 32 + TPB - 1) / TPB;
            scatter_kernel<<<blocks, blk>>>(pxw, eidx, eidx + E, pen, pZ2, E, DDIM);
        }
        sparse_combine_kernel<<<(ND + TPB - 1) / TPB, blk>>>(ptS, pZ2, pxw, pdis2,
                                                             gnn1_b + (size_t)l * DDIM,
                                                             n, DDIM, ptSh, ptSm);
    }

    // 9) outputs
    cudaMemcpyAsync(out_emb1, emb1, (size_t)ND * sizeof(float), cudaMemcpyDeviceToDevice);
    add_kernel<<<(ND + TPB - 1) / TPB, blk>>>(out_skill, ptD, ptS, ND);
}

// round 8
// speedup vs baseline: 6.0176x; 1.0766x over previous
#include <cuda_runtime.h>
#include <cuda_bf16.h>
#include <math.h>
#include <stdint.h>

#define NNODE 8000
#define DDIM  256
#define K3    768
#define EMAX  256000
#define LLAYERS 2
#define PRESERVE_F 0.1f
#define MAXNNZ (4 * NNODE)   // softmax rows sum to 1 => <=4 entries/row exceed 0.2

// ---------------- scratch (static device memory) ---------------------------------
__device__ float g_U [NNODE * DDIM];
__device__ float g_tmpD[NNODE * DDIM];
__device__ float g_tmpS[NNODE * DDIM];
__device__ float g_xw [NNODE * DDIM];     // dense-branch xw
__device__ float g_xwS[NNODE * DDIM];     // sparse-branch xw
__device__ float g_Z2 [NNODE * DDIM];     // dense-branch agg
__device__ float g_Z2b[NNODE * DDIM];     // sparse-branch agg
__device__ float g_deg [NNODE];
__device__ float g_dis [NNODE];
__device__ float g_deg2[NNODE];
__device__ float g_dis2[NNODE];
__device__ float g_enorm[EMAX];
__device__ int   g_nnz;
__device__ int   g_sp_r[MAXNNZ];
__device__ int   g_sp_c[MAXNNZ];
__device__ float g_sp_v[MAXNNZ];
// bf16 splits
__device__ __nv_bfloat16 g_X3h[NNODE * K3];
__device__ __nv_bfloat16 g_X3m[NNODE * K3];
__device__ __nv_bfloat16 g_X3l[NNODE * K3];
__device__ __nv_bfloat16 g_Uh[NNODE * DDIM];
__device__ __nv_bfloat16 g_Um[NNODE * DDIM];
__device__ __nv_bfloat16 g_Ul[NNODE * DDIM];
__device__ __nv_bfloat16 g_tDh[NNODE * DDIM];
__device__ __nv_bfloat16 g_tDm[NNODE * DDIM];
__device__ __nv_bfloat16 g_tSh[NNODE * DDIM];
__device__ __nv_bfloat16 g_tSm[NNODE * DDIM];
__device__ __nv_bfloat16 g_Wfh[K3 * DDIM];
__device__ __nv_bfloat16 g_Wfm[K3 * DDIM];
__device__ __nv_bfloat16 g_Wfl[K3 * DDIM];
__device__ __nv_bfloat16 g_W0h[LLAYERS * DDIM * DDIM];
__device__ __nv_bfloat16 g_W0m[LLAYERS * DDIM * DDIM];
__device__ __nv_bfloat16 g_W1h[LLAYERS * DDIM * DDIM];
__device__ __nv_bfloat16 g_W1m[LLAYERS * DDIM * DDIM];

__device__ __forceinline__ uint32_t smem_u32(const void* p) {
    uint32_t a;
    asm("{ .reg .u64 t; cvta.to.shared.u64 t, %1; cvt.u32.u64 %0, t; }" : "=r"(a) : "l"(p));
    return a;
}

__device__ __forceinline__ void red_add_v4(float* addr, float4 v) {
    asm volatile("red.global.add.v4.f32 [%0], {%1,%2,%3,%4};"
                 :: "l"(addr), "f"(v.x), "f"(v.y), "f"(v.z), "f"(v.w) : "memory");
}

#define LDSM_X4(r0, r1, r2, r3, addr) \
    asm volatile("ldmatrix.sync.aligned.m8n8.x4.shared.b16 {%0,%1,%2,%3}, [%4];" \
                 : "=r"(r0), "=r"(r1), "=r"(r2), "=r"(r3) : "r"(addr))
#define LDSM_X2(r0, r1, addr) \
    asm volatile("ldmatrix.sync.aligned.m8n8.x2.shared.b16 {%0,%1}, [%2];" \
                 : "=r"(r0), "=r"(r1) : "r"(addr))
#define LDSM_X2_T(r0, r1, addr) \
    asm volatile("ldmatrix.sync.aligned.m8n8.x2.trans.shared.b16 {%0,%1}, [%2];" \
                 : "=r"(r0), "=r"(r1) : "r"(addr))
#define MMA_BF16(c, a0, a1, a2, a3, b0, b1) \
    asm volatile("mma.sync.aligned.m16n8k16.row.col.f32.bf16.bf16.f32 " \
                 "{%0,%1,%2,%3}, {%4,%5,%6,%7}, {%8,%9}, {%0,%1,%2,%3};" \
                 : "+f"((c)[0]), "+f"((c)[1]), "+f"((c)[2]), "+f"((c)[3]) \
                 : "r"(a0), "r"(a1), "r"(a2), "r"(a3), "r"(b0), "r"(b1))
#define CP_ASYNC16(saddr, gptr, sz) \
    asm volatile("cp.async.cg.shared.global [%0], [%1], 16, %2;" \
                 :: "r"(saddr), "l"(gptr), "r"(sz))
#define CP_COMMIT() asm volatile("cp.async.commit_group;")
#define CP_WAIT2()  asm volatile("cp.async.wait_group 2;")
#define CP_WAIT1()  asm volatile("cp.async.wait_group 1;")
#define CP_WAIT0()  asm volatile("cp.async.wait_group 0;")

#define LDT 40   // A-tile smem stride (bf16), 80 B
#define LDB 136  // B-tile smem stride (bf16), 272 B

// =================== syrk: C = U @ U^T (3-way bf16 split, 3-stage pipeline) ======
#define SYRK_TILE_ELEMS (128 * LDT)
#define SYRK_STAGE_ELEMS (6 * SYRK_TILE_ELEMS)
#define SYRK_SMEM_DYN (3 * SYRK_STAGE_ELEMS * 2)

__global__ __launch_bounds__(256)
void syrk_mma_kernel(const __nv_bfloat16* __restrict__ Uh,
                     const __nv_bfloat16* __restrict__ Um,
                     const __nv_bfloat16* __restrict__ Ul,
                     float* __restrict__ C, int n)
{
    extern __shared__ char smem[];
    __nv_bfloat16* tiles = (__nv_bfloat16*)smem;
    float* epi = (float*)smem;

    const int tid  = threadIdx.x;
    const int wid  = tid >> 5;
    const int lane = tid & 31;
    const int wm   = wid & 1;
    const int wn   = wid >> 1;
    const int group = lane >> 2;
    const int tig   = lane & 3;

    int t = blockIdx.x;
    int bi = (int)((sqrtf(8.0f * (float)t + 1.0f) - 1.0f) * 0.5f);
    while ((bi + 1) * (bi + 2) / 2 <= t) bi++;
    while (bi * (bi + 1) / 2 > t) bi--;
    int bj = t - bi * (bi + 1) / 2;
    const int m0 = bi * 128;
    const int n0 = bj * 128;

    float acc[4][4][4];
#pragma unroll
    for (int a = 0; a < 4; a++)
#pragma unroll
        for (int b = 0; b < 4; b++)
#pragma unroll
            for (int c = 0; c < 4; c++) acc[a][b][c] = 0.f;

    const __nv_bfloat16* srcs[6] = { Uh, Um, Ul, Uh, Um, Ul };
    const uint32_t sT = smem_u32(tiles);

    const int a_row = (lane & 15);
    const int a_col = (lane >> 4) * 8;
    const int b_row = (lane & 7);
    const int b_col = ((lane >> 3) & 1) * 8;
    const uint32_t a_base = (uint32_t)((wm * 64 + a_row) * LDT + a_col) * 2;
    const uint32_t b_base = (uint32_t)((wn * 32 + b_row) * LDT + b_col) * 2;

    auto load_chunk = [&](int k0, int stage) {
        uint32_t dst0 = sT + (uint32_t)(stage * SYRK_STAGE_ELEMS) * 2;
#pragma unroll
        for (int s = 0; s < 6; s++) {
            const __nv_bfloat16* src = srcs[s];
            const int rowbase = (s < 3) ? m0 : n0;
            uint32_t dts = dst0 + (uint32_t)(s * SYRK_TILE_ELEMS) * 2;
#pragma unroll
            for (int it = 0; it < 2; it++) {
                int lin = it * 256 + tid;
                int r   = lin >> 2;
                int c8  = (lin & 3) * 8;
                int g   = rowbase + r;
                uint32_t sz = (g < n) ? 16u : 0u;
                int g2 = (g < n) ? g : 0;
                const __nv_bfloat16* gp = src + (size_t)g2 * DDIM + k0 + c8;
                CP_ASYNC16(dts + (uint32_t)(r * LDT + c8) * 2, gp, sz);
            }
        }
    };

    load_chunk(0, 0);
    CP_COMMIT();
    load_chunk(32, 1);
    CP_COMMIT();

#pragma unroll 1
    for (int kc = 0; kc < 8; kc++) {
        const int cur = kc % 3;
        if (kc + 2 < 8) {
            load_chunk((kc + 2) * 32, (kc + 2) % 3);
            CP_COMMIT();
            CP_WAIT2();
        } else if (kc + 1 < 8) {
            CP_WAIT1();
        } else {
            CP_WAIT0();
        }
        __syncthreads();

        const uint32_t stg = sT + (uint32_t)(cur * SYRK_STAGE_ELEMS) * 2;
        const uint32_t sA0 = stg;
        const uint32_t sA1 = stg + SYRK_TILE_ELEMS * 2u;
        const uint32_t sA2 = stg + SYRK_TILE_ELEMS * 4u;
        const uint32_t sB0 = stg + SYRK_TILE_ELEMS * 6u;
        const uint32_t sB1 = stg + SYRK_TILE_ELEMS * 8u;
        const uint32_t sB2 = stg + SYRK_TILE_ELEMS * 10u;

#pragma unroll
        for (int ks = 0; ks < 2; ks++) {
            const uint32_t koff = (uint32_t)(ks * 16) * 2;
            uint32_t ah[4][4], bh[4][2];
#pragma unroll
            for (int mt = 0; mt < 4; mt++)
                LDSM_X4(ah[mt][0], ah[mt][1], ah[mt][2], ah[mt][3],
                        sA0 + a_base + koff + (uint32_t)(mt * 16 * LDT) * 2);
#pragma unroll
            for (int nt = 0; nt < 4; nt++)
                LDSM_X2(bh[nt][0], bh[nt][1],
                        sB0 + b_base + koff + (uint32_t)(nt * 8 * LDT) * 2);
#pragma unroll
            for (int mt = 0; mt < 4; mt++)
#pragma unroll
                for (int nt = 0; nt < 4; nt++)
                    MMA_BF16(acc[mt][nt], ah[mt][0], ah[mt][1], ah[mt][2], ah[mt][3],
                             bh[nt][0], bh[nt][1]);
            {
                uint32_t bm[4][2], am[4][4];
#pragma unroll
                for (int nt = 0; nt < 4; nt++)
                    LDSM_X2(bm[nt][0], bm[nt][1],
                            sB1 + b_base + koff + (uint32_t)(nt * 8 * LDT) * 2);
#pragma unroll
                for (int mt = 0; mt < 4; mt++)
#pragma unroll
                    for (int nt = 0; nt < 4; nt++)
                        MMA_BF16(acc[mt][nt], ah[mt][0], ah[mt][1], ah[mt][2], ah[mt][3],
                                 bm[nt][0], bm[nt][1]);
#pragma unroll
                for (int mt = 0; mt < 4; mt++)
                    LDSM_X4(am[mt][0], am[mt][1], am[mt][2], am[mt][3],
                            sA1 + a_base + koff + (uint32_t)(mt * 16 * LDT) * 2);
#pragma unroll
                for (int mt = 0; mt < 4; mt++)
#pragma unroll
                    for (int nt = 0; nt < 4; nt++) {
                        MMA_BF16(acc[mt][nt], am[mt][0], am[mt][1], am[mt][2], am[mt][3],
                                 bh[nt][0], bh[nt][1]);
                        MMA_BF16(acc[mt][nt], am[mt][0], am[mt][1], am[mt][2], am[mt][3],
                                 bm[nt][0], bm[nt][1]);
                    }
            }
            {
                uint32_t bl[4][2];
#pragma unroll
                for (int nt = 0; nt < 4; nt++)
                    LDSM_X2(bl[nt][0], bl[nt][1],
                            sB2 + b_base + koff + (uint32_t)(nt * 8 * LDT) * 2);
#pragma unroll
                for (int mt = 0; mt < 4; mt++)
#pragma unroll
                    for (int nt = 0; nt < 4; nt++)
                        MMA_BF16(acc[mt][nt], ah[mt][0], ah[mt][1], ah[mt][2], ah[mt][3],
                                 bl[nt][0], bl[nt][1]);
            }
            {
                uint32_t al[4][4];
#pragma unroll
                for (int mt = 0; mt < 4; mt++)
                    LDSM_X4(al[mt][0], al[mt][1], al[mt][2], al[mt][3],
                            sA2 + a_base + koff + (uint32_t)(mt * 16 * LDT) * 2);
#pragma unroll
                for (int mt = 0; mt < 4; mt++)
#pragma unroll
                    for (int nt = 0; nt < 4; nt++)
                        MMA_BF16(acc[mt][nt], al[mt][0], al[mt][1], al[mt][2], al[mt][3],
                                 bh[nt][0], bh[nt][1]);
            }
        }
        __syncthreads();
    }

    // direct write
#pragma unroll
    for (int mt = 0; mt < 4; mt++) {
#pragma unroll
        for (int nt = 0; nt < 4; nt++) {
            int lm = wm * 64 + mt * 16 + group;
            int ln = wn * 32 + nt * 8 + tig * 2;
            int gm = m0 + lm, gn = n0 + ln;
            if (gn + 1 < n) {
                if (gm < n)
                    *reinterpret_cast<float2*>(C + (size_t)gm * n + gn) =
                        make_float2(acc[mt][nt][0], acc[mt][nt][1]);
                if (gm + 8 < n)
                    *reinterpret_cast<float2*>(C + (size_t)(gm + 8) * n + gn) =
                        make_float2(acc[mt][nt][2], acc[mt][nt][3]);
            }
        }
    }

    // mirrored write via smem transpose
    if (bi != bj) {
        __syncthreads();
#pragma unroll
        for (int mt = 0; mt < 4; mt++) {
#pragma unroll
            for (int nt = 0; nt < 4; nt++) {
                int lm = wm * 64 + mt * 16 + group;
                int ln = wn * 32 + nt * 8 + tig * 2;
                epi[lm * 129 + ln]           = acc[mt][nt][0];
                epi[lm * 129 + ln + 1]       = acc[mt][nt][1];
                epi[(lm + 8) * 129 + ln]     = acc[mt][nt][2];
                epi[(lm + 8) * 129 + ln + 1] = acc[mt][nt][3];
            }
        }
        __syncthreads();
        const int c_row = tid >> 1;
        const int half  = tid & 1;
        const int grow  = n0 + c_row;
        if (grow < n) {
            float* outrow = C + (size_t)grow * n;
#pragma unroll
            for (int i = 0; i < 16; i++) {
                int ml = half * 64 + i * 4;
                if (m0 + ml + 3 < n) {
                    float4 v = make_float4(epi[(ml + 0) * 129 + c_row],
                                           epi[(ml + 1) * 129 + c_row],
                                           epi[(ml + 2) * 129 + c_row],
                                           epi[(ml + 3) * 129 + c_row]);
                    *reinterpret_cast<float4*>(outrow + m0 + ml) = v;
                } else {
                    for (int q = 0; q < 4; q++)
                        if (m0 + ml + q < n)
                            outrow[m0 + ml + q] = epi[(ml + q) * 129 + c_row];
                }
            }
        }
    }
}

// =================== general MMA GEMM: C = A @ B (+bias), 3-stage ================
#define GEMM_AT_ELEMS (128 * LDT)
#define GEMM_BT_ELEMS (32 * LDB)

template<int SP, bool BIAS>
__global__ __launch_bounds__(256)
void gemm_mma_kernel(const __nv_bfloat16* __restrict__ Ah_,
                     const __nv_bfloat16* __restrict__ Am_,
                     const __nv_bfloat16* __restrict__ Al_,
                     const __nv_bfloat16* __restrict__ Bh_,
                     const __nv_bfloat16* __restrict__ Bm_,
                     const __nv_bfloat16* __restrict__ Bl_,
                     float* __restrict__ C, const float* __restrict__ bias,
                     int M, int N, int K)
{
    extern __shared__ char smem[];
    __nv_bfloat16* tiles = (__nv_bfloat16*)smem;
    const int STAGE_ELEMS = SP * (GEMM_AT_ELEMS + GEMM_BT_ELEMS);

    const int tid  = threadIdx.x;
    const int wid  = tid >> 5;
    const int lane = tid & 31;
    const int wm   = wid & 1;
    const int wn   = wid >> 1;
    const int group = lane >> 2;
    const int tig   = lane & 3;

    const int n0 = blockIdx.x * 128;
    const int m0 = blockIdx.y * 128;

    float acc[4][4][4];
#pragma unroll
    for (int a = 0; a < 4; a++)
#pragma unroll
        for (int b = 0; b < 4; b++)
#pragma unroll
            for (int c = 0; c < 4; c++) acc[a][b][c] = 0.f;

    const __nv_bfloat16* Asrc[3] = { Ah_, Am_, Al_ };
    const __nv_bfloat16* Bsrc[3] = { Bh_, Bm_, Bl_ };
    const uint32_t sT = smem_u32(tiles);

    const int a_row = (lane & 15);
    const int a_col = (lane >> 4) * 8;
    const uint32_t a_base = (uint32_t)((wm * 64 + a_row) * LDT + a_col) * 2;
    const uint32_t bt_base = (uint32_t)((lane & 15) * LDB + wn * 32) * 2;

    auto load_chunk = [&](int k0, int stage) {
        uint32_t dst0 = sT + (uint32_t)(stage * STAGE_ELEMS) * 2;
#pragma unroll
        for (int s = 0; s < SP; s++) {
            uint32_t dts = dst0 + (uint32_t)(s * GEMM_AT_ELEMS) * 2;
#pragma unroll
            for (int it = 0; it < 2; it++) {
                int lin = it * 256 + tid;
                int r   = lin >> 2;
                int c8  = (lin & 3) * 8;
                int g   = m0 + r;
                uint32_t sz = (g < M) ? 16u : 0u;
                int g2 = (g < M) ? g : 0;
                const __nv_bfloat16* gp = Asrc[s] + (size_t)g2 * K + k0 + c8;
                CP_ASYNC16(dts + (uint32_t)(r * LDT + c8) * 2, gp, sz);
            }
        }
        uint32_t dstB = dst0 + (uint32_t)(SP * GEMM_AT_ELEMS) * 2;
#pragma unroll
        for (int s = 0; s < SP; s++) {
            uint32_t dts = dstB + (uint32_t)(s * GEMM_BT_ELEMS) * 2;
#pragma unroll
            for (int it = 0; it < 2; it++) {
                int lin = it * 256 + tid;
                int r   = lin >> 4;
                int c8  = (lin & 15) * 8;
                const __nv_bfloat16* gp = Bsrc[s] + (size_t)(k0 + r) * N + n0 + c8;
                CP_ASYNC16(dts + (uint32_t)(r * LDB + c8) * 2, gp, 16u);
            }
        }
    };

    const int NC = K / 32;
    load_chunk(0, 0);
    CP_COMMIT();
    if (NC > 1) { load_chunk(32, 1); CP_COMMIT(); }

#pragma unroll 1
    for (int kc = 0; kc < NC; kc++) {
        const int cur = kc % 3;
        if (kc + 2 < NC) {
            load_chunk((kc + 2) * 32, (kc + 2) % 3);
            CP_COMMIT();
            CP_WAIT2();
        } else if (kc + 1 < NC) {
            CP_WAIT1();
        } else {
            CP_WAIT0();
        }
        __syncthreads();

        const uint32_t stg = sT + (uint32_t)(cur * STAGE_ELEMS) * 2;
        const uint32_t sA0 = stg;
        const uint32_t sA1 = stg + GEMM_AT_ELEMS * 2u;
        const uint32_t sA2 = stg + GEMM_AT_ELEMS * 4u;
        const uint32_t sBb = stg + (uint32_t)(SP * GEMM_AT_ELEMS) * 2u;
        const uint32_t sB0 = sBb;
        const uint32_t sB1 = sBb + GEMM_BT_ELEMS * 2u;
        const uint32_t sB2 = sBb + GEMM_BT_ELEMS * 4u;

#pragma unroll
        for (int ks = 0; ks < 2; ks++) {
            const uint32_t akoff = (uint32_t)(ks * 16) * 2;
            const uint32_t bkoff = (uint32_t)(ks * 16 * LDB) * 2;
            uint32_t ah[4][4], bh[4][2];
#pragma unroll
            for (int mt = 0; mt < 4; mt++)
                LDSM_X4(ah[mt][0], ah[mt][1], ah[mt][2], ah[mt][3],
                        sA0 + a_base + akoff + (uint32_t)(mt * 16 * LDT) * 2);
#pragma unroll
            for (int nt = 0; nt < 4; nt++)
                LDSM_X2_T(bh[nt][0], bh[nt][1],
                          sB0 + bt_base + bkoff + (uint32_t)(nt * 8) * 2);
#pragma unroll
            for (int mt = 0; mt < 4; mt++)
#pragma unroll
                for (int nt = 0; nt < 4; nt++)
                    MMA_BF16(acc[mt][nt], ah[mt][0], ah[mt][1], ah[mt][2], ah[mt][3],
                             bh[nt][0], bh[nt][1]);
            {
                uint32_t bm[4][2], am[4][4];
#pragma unroll
                for (int nt = 0; nt < 4; nt++)
                    LDSM_X2_T(bm[nt][0], bm[nt][1],
                              sB1 + bt_base + bkoff + (uint32_t)(nt * 8) * 2);
#pragma unroll
                for (int mt = 0; mt < 4; mt++)
#pragma unroll
                    for (int nt = 0; nt < 4; nt++)
                        MMA_BF16(acc[mt][nt], ah[mt][0], ah[mt][1], ah[mt][2], ah[mt][3],
                                 bm[nt][0], bm[nt][1]);
#pragma unroll
                for (int mt = 0; mt < 4; mt++)
                    LDSM_X4(am[mt][0], am[mt][1], am[mt][2], am[mt][3],
                            sA1 + a_base + akoff + (uint32_t)(mt * 16 * LDT) * 2);
#pragma unroll
                for (int mt = 0; mt < 4; mt++)
#pragma unroll
                    for (int nt = 0; nt < 4; nt++) {
                        MMA_BF16(acc[mt][nt], am[mt][0], am[mt][1], am[mt][2], am[mt][3],
                                 bh[nt][0], bh[nt][1]);
                        if (SP == 3)
                            MMA_BF16(acc[mt][nt], am[mt][0], am[mt][1], am[mt][2], am[mt][3],
                                     bm[nt][0], bm[nt][1]);
                    }
            }
            if (SP == 3) {
                {
                    uint32_t bl[4][2];
#pragma unroll
                    for (int nt = 0; nt < 4; nt++)
                        LDSM_X2_T(bl[nt][0], bl[nt][1],
                                  sB2 + bt_base + bkoff + (uint32_t)(nt * 8) * 2);
#pragma unroll
                    for (int mt = 0; mt < 4; mt++)
#pragma unroll
                        for (int nt = 0; nt < 4; nt++)
                            MMA_BF16(acc[mt][nt], ah[mt][0], ah[mt][1], ah[mt][2], ah[mt][3],
                                     bl[nt][0], bl[nt][1]);
                }
                {
                    uint32_t al[4][4];
#pragma unroll
                    for (int mt = 0; mt < 4; mt++)
                        LDSM_X4(al[mt][0], al[mt][1], al[mt][2], al[mt][3],
                                sA2 + a_base + akoff + (uint32_t)(mt * 16 * LDT) * 2);
#pragma unroll
                    for (int mt = 0; mt < 4; mt++)
#pragma unroll
                        for (int nt = 0; nt < 4; nt++)
                            MMA_BF16(acc[mt][nt], al[mt][0], al[mt][1], al[mt][2], al[mt][3],
                                     bh[nt][0], bh[nt][1]);
                }
            }
        }
        __syncthreads();
    }

    // epilogue
#pragma unroll
    for (int mt = 0; mt < 4; mt++) {
#pragma unroll
        for (int nt = 0; nt < 4; nt++) {
            int lm = wm * 64 + mt * 16 + group;
            int ln = wn * 32 + nt * 8 + tig * 2;
            int gm = m0 + lm, gn = n0 + ln;
            float b0 = 0.f, b1 = 0.f;
            if (BIAS) { b0 = bias[gn]; b1 = bias[gn + 1]; }
            if (gm < M)
                *reinterpret_cast<float2*>(C + (size_t)gm * N + gn) =
                    make_float2(acc[mt][nt][0] + b0, acc[mt][nt][1] + b1);
            if (gm + 8 < M)
                *reinterpret_cast<float2*>(C + (size_t)(gm + 8) * N + gn) =
                    make_float2(acc[mt][nt][2] + b0, acc[mt][nt][3] + b1);
        }
    }
}

// ---------------- split kernels ---------------------------------------------------
__global__ void split3_kernel(const float* __restrict__ U,
                              __nv_bfloat16* __restrict__ Uh,
                              __nv_bfloat16* __restrict__ Um,
                              __nv_bfloat16* __restrict__ Ul, int total)
{
    int i = blockIdx.x * blockDim.x + threadIdx.x;
    if (i >= total) return;
    float x = U[i];
    __nv_bfloat16 h = __float2bfloat16(x);
    float r = x - __bfloat162float(h);
    __nv_bfloat16 m = __float2bfloat16(r);
    float r2 = r - __bfloat162float(m);
    Uh[i] = h; Um[i] = m; Ul[i] = __float2bfloat16(r2);
}

__global__ void split2_kernel(const float* __restrict__ U,
                              __nv_bfloat16* __restrict__ Uh,
                              __nv_bfloat16* __restrict__ Um, int total)
{
    int i = blockIdx.x * blockDim.x + threadIdx.x;
    if (i >= total) return;
    float x = U[i];
    __nv_bfloat16 h = __float2bfloat16(x);
    float r = x - __bfloat162float(h);
    Uh[i] = h; Um[i] = __float2bfloat16(r);
}

__global__ void gather_split3_kernel(const float* __restrict__ emb1,
                                     const float* __restrict__ demand,
                                     const float* __restrict__ supply,
                                     __nv_bfloat16* __restrict__ Xh,
                                     __nv_bfloat16* __restrict__ Xm,
                                     __nv_bfloat16* __restrict__ Xl, int n, int T)
{
    int i = blockIdx.x * blockDim.x + threadIdx.x;
    int total = n * DDIM;
    if (i >= total) return;
    int node = i / DDIM, d = i % DDIM;
    float v[3];
    v[0] = emb1[(size_t)node * DDIM + d];
    v[1] = demand[((size_t)node * T + (T - 1)) * DDIM + d];
    v[2] = supply[((size_t)node * T + (T - 1)) * DDIM + d];
#pragma unroll
    for (int s = 0; s < 3; s++) {
        size_t idx = (size_t)node * K3 + s * DDIM + d;
        float x = v[s];
        __nv_bfloat16 h = __float2bfloat16(x);
        float r = x - __bfloat162float(h);
        __nv_bfloat16 m = __float2bfloat16(r);
        float r2 = r - __bfloat162float(m);
        Xh[idx] = h; Xm[idx] = m; Xl[idx] = __float2bfloat16(r2);
    }
}

// ---------------- small kernels ---------------------------------------------------
__global__ void softmax_relu_kernel(float* __restrict__ Z, int n,
                                    int* __restrict__ nnz,
                                    int* __restrict__ sr, int* __restrict__ sc,
                                    float* __restrict__ sv,
                                    float* __restrict__ deg)
{
    __shared__ float row[NNODE];
    __shared__ float red[256];
    int r = blockIdx.x;
    int t = threadIdx.x;
    float* zr = Z + (size_t)r * n;

    float mx = -3.4e38f;
    for (int c = t; c < n; c += 256) {
        float v = zr[c];
        row[c] = v;
        mx = fmaxf(mx, v);
    }
    red[t] = mx; __syncthreads();
    for (int s = 128; s > 0; s >>= 1) {
        if (t < s) red[t] = fmaxf(red[t], red[t + s]);
        __syncthreads();
    }
    mx = red[0];
    __syncthreads();

    float sm = 0.f;
    for (int c = t; c < n; c += 256) {
        float e = __expf(row[c] - mx);
        row[c] = e;
        sm += e;
    }
    red[t] = sm; __syncthreads();
    for (int s = 128; s > 0; s >>= 1) {
        if (t < s) red[t] += red[t + s];
        __syncthreads();
    }
    float inv = 1.0f / red[0];
    for (int c = t; c < n; c += 256) {
        float p = row[c] * inv - 0.2f;
        p = p > 0.f ? p : 0.f;
        zr[c] = p;
        if (p > 0.f) {
            int idx = atomicAdd(nnz, 1);
            if (idx < MAXNNZ) {
                sr[idx] = r; sc[idx] = c; sv[idx] = p;
            }
            atomicAdd(&deg[c], p);
        }
    }
}

__global__ void fill_kernel(float* p, float v, int n)
{
    int i = blockIdx.x * blockDim.x + threadIdx.x;
    if (i < n) p[i] = v;
}

__global__ void zero_int_kernel(int* p) { *p = 0; }

__global__ void rsqrt_kernel(float* __restrict__ dst, const float* __restrict__ src, int n)
{
    int i = blockIdx.x * blockDim.x + threadIdx.x;
    if (i < n) dst[i] = rsqrtf(src[i]);
}

__global__ void dense_scatter_kernel(const float* __restrict__ xw,
                                     const int* __restrict__ sr,
                                     const int* __restrict__ sc,
                                     const float* __restrict__ sv,
                                     const float* __restrict__ dis,
                                     float* __restrict__ agg,
                                     const int* __restrict__ nnz)
{
    int warp = (blockIdx.x * blockDim.x + threadIdx.x) >> 5;
    int lane = threadIdx.x & 31;
    int m = *nnz; if (m > MAXNNZ) m = MAXNNZ;
    if (warp >= m) return;
    int r = sr[warp], c = sc[warp];
    float w = sv[warp] * dis[r];
    const float4* xr = reinterpret_cast<const float4*>(xw + (size_t)r * DDIM);
    float* ar = agg + (size_t)c * DDIM;
#pragma unroll
    for (int h = 0; h < 2; h++) {
        int f4 = h * 32 + lane;
        float4 x = xr[f4];
        red_add_v4(ar + f4 * 4, make_float4(w * x.x, w * x.y, w * x.z, w * x.w));
    }
}

__global__ void dense_combine_kernel(float* __restrict__ temp, const float* __restrict__ Z2,
                                     const float* __restrict__ xw, const float* __restrict__ dis,
                                     const float* __restrict__ b, int n, int d,
                                     __nv_bfloat16* __restrict__ th,
                                     __nv_bfloat16* __restrict__ tm)
{
    int i = blockIdx.x * blockDim.x + threadIdx.x;
    if (i >= n * d) return;
    int c = i / d, dd = i - c * d;
    float s = dis[c];
    float out = s * Z2[i] + s * s * xw[i] + b[dd];
    float v = (1.0f - PRESERVE_F) * out + PRESERVE_F * temp[i];
    temp[i] = v;
    __nv_bfloat16 h = __float2bfloat16(v);
    th[i] = h; tm[i] = __float2bfloat16(v - __bfloat162float(h));
}

__global__ void edge_deg_kernel(const int* __restrict__ dst, const float* __restrict__ attr,
                                float* __restrict__ deg2, int E)
{
    int e = blockIdx.x * blockDim.x + threadIdx.x;
    if (e < E) atomicAdd(&deg2[dst[e]], attr[e]);
}

__global__ void enorm_kernel(const int* __restrict__ src, const int* __restrict__ dst,
                             const float* __restrict__ attr, const float* __restrict__ dis2,
                             float* __restrict__ enorm, int E)
{
    int e = blockIdx.x * blockDim.x + threadIdx.x;
    if (e < E) enorm[e] = dis2[src[e]] * attr[e] * dis2[dst[e]];
}

__global__ void scatter_kernel(const float* __restrict__ xw, const int* __restrict__ src,
                               const int* __restrict__ dst, const float* __restrict__ enorm,
                               float* __restrict__ agg, int E, int d)
{
    int warp = (blockIdx.x * blockDim.x + threadIdx.x) >> 5;
    int lane = threadIdx.x & 31;
    if (warp >= E) return;
    int s = src[warp], t = dst[warp];
    float w = enorm[warp];
    const float4* xr = reinterpret_cast<const float4*>(xw + (size_t)s * DDIM);
    float* ar = agg + (size_t)t * DDIM;
#pragma unroll
    for (int h = 0; h < 2; h++) {
        int f4 = h * 32 + lane;
        float4 x = xr[f4];
        red_add_v4(ar + f4 * 4, make_float4(w * x.x, w * x.y, w * x.z, w * x.w));
    }
}

__global__ void sparse_combine_kernel(float* __restrict__ temp, const float* __restrict__ agg,
                                      const float* __restrict__ xw, const float* __restrict__ dis2,
                                      const float* __restrict__ b, int n, int d,
                                      __nv_bfloat16* __restrict__ th,
                                      __nv_bfloat16* __restrict__ tm)
{
    int i = blockIdx.x * blockDim.x + threadIdx.x;
    if (i >= n * d) return;
    int c = i / d, dd = i - c * d;
    float s = dis2[c];
    float out = agg[i] + s * s * xw[i] + b[dd];
    float v = (1.0f - PRESERVE_F) * out + PRESERVE_F * temp[i];
    temp[i] = v;
    __nv_bfloat16 h = __float2bfloat16(v);
    th[i] = h; tm[i] = __float2bfloat16(v - __bfloat162float(h));
}

__global__ void add_kernel(float* __restrict__ out, const float* __restrict__ a,
                           const float* __restrict__ b, int n)
{
    int i = blockIdx.x * blockDim.x + threadIdx.x;
    if (i < n) out[i] = a[i] + b[i];
}

// ---------------- host orchestration ----------------------------------------------
extern "C" void kernel_launch(void* const* d_in, const int* in_sizes, int n_in,
                              void* d_out, int out_size)
{
    const float* demand  = (const float*)d_in[0];
    const float* supply  = (const float*)d_in[1];
    const int*   eidx    = (const int*)  d_in[2];
    const float* eattr   = (const float*)d_in[3];
    const float* emb1    = (const float*)d_in[4];
    const float* fuse_W  = (const float*)d_in[5];
    const float* fuse_b  = (const float*)d_in[6];
    const float* gnn0_W  = (const float*)d_in[7];
    const float* gnn0_b  = (const float*)d_in[8];
    const float* gnn1_W  = (const float*)d_in[9];
    const float* gnn1_b  = (const float*)d_in[10];

    const int n = in_sizes[4] / DDIM;
    const int E = in_sizes[3];
    const int T = in_sizes[0] / (n * DDIM);

    float* out_emb1  = (float*)d_out;
    float* out_skill = out_emb1 + (size_t)n * DDIM;
    float* out_pred  = out_skill + (size_t)n * DDIM;

    float *pU, *ptD, *ptS, *pxw, *pxwS, *pZ2, *pZ2b, *pdeg, *pdis, *pdeg2, *pdis2, *pen, *psv;
    int *pnnz, *psr, *psc;
    __nv_bfloat16 *pX3h, *pX3m, *pX3l, *pUh, *pUm, *pUl;
    __nv_bfloat16 *ptDh, *ptDm, *ptSh, *ptSm;
    __nv_bfloat16 *pWfh, *pWfm, *pWfl, *pW0h, *pW0m, *pW1h, *pW1m;
    cudaGetSymbolAddress((void**)&pU,   g_U);
    cudaGetSymbolAddress((void**)&ptD,  g_tmpD);
    cudaGetSymbolAddress((void**)&ptS,  g_tmpS);
    cudaGetSymbolAddress((void**)&pxw,  g_xw);
    cudaGetSymbolAddress((void**)&pxwS, g_xwS);
    cudaGetSymbolAddress((void**)&pZ2,  g_Z2);
    cudaGetSymbolAddress((void**)&pZ2b, g_Z2b);
    cudaGetSymbolAddress((void**)&pdeg, g_deg);
    cudaGetSymbolAddress((void**)&pdis, g_dis);
    cudaGetSymbolAddress((void**)&pdeg2,g_deg2);
    cudaGetSymbolAddress((void**)&pdis2,g_dis2);
    cudaGetSymbolAddress((void**)&pen,  g_enorm);
    cudaGetSymbolAddress((void**)&pnnz, g_nnz);
    cudaGetSymbolAddress((void**)&psr,  g_sp_r);
    cudaGetSymbolAddress((void**)&psc,  g_sp_c);
    cudaGetSymbolAddress((void**)&psv,  g_sp_v);
    cudaGetSymbolAddress((void**)&pX3h, g_X3h);
    cudaGetSymbolAddress((void**)&pX3m, g_X3m);
    cudaGetSymbolAddress((void**)&pX3l, g_X3l);
    cudaGetSymbolAddress((void**)&pUh,  g_Uh);
    cudaGetSymbolAddress((void**)&pUm,  g_Um);
    cudaGetSymbolAddress((void**)&pUl,  g_Ul);
    cudaGetSymbolAddress((void**)&ptDh, g_tDh);
    cudaGetSymbolAddress((void**)&ptDm, g_tDm);
    cudaGetSymbolAddress((void**)&ptSh, g_tSh);
    cudaGetSymbolAddress((void**)&ptSm, g_tSm);
    cudaGetSymbolAddress((void**)&pWfh, g_Wfh);
    cudaGetSymbolAddress((void**)&pWfm, g_Wfm);
    cudaGetSymbolAddress((void**)&pWfl, g_Wfl);
    cudaGetSymbolAddress((void**)&pW0h, g_W0h);
    cudaGetSymbolAddress((void**)&pW0m, g_W0m);
    cudaGetSymbolAddress((void**)&pW1h, g_W1h);
    cudaGetSymbolAddress((void**)&pW1m, g_W1m);

    static cudaStream_t s2 = nullptr;
    static cudaEvent_t evFork = nullptr, evJoin = nullptr;
    static int attr_set = 0;
    if (!attr_set) {
        cudaFuncSetAttribute(syrk_mma_kernel,
                             cudaFuncAttributeMaxDynamicSharedMemorySize, SYRK_SMEM_DYN);
        cudaFuncSetAttribute(gemm_mma_kernel<3, true>,
                             cudaFuncAttributeMaxDynamicSharedMemorySize, 170496);
        cudaFuncSetAttribute(gemm_mma_kernel<2, false>,
                             cudaFuncAttributeMaxDynamicSharedMemorySize, 113664);
        cudaStreamCreateWithFlags(&s2, cudaStreamNonBlocking);
        cudaEventCreateWithFlags(&evFork, cudaEventDisableTiming);
        cudaEventCreateWithFlags(&evJoin, cudaEventDisableTiming);
        attr_set = 1;
    }

    const int ND = n * DDIM;
    const int TPB = 256;
    dim3 blk(TPB);

    // ---- prologue (stream 0): splits + fuse GEMM + U splits ----
    gather_split3_kernel<<<(ND + TPB - 1) / TPB, blk>>>(emb1, demand, supply,
                                                        pX3h, pX3m, pX3l, n, T);
    split3_kernel<<<(K3 * DDIM + TPB - 1) / TPB, blk>>>(fuse_W, pWfh, pWfm, pWfl, K3 * DDIM);
    split2_kernel<<<(LLAYERS * DDIM * DDIM + TPB - 1) / TPB, blk>>>(gnn0_W, pW0h, pW0m,
                                                                    LLAYERS * DDIM * DDIM);
    split2_kernel<<<(LLAYERS * DDIM * DDIM + TPB - 1) / TPB, blk>>>(gnn1_W, pW1h, pW1m,
                                                                    LLAYERS * DDIM * DDIM);
    cudaMemcpyAsync(out_emb1, emb1, (size_t)ND * sizeof(float), cudaMemcpyDeviceToDevice);

    {
        dim3 grid(DDIM / 128, (n + 127) / 128);
        gemm_mma_kernel<3, true><<<grid, blk, 170496>>>(pX3h, pX3m, pX3l,
                                                        pWfh, pWfm, pWfl,
                                                        pU, fuse_b, n, DDIM, K3);
    }
    split3_kernel<<<(ND + TPB - 1) / TPB, blk>>>(pU, pUh, pUm, pUl, ND);
    cudaMemcpyAsync(ptD, pU, (size_t)ND * sizeof(float), cudaMemcpyDeviceToDevice);

    // ---- fork: sparse branch on s2, dense branch continues on stream 0 ----
    cudaEventRecord(evFork, 0);
    cudaStreamWaitEvent(s2, evFork, 0);

    // === stream s2: sparse GCN branch (independent of syrk/softmax) ===
    cudaMemcpyAsync(ptS, pU, (size_t)ND * sizeof(float), cudaMemcpyDeviceToDevice, s2);
    fill_kernel<<<(n + TPB - 1) / TPB, blk, 0, s2>>>(pdeg2, 1.0f, n);
    edge_deg_kernel<<<(E + TPB - 1) / TPB, blk, 0, s2>>>(eidx + E, eattr, pdeg2, E);
    rsqrt_kernel<<<(n + TPB - 1) / TPB, blk, 0, s2>>>(pdis2, pdeg2, n);
    enorm_kernel<<<(E + TPB - 1) / TPB, blk, 0, s2>>>(eidx, eidx + E, eattr, pdis2, pen, E);
    for (int l = 0; l < LLAYERS; l++) {
        const __nv_bfloat16* Ah = (l == 0) ? pUh : ptSh;
        const __nv_bfloat16* Am = (l == 0) ? pUm : ptSm;
        dim3 grid(DDIM / 128, (n + 127) / 128);
        gemm_mma_kernel<2, false><<<grid, blk, 113664, s2>>>(Ah, Am, nullptr,
                                                             pW1h + (size_t)l * DDIM * DDIM,
                                                             pW1m + (size_t)l * DDIM * DDIM,
                                                             nullptr, pxwS, nullptr,
                                                             n, DDIM, DDIM);
        fill_kernel<<<(ND + TPB - 1) / TPB, blk, 0, s2>>>(pZ2b, 0.0f, ND);
        {
            int blocks = (E * 32 + TPB - 1) / TPB;
            scatter_kernel<<<blocks, blk, 0, s2>>>(pxwS, eidx, eidx + E, pen, pZ2b, E, DDIM);
        }
        sparse_combine_kernel<<<(ND + TPB - 1) / TPB, blk, 0, s2>>>(ptS, pZ2b, pxwS, pdis2,
                                                                    gnn1_b + (size_t)l * DDIM,
                                                                    n, DDIM, ptSh, ptSm);
    }
    cudaEventRecord(evJoin, s2);

    // === stream 0: dense branch (syrk -> softmax -> dense GCN) ===
    {
        int nblk = (n + 127) / 128;
        int ntiles = nblk * (nblk + 1) / 2;
        syrk_mma_kernel<<<ntiles, 256, SYRK_SMEM_DYN>>>(pUh, pUm, pUl, out_pred, n);
    }
    fill_kernel<<<(n + TPB - 1) / TPB, blk>>>(pdeg, 1.0f, n);
    zero_int_kernel<<<1, 1>>>(pnnz);
    softmax_relu_kernel<<<n, blk>>>(out_pred, n, pnnz, psr, psc, psv, pdeg);
    rsqrt_kernel<<<(n + TPB - 1) / TPB, blk>>>(pdis, pdeg, n);

    for (int l = 0; l < LLAYERS; l++) {
        const __nv_bfloat16* Ah = (l == 0) ? pUh : ptDh;
        const __nv_bfloat16* Am = (l == 0) ? pUm : ptDm;
        dim3 grid(DDIM / 128, (n + 127) / 128);
        gemm_mma_kernel<2, false><<<grid, blk, 113664>>>(Ah, Am, nullptr,
                                                         pW0h + (size_t)l * DDIM * DDIM,
                                                         pW0m + (size_t)l * DDIM * DDIM,
                                                         nullptr, pxw, nullptr,
                                                         n, DDIM, DDIM);
        fill_kernel<<<(ND + TPB - 1) / TPB, blk>>>(pZ2, 0.0f, ND);
        {
            int blocks = (MAXNNZ * 32 + TPB - 1) / TPB;
            dense_scatter_kernel<<<blocks, blk>>>(pxw, psr, psc, psv, pdis, pZ2, pnnz);
        }
        dense_combine_kernel<<<(ND + TPB - 1) / TPB, blk>>>(ptD, pZ2, pxw, pdis,
                                                            gnn0_b + (size_t)l * DDIM,
                                                            n, DDIM, ptDh, ptDm);
    }

    // ---- join + final add ----
    cudaStreamWaitEvent((cudaStream_t)0, evJoin, 0);
    add_kernel<<<(ND + TPB - 1) / TPB, blk>>>(out_skill, ptD, ptS, ND);
}

// round 9
// speedup vs baseline: 7.5063x; 1.2474x over previous
#include <cuda_runtime.h>
#include <cuda_fp16.h>
#include <math.h>
#include <stdint.h>

#define NNODE 8000
#define DDIM  256
#define K3    768
#define EMAX  256000
#define LLAYERS 2
#define PRESERVE_F 0.1f
#define MAXNNZ (4 * NNODE)   // softmax rows sum to 1 => <=4 entries/row exceed 0.2

// ---------------- scratch (static device memory) ---------------------------------
__device__ float g_U [NNODE * DDIM];
__device__ float g_tmpD[NNODE * DDIM];
__device__ float g_tmpS[NNODE * DDIM];
__device__ float g_xw [NNODE * DDIM];     // dense-branch xw
__device__ float g_xwS[NNODE * DDIM];     // sparse-branch xw
__device__ float g_Z2 [NNODE * DDIM];     // dense-branch agg
__device__ float g_Z2b[NNODE * DDIM];     // sparse-branch agg
__device__ float g_deg [NNODE];
__device__ float g_dis [NNODE];
__device__ float g_deg2[NNODE];
__device__ float g_dis2[NNODE];
__device__ float g_enorm[EMAX];
__device__ int   g_nnz;
__device__ int   g_sp_r[MAXNNZ];
__device__ int   g_sp_c[MAXNNZ];
__device__ float g_sp_v[MAXNNZ];
// fp16 2-way splits (x = h + l, ~22 mantissa bits)
__device__ __half g_X3h[NNODE * K3];
__device__ __half g_X3l[NNODE * K3];
__device__ __half g_Uh[NNODE * DDIM];
__device__ __half g_Ul[NNODE * DDIM];
__device__ __half g_tDh[NNODE * DDIM];
__device__ __half g_tDl[NNODE * DDIM];
__device__ __half g_tSh[NNODE * DDIM];
__device__ __half g_tSl[NNODE * DDIM];
__device__ __half g_Wfh[K3 * DDIM];
__device__ __half g_Wfl[K3 * DDIM];
__device__ __half g_W0h[LLAYERS * DDIM * DDIM];
__device__ __half g_W0l[LLAYERS * DDIM * DDIM];
__device__ __half g_W1h[LLAYERS * DDIM * DDIM];
__device__ __half g_W1l[LLAYERS * DDIM * DDIM];

__device__ __forceinline__ uint32_t smem_u32(const void* p) {
    uint32_t a;
    asm("{ .reg .u64 t; cvta.to.shared.u64 t, %1; cvt.u32.u64 %0, t; }" : "=r"(a) : "l"(p));
    return a;
}

__device__ __forceinline__ void red_add_v4(float* addr, float4 v) {
    asm volatile("red.global.add.v4.f32 [%0], {%1,%2,%3,%4};"
                 :: "l"(addr), "f"(v.x), "f"(v.y), "f"(v.z), "f"(v.w) : "memory");
}

#define LDSM_X4(r0, r1, r2, r3, addr) \
    asm volatile("ldmatrix.sync.aligned.m8n8.x4.shared.b16 {%0,%1,%2,%3}, [%4];" \
                 : "=r"(r0), "=r"(r1), "=r"(r2), "=r"(r3) : "r"(addr))
#define LDSM_X2(r0, r1, addr) \
    asm volatile("ldmatrix.sync.aligned.m8n8.x2.shared.b16 {%0,%1}, [%2];" \
                 : "=r"(r0), "=r"(r1) : "r"(addr))
#define LDSM_X2_T(r0, r1, addr) \
    asm volatile("ldmatrix.sync.aligned.m8n8.x2.trans.shared.b16 {%0,%1}, [%2];" \
                 : "=r"(r0), "=r"(r1) : "r"(addr))
#define MMA_F16(c, a0, a1, a2, a3, b0, b1) \
    asm volatile("mma.sync.aligned.m16n8k16.row.col.f32.f16.f16.f32 " \
                 "{%0,%1,%2,%3}, {%4,%5,%6,%7}, {%8,%9}, {%0,%1,%2,%3};" \
                 : "+f"((c)[0]), "+f"((c)[1]), "+f"((c)[2]), "+f"((c)[3]) \
                 : "r"(a0), "r"(a1), "r"(a2), "r"(a3), "r"(b0), "r"(b1))
#define CP_ASYNC16(saddr, gptr, sz) \
    asm volatile("cp.async.cg.shared.global [%0], [%1], 16, %2;" \
                 :: "r"(saddr), "l"(gptr), "r"(sz))
#define CP_COMMIT() asm volatile("cp.async.commit_group;")
#define CP_WAIT2()  asm volatile("cp.async.wait_group 2;")
#define CP_WAIT1()  asm volatile("cp.async.wait_group 1;")
#define CP_WAIT0()  asm volatile("cp.async.wait_group 0;")

#define LDT 40   // A-tile smem stride (fp16), 80 B
#define LDB 136  // B-tile smem stride (fp16), 272 B

// =================== syrk: C = U @ U^T (fp16 2-split, 3 products, 3-stage) =======
#define SYRK_TILE_ELEMS (128 * LDT)
#define SYRK_STAGE_ELEMS (4 * SYRK_TILE_ELEMS)          // Ah Al Bh Bl
#define SYRK_SMEM_DYN (3 * SYRK_STAGE_ELEMS * 2)        // 122880 B

__global__ __launch_bounds__(256)
void syrk_mma_kernel(const __half* __restrict__ Uh,
                     const __half* __restrict__ Ul,
                     float* __restrict__ C, int n)
{
    extern __shared__ char smem[];
    __half* tiles = (__half*)smem;
    float* epi = (float*)smem;

    const int tid  = threadIdx.x;
    const int wid  = tid >> 5;
    const int lane = tid & 31;
    const int wm   = wid & 1;
    const int wn   = wid >> 1;
    const int group = lane >> 2;
    const int tig   = lane & 3;

    int t = blockIdx.x;
    int bi = (int)((sqrtf(8.0f * (float)t + 1.0f) - 1.0f) * 0.5f);
    while ((bi + 1) * (bi + 2) / 2 <= t) bi++;
    while (bi * (bi + 1) / 2 > t) bi--;
    int bj = t - bi * (bi + 1) / 2;
    const int m0 = bi * 128;
    const int n0 = bj * 128;

    float acc[4][4][4];
#pragma unroll
    for (int a = 0; a < 4; a++)
#pragma unroll
        for (int b = 0; b < 4; b++)
#pragma unroll
            for (int c = 0; c < 4; c++) acc[a][b][c] = 0.f;

    const __half* srcs[4] = { Uh, Ul, Uh, Ul };
    const uint32_t sT = smem_u32(tiles);

    const int a_row = (lane & 15);
    const int a_col = (lane >> 4) * 8;
    const int b_row = (lane & 7);
    const int b_col = ((lane >> 3) & 1) * 8;
    const uint32_t a_base = (uint32_t)((wm * 64 + a_row) * LDT + a_col) * 2;
    const uint32_t b_base = (uint32_t)((wn * 32 + b_row) * LDT + b_col) * 2;

    auto load_chunk = [&](int k0, int stage) {
        uint32_t dst0 = sT + (uint32_t)(stage * SYRK_STAGE_ELEMS) * 2;
#pragma unroll
        for (int s = 0; s < 4; s++) {
            const __half* src = srcs[s];
            const int rowbase = (s < 2) ? m0 : n0;
            uint32_t dts = dst0 + (uint32_t)(s * SYRK_TILE_ELEMS) * 2;
#pragma unroll
            for (int it = 0; it < 2; it++) {
                int lin = it * 256 + tid;
                int r   = lin >> 2;
                int c8  = (lin & 3) * 8;
                int g   = rowbase + r;
                uint32_t sz = (g < n) ? 16u : 0u;
                int g2 = (g < n) ? g : 0;
                const __half* gp = src + (size_t)g2 * DDIM + k0 + c8;
                CP_ASYNC16(dts + (uint32_t)(r * LDT + c8) * 2, gp, sz);
            }
        }
    };

    load_chunk(0, 0);
    CP_COMMIT();
    load_chunk(32, 1);
    CP_COMMIT();

#pragma unroll 1
    for (int kc = 0; kc < 8; kc++) {
        const int cur = kc % 3;
        if (kc + 2 < 8) {
            load_chunk((kc + 2) * 32, (kc + 2) % 3);
            CP_COMMIT();
            CP_WAIT2();
        } else if (kc + 1 < 8) {
            CP_WAIT1();
        } else {
            CP_WAIT0();
        }
        __syncthreads();

        const uint32_t stg = sT + (uint32_t)(cur * SYRK_STAGE_ELEMS) * 2;
        const uint32_t sAh = stg;
        const uint32_t sAl = stg + SYRK_TILE_ELEMS * 2u;
        const uint32_t sBh = stg + SYRK_TILE_ELEMS * 4u;
        const uint32_t sBl = stg + SYRK_TILE_ELEMS * 6u;

#pragma unroll
        for (int ks = 0; ks < 2; ks++) {
            const uint32_t koff = (uint32_t)(ks * 16) * 2;
            uint32_t ah[4][4], bh[4][2];
#pragma unroll
            for (int mt = 0; mt < 4; mt++)
                LDSM_X4(ah[mt][0], ah[mt][1], ah[mt][2], ah[mt][3],
                        sAh + a_base + koff + (uint32_t)(mt * 16 * LDT) * 2);
#pragma unroll
            for (int nt = 0; nt < 4; nt++)
                LDSM_X2(bh[nt][0], bh[nt][1],
                        sBh + b_base + koff + (uint32_t)(nt * 8 * LDT) * 2);
            // hh
#pragma unroll
            for (int mt = 0; mt < 4; mt++)
#pragma unroll
                for (int nt = 0; nt < 4; nt++)
                    MMA_F16(acc[mt][nt], ah[mt][0], ah[mt][1], ah[mt][2], ah[mt][3],
                            bh[nt][0], bh[nt][1]);
            {   // hl
                uint32_t bl[4][2];
#pragma unroll
                for (int nt = 0; nt < 4; nt++)
                    LDSM_X2(bl[nt][0], bl[nt][1],
                            sBl + b_base + koff + (uint32_t)(nt * 8 * LDT) * 2);
#pragma unroll
                for (int mt = 0; mt < 4; mt++)
#pragma unroll
                    for (int nt = 0; nt < 4; nt++)
                        MMA_F16(acc[mt][nt], ah[mt][0], ah[mt][1], ah[mt][2], ah[mt][3],
                                bl[nt][0], bl[nt][1]);
            }
            {   // lh
                uint32_t al[4][4];
#pragma unroll
                for (int mt = 0; mt < 4; mt++)
                    LDSM_X4(al[mt][0], al[mt][1], al[mt][2], al[mt][3],
                            sAl + a_base + koff + (uint32_t)(mt * 16 * LDT) * 2);
#pragma unroll
                for (int mt = 0; mt < 4; mt++)
#pragma unroll
                    for (int nt = 0; nt < 4; nt++)
                        MMA_F16(acc[mt][nt], al[mt][0], al[mt][1], al[mt][2], al[mt][3],
                                bh[nt][0], bh[nt][1]);
            }
        }
        __syncthreads();
    }

    // direct write
#pragma unroll
    for (int mt = 0; mt < 4; mt++) {
#pragma unroll
        for (int nt = 0; nt < 4; nt++) {
            int lm = wm * 64 + mt * 16 + group;
            int ln = wn * 32 + nt * 8 + tig * 2;
            int gm = m0 + lm, gn = n0 + ln;
            if (gn + 1 < n) {
                if (gm < n)
                    *reinterpret_cast<float2*>(C + (size_t)gm * n + gn) =
                        make_float2(acc[mt][nt][0], acc[mt][nt][1]);
                if (gm + 8 < n)
                    *reinterpret_cast<float2*>(C + (size_t)(gm + 8) * n + gn) =
                        make_float2(acc[mt][nt][2], acc[mt][nt][3]);
            }
        }
    }

    // mirrored write via smem transpose
    if (bi != bj) {
        __syncthreads();
#pragma unroll
        for (int mt = 0; mt < 4; mt++) {
#pragma unroll
            for (int nt = 0; nt < 4; nt++) {
                int lm = wm * 64 + mt * 16 + group;
                int ln = wn * 32 + nt * 8 + tig * 2;
                epi[lm * 129 + ln]           = acc[mt][nt][0];
                epi[lm * 129 + ln + 1]       = acc[mt][nt][1];
                epi[(lm + 8) * 129 + ln]     = acc[mt][nt][2];
                epi[(lm + 8) * 129 + ln + 1] = acc[mt][nt][3];
            }
        }
        __syncthreads();
        const int c_row = tid >> 1;
        const int half  = tid & 1;
        const int grow  = n0 + c_row;
        if (grow < n) {
            float* outrow = C + (size_t)grow * n;
#pragma unroll
            for (int i = 0; i < 16; i++) {
                int ml = half * 64 + i * 4;
                if (m0 + ml + 3 < n) {
                    float4 v = make_float4(epi[(ml + 0) * 129 + c_row],
                                           epi[(ml + 1) * 129 + c_row],
                                           epi[(ml + 2) * 129 + c_row],
                                           epi[(ml + 3) * 129 + c_row]);
                    *reinterpret_cast<float4*>(outrow + m0 + ml) = v;
                } else {
                    for (int q = 0; q < 4; q++)
                        if (m0 + ml + q < n)
                            outrow[m0 + ml + q] = epi[(ml + q) * 129 + c_row];
                }
            }
        }
    }
}

// =================== GEMM: C = A @ B (+bias), fp16 2-split, 3 products ===========
#define GEMM_AT_ELEMS (128 * LDT)
#define GEMM_BT_ELEMS (32 * LDB)
#define GEMM_STAGE_ELEMS (2 * (GEMM_AT_ELEMS + GEMM_BT_ELEMS))
#define GEMM_SMEM_DYN (3 * GEMM_STAGE_ELEMS * 2)        // 113664 B

template<bool BIAS>
__global__ __launch_bounds__(256)
void gemm_mma_kernel(const __half* __restrict__ Ah_,
                     const __half* __restrict__ Al_,
                     const __half* __restrict__ Bh_,
                     const __half* __restrict__ Bl_,
                     float* __restrict__ C, const float* __restrict__ bias,
                     int M, int N, int K)
{
    extern __shared__ char smem[];
    __half* tiles = (__half*)smem;

    const int tid  = threadIdx.x;
    const int wid  = tid >> 5;
    const int lane = tid & 31;
    const int wm   = wid & 1;
    const int wn   = wid >> 1;
    const int group = lane >> 2;
    const int tig   = lane & 3;

    const int n0 = blockIdx.x * 128;
    const int m0 = blockIdx.y * 128;

    float acc[4][4][4];
#pragma unroll
    for (int a = 0; a < 4; a++)
#pragma unroll
        for (int b = 0; b < 4; b++)
#pragma unroll
            for (int c = 0; c < 4; c++) acc[a][b][c] = 0.f;

    const __half* Asrc[2] = { Ah_, Al_ };
    const __half* Bsrc[2] = { Bh_, Bl_ };
    const uint32_t sT = smem_u32(tiles);

    const int a_row = (lane & 15);
    const int a_col = (lane >> 4) * 8;
    const uint32_t a_base = (uint32_t)((wm * 64 + a_row) * LDT + a_col) * 2;
    const uint32_t bt_base = (uint32_t)((lane & 15) * LDB + wn * 32) * 2;

    auto load_chunk = [&](int k0, int stage) {
        uint32_t dst0 = sT + (uint32_t)(stage * GEMM_STAGE_ELEMS) * 2;
#pragma unroll
        for (int s = 0; s < 2; s++) {
            uint32_t dts = dst0 + (uint32_t)(s * GEMM_AT_ELEMS) * 2;
#pragma unroll
            for (int it = 0; it < 2; it++) {
                int lin = it * 256 + tid;
                int r   = lin >> 2;
                int c8  = (lin & 3) * 8;
                int g   = m0 + r;
                uint32_t sz = (g < M) ? 16u : 0u;
                int g2 = (g < M) ? g : 0;
                const __half* gp = Asrc[s] + (size_t)g2 * K + k0 + c8;
                CP_ASYNC16(dts + (uint32_t)(r * LDT + c8) * 2, gp, sz);
            }
        }
        uint32_t dstB = dst0 + (uint32_t)(2 * GEMM_AT_ELEMS) * 2;
#pragma unroll
        for (int s = 0; s < 2; s++) {
            uint32_t dts = dstB + (uint32_t)(s * GEMM_BT_ELEMS) * 2;
#pragma unroll
            for (int it = 0; it < 2; it++) {
                int lin = it * 256 + tid;
                int r   = lin >> 4;
                int c8  = (lin & 15) * 8;
                const __half* gp = Bsrc[s] + (size_t)(k0 + r) * N + n0 + c8;
                CP_ASYNC16(dts + (uint32_t)(r * LDB + c8) * 2, gp, 16u);
            }
        }
    };

    const int NC = K / 32;
    load_chunk(0, 0);
    CP_COMMIT();
    if (NC > 1) { load_chunk(32, 1); CP_COMMIT(); }

#pragma unroll 1
    for (int kc = 0; kc < NC; kc++) {
        const int cur = kc % 3;
        if (kc + 2 < NC) {
            load_chunk((kc + 2) * 32, (kc + 2) % 3);
            CP_COMMIT();
            CP_WAIT2();
        } else if (kc + 1 < NC) {
            CP_WAIT1();
        } else {
            CP_WAIT0();
        }
        __syncthreads();

        const uint32_t stg = sT + (uint32_t)(cur * GEMM_STAGE_ELEMS) * 2;
        const uint32_t sAh = stg;
        const uint32_t sAl = stg + GEMM_AT_ELEMS * 2u;
        const uint32_t sBh = stg + GEMM_AT_ELEMS * 4u;
        const uint32_t sBl = sBh + GEMM_BT_ELEMS * 2u;

#pragma unroll
        for (int ks = 0; ks < 2; ks++) {
            const uint32_t akoff = (uint32_t)(ks * 16) * 2;
            const uint32_t bkoff = (uint32_t)(ks * 16 * LDB) * 2;
            uint32_t ah[4][4], bh[4][2];
#pragma unroll
            for (int mt = 0; mt < 4; mt++)
                LDSM_X4(ah[mt][0], ah[mt][1], ah[mt][2], ah[mt][3],
                        sAh + a_base + akoff + (uint32_t)(mt * 16 * LDT) * 2);
#pragma unroll
            for (int nt = 0; nt < 4; nt++)
                LDSM_X2_T(bh[nt][0], bh[nt][1],
                          sBh + bt_base + bkoff + (uint32_t)(nt * 8) * 2);
            // hh
#pragma unroll
            for (int mt = 0; mt < 4; mt++)
#pragma unroll
                for (int nt = 0; nt < 4; nt++)
                    MMA_F16(acc[mt][nt], ah[mt][0], ah[mt][1], ah[mt][2], ah[mt][3],
                            bh[nt][0], bh[nt][1]);
            {   // hl
                uint32_t bl[4][2];
#pragma unroll
                for (int nt = 0; nt < 4; nt++)
                    LDSM_X2_T(bl[nt][0], bl[nt][1],
                              sBl + bt_base + bkoff + (uint32_t)(nt * 8) * 2);
#pragma unroll
                for (int mt = 0; mt < 4; mt++)
#pragma unroll
                    for (int nt = 0; nt < 4; nt++)
                        MMA_F16(acc[mt][nt], ah[mt][0], ah[mt][1], ah[mt][2], ah[mt][3],
                                bl[nt][0], bl[nt][1]);
            }
            {   // lh
                uint32_t al[4][4];
#pragma unroll
                for (int mt = 0; mt < 4; mt++)
                    LDSM_X4(al[mt][0], al[mt][1], al[mt][2], al[mt][3],
                            sAl + a_base + akoff + (uint32_t)(mt * 16 * LDT) * 2);
#pragma unroll
                for (int mt = 0; mt < 4; mt++)
#pragma unroll
                    for (int nt = 0; nt < 4; nt++)
                        MMA_F16(acc[mt][nt], al[mt][0], al[mt][1], al[mt][2], al[mt][3],
                                bh[nt][0], bh[nt][1]);
            }
        }
        __syncthreads();
    }

    // epilogue
#pragma unroll
    for (int mt = 0; mt < 4; mt++) {
#pragma unroll
        for (int nt = 0; nt < 4; nt++) {
            int lm = wm * 64 + mt * 16 + group;
            int ln = wn * 32 + nt * 8 + tig * 2;
            int gm = m0 + lm, gn = n0 + ln;
            float b0 = 0.f, b1 = 0.f;
            if (BIAS) { b0 = bias[gn]; b1 = bias[gn + 1]; }
            if (gm < M)
                *reinterpret_cast<float2*>(C + (size_t)gm * N + gn) =
                    make_float2(acc[mt][nt][0] + b0, acc[mt][nt][1] + b1);
            if (gm + 8 < M)
                *reinterpret_cast<float2*>(C + (size_t)(gm + 8) * N + gn) =
                    make_float2(acc[mt][nt][2] + b0, acc[mt][nt][3] + b1);
        }
    }
}

// ---------------- split kernels (fp16 2-way) --------------------------------------
__global__ void split2h_kernel(const float* __restrict__ U,
                               __half* __restrict__ Uh,
                               __half* __restrict__ Ul, int total)
{
    int i = blockIdx.x * blockDim.x + threadIdx.x;
    if (i >= total) return;
    float x = U[i];
    __half h = __float2half(x);
    Uh[i] = h;
    Ul[i] = __float2half(x - __half2float(h));
}

__global__ void gather_split2_kernel(const float* __restrict__ emb1,
                                     const float* __restrict__ demand,
                                     const float* __restrict__ supply,
                                     __half* __restrict__ Xh,
                                     __half* __restrict__ Xl, int n, int T)
{
    int i = blockIdx.x * blockDim.x + threadIdx.x;
    int total = n * DDIM;
    if (i >= total) return;
    int node = i / DDIM, d = i % DDIM;
    float v[3];
    v[0] = emb1[(size_t)node * DDIM + d];
    v[1] = demand[((size_t)node * T + (T - 1)) * DDIM + d];
    v[2] = supply[((size_t)node * T + (T - 1)) * DDIM + d];
#pragma unroll
    for (int s = 0; s < 3; s++) {
        size_t idx = (size_t)node * K3 + s * DDIM + d;
        float x = v[s];
        __half h = __float2half(x);
        Xh[idx] = h;
        Xl[idx] = __float2half(x - __half2float(h));
    }
}

// ---------------- small kernels ---------------------------------------------------
__global__ void softmax_relu_kernel(float* __restrict__ Z, int n,
                                    int* __restrict__ nnz,
                                    int* __restrict__ sr, int* __restrict__ sc,
                                    float* __restrict__ sv,
                                    float* __restrict__ deg)
{
    __shared__ float row[NNODE];
    __shared__ float red[256];
    int r = blockIdx.x;
    int t = threadIdx.x;
    float* zr = Z + (size_t)r * n;
    const int n4 = n >> 2;

    float mx = -3.4e38f;
    for (int c4 = t; c4 < n4; c4 += 256) {
        float4 v = reinterpret_cast<const float4*>(zr)[c4];
        reinterpret_cast<float4*>(row)[c4] = v;
        mx = fmaxf(mx, fmaxf(fmaxf(v.x, v.y), fmaxf(v.z, v.w)));
    }
    for (int c = n4 * 4 + t; c < n; c += 256) { float v = zr[c]; row[c] = v; mx = fmaxf(mx, v); }
    red[t] = mx; __syncthreads();
    for (int s = 128; s > 0; s >>= 1) {
        if (t < s) red[t] = fmaxf(red[t], red[t + s]);
        __syncthreads();
    }
    mx = red[0];
    __syncthreads();

    float sm = 0.f;
    for (int c4 = t; c4 < n4; c4 += 256) {
        float4 v = reinterpret_cast<const float4*>(row)[c4];
        v.x = __expf(v.x - mx); v.y = __expf(v.y - mx);
        v.z = __expf(v.z - mx); v.w = __expf(v.w - mx);
        reinterpret_cast<float4*>(row)[c4] = v;
        sm += v.x + v.y + v.z + v.w;
    }
    for (int c = n4 * 4 + t; c < n; c += 256) { float e = __expf(row[c] - mx); row[c] = e; sm += e; }
    red[t] = sm; __syncthreads();
    for (int s = 128; s > 0; s >>= 1) {
        if (t < s) red[t] += red[t + s];
        __syncthreads();
    }
    float inv = 1.0f / red[0];
    for (int c4 = t; c4 < n4; c4 += 256) {
        float4 v = reinterpret_cast<const float4*>(row)[c4];
        float4 p;
        p.x = fmaxf(v.x * inv - 0.2f, 0.f);
        p.y = fmaxf(v.y * inv - 0.2f, 0.f);
        p.z = fmaxf(v.z * inv - 0.2f, 0.f);
        p.w = fmaxf(v.w * inv - 0.2f, 0.f);
        reinterpret_cast<float4*>(zr)[c4] = p;
        float pv[4] = { p.x, p.y, p.z, p.w };
#pragma unroll
        for (int q = 0; q < 4; q++) {
            if (pv[q] > 0.f) {
                int c = c4 * 4 + q;
                int idx = atomicAdd(nnz, 1);
                if (idx < MAXNNZ) { sr[idx] = r; sc[idx] = c; sv[idx] = pv[q]; }
                atomicAdd(&deg[c], pv[q]);
            }
        }
    }
    for (int c = n4 * 4 + t; c < n; c += 256) {
        float p = fmaxf(row[c] * inv - 0.2f, 0.f);
        zr[c] = p;
        if (p > 0.f) {
            int idx = atomicAdd(nnz, 1);
            if (idx < MAXNNZ) { sr[idx] = r; sc[idx] = c; sv[idx] = p; }
            atomicAdd(&deg[c], p);
        }
    }
}

__global__ void fill_kernel(float* p, float v, int n)
{
    int i = blockIdx.x * blockDim.x + threadIdx.x;
    if (i < n) p[i] = v;
}

__global__ void zero_int_kernel(int* p) { *p = 0; }

__global__ void rsqrt_kernel(float* __restrict__ dst, const float* __restrict__ src, int n)
{
    int i = blockIdx.x * blockDim.x + threadIdx.x;
    if (i < n) dst[i] = rsqrtf(src[i]);
}

__global__ void dense_scatter_kernel(const float* __restrict__ xw,
                                     const int* __restrict__ sr,
                                     const int* __restrict__ sc,
                                     const float* __restrict__ sv,
                                     const float* __restrict__ dis,
                                     float* __restrict__ agg,
                                     const int* __restrict__ nnz)
{
    int warp = (blockIdx.x * blockDim.x + threadIdx.x) >> 5;
    int lane = threadIdx.x & 31;
    int m = *nnz; if (m > MAXNNZ) m = MAXNNZ;
    if (warp >= m) return;
    int r = sr[warp], c = sc[warp];
    float w = sv[warp] * dis[r];
    const float4* xr = reinterpret_cast<const float4*>(xw + (size_t)r * DDIM);
    float* ar = agg + (size_t)c * DDIM;
#pragma unroll
    for (int h = 0; h < 2; h++) {
        int f4 = h * 32 + lane;
        float4 x = xr[f4];
        red_add_v4(ar + f4 * 4, make_float4(w * x.x, w * x.y, w * x.z, w * x.w));
    }
}

__global__ void dense_combine_kernel(float* __restrict__ temp, const float* __restrict__ Z2,
                                     const float* __restrict__ xw, const float* __restrict__ dis,
                                     const float* __restrict__ b, int n, int d,
                                     __half* __restrict__ th,
                                     __half* __restrict__ tl)
{
    int i = blockIdx.x * blockDim.x + threadIdx.x;
    if (i >= n * d) return;
    int c = i / d, dd = i - c * d;
    float s = dis[c];
    float out = s * Z2[i] + s * s * xw[i] + b[dd];
    float v = (1.0f - PRESERVE_F) * out + PRESERVE_F * temp[i];
    temp[i] = v;
    __half h = __float2half(v);
    th[i] = h; tl[i] = __float2half(v - __half2float(h));
}

__global__ void edge_deg_kernel(const int* __restrict__ dst, const float* __restrict__ attr,
                                float* __restrict__ deg2, int E)
{
    int e = blockIdx.x * blockDim.x + threadIdx.x;
    if (e < E) atomicAdd(&deg2[dst[e]], attr[e]);
}

__global__ void enorm_kernel(const int* __restrict__ src, const int* __restrict__ dst,
                             const float* __restrict__ attr, const float* __restrict__ dis2,
                             float* __restrict__ enorm, int E)
{
    int e = blockIdx.x * blockDim.x + threadIdx.x;
    if (e < E) enorm[e] = dis2[src[e]] * attr[e] * dis2[dst[e]];
}

__global__ void scatter_kernel(const float* __restrict__ xw, const int* __restrict__ src,
                               const int* __restrict__ dst, const float* __restrict__ enorm,
                               float* __restrict__ agg, int E, int d)
{
    int warp = (blockIdx.x * blockDim.x + threadIdx.x) >> 5;
    int lane = threadIdx.x & 31;
    if (warp >= E) return;
    int s = src[warp], t = dst[warp];
    float w = enorm[warp];
    const float4* xr = reinterpret_cast<const float4*>(xw + (size_t)s * DDIM);
    float* ar = agg + (size_t)t * DDIM;
#pragma unroll
    for (int h = 0; h < 2; h++) {
        int f4 = h * 32 + lane;
        float4 x = xr[f4];
        red_add_v4(ar + f4 * 4, make_float4(w * x.x, w * x.y, w * x.z, w * x.w));
    }
}

__global__ void sparse_combine_kernel(float* __restrict__ temp, const float* __restrict__ agg,
                                      const float* __restrict__ xw, const float* __restrict__ dis2,
                                      const float* __restrict__ b, int n, int d,
                                      __half* __restrict__ th,
                                      __half* __restrict__ tl)
{
    int i = blockIdx.x * blockDim.x + threadIdx.x;
    if (i >= n * d) return;
    int c = i / d, dd = i - c * d;
    float s = dis2[c];
    float out = agg[i] + s * s * xw[i] + b[dd];
    float v = (1.0f - PRESERVE_F) * out + PRESERVE_F * temp[i];
    temp[i] = v;
    __half h = __float2half(v);
    th[i] = h; tl[i] = __float2half(v - __half2float(h));
}

__global__ void add_kernel(float* __restrict__ out, const float* __restrict__ a,
                           const float* __restrict__ b, int n)
{
    int i = blockIdx.x * blockDim.x + threadIdx.x;
    if (i < n) out[i] = a[i] + b[i];
}

// ---------------- host orchestration ----------------------------------------------
extern "C" void kernel_launch(void* const* d_in, const int* in_sizes, int n_in,
                              void* d_out, int out_size)
{
    const float* demand  = (const float*)d_in[0];
    const float* supply  = (const float*)d_in[1];
    const int*   eidx    = (const int*)  d_in[2];
    const float* eattr   = (const float*)d_in[3];
    const float* emb1    = (const float*)d_in[4];
    const float* fuse_W  = (const float*)d_in[5];
    const float* fuse_b  = (const float*)d_in[6];
    const float* gnn0_W  = (const float*)d_in[7];
    const float* gnn0_b  = (const float*)d_in[8];
    const float* gnn1_W  = (const float*)d_in[9];
    const float* gnn1_b  = (const float*)d_in[10];

    const int n = in_sizes[4] / DDIM;
    const int E = in_sizes[3];
    const int T = in_sizes[0] / (n * DDIM);

    float* out_emb1  = (float*)d_out;
    float* out_skill = out_emb1 + (size_t)n * DDIM;
    float* out_pred  = out_skill + (size_t)n * DDIM;

    float *pU, *ptD, *ptS, *pxw, *pxwS, *pZ2, *pZ2b, *pdeg, *pdis, *pdeg2, *pdis2, *pen, *psv;
    int *pnnz, *psr, *psc;
    __half *pX3h, *pX3l, *pUh, *pUl, *ptDh, *ptDl, *ptSh, *ptSl;
    __half *pWfh, *pWfl, *pW0h, *pW0l, *pW1h, *pW1l;
    cudaGetSymbolAddress((void**)&pU,   g_U);
    cudaGetSymbolAddress((void**)&ptD,  g_tmpD);
    cudaGetSymbolAddress((void**)&ptS,  g_tmpS);
    cudaGetSymbolAddress((void**)&pxw,  g_xw);
    cudaGetSymbolAddress((void**)&pxwS, g_xwS);
    cudaGetSymbolAddress((void**)&pZ2,  g_Z2);
    cudaGetSymbolAddress((void**)&pZ2b, g_Z2b);
    cudaGetSymbolAddress((void**)&pdeg, g_deg);
    cudaGetSymbolAddress((void**)&pdis, g_dis);
    cudaGetSymbolAddress((void**)&pdeg2,g_deg2);
    cudaGetSymbolAddress((void**)&pdis2,g_dis2);
    cudaGetSymbolAddress((void**)&pen,  g_enorm);
    cudaGetSymbolAddress((void**)&pnnz, g_nnz);
    cudaGetSymbolAddress((void**)&psr,  g_sp_r);
    cudaGetSymbolAddress((void**)&psc,  g_sp_c);
    cudaGetSymbolAddress((void**)&psv,  g_sp_v);
    cudaGetSymbolAddress((void**)&pX3h, g_X3h);
    cudaGetSymbolAddress((void**)&pX3l, g_X3l);
    cudaGetSymbolAddress((void**)&pUh,  g_Uh);
    cudaGetSymbolAddress((void**)&pUl,  g_Ul);
    cudaGetSymbolAddress((void**)&ptDh, g_tDh);
    cudaGetSymbolAddress((void**)&ptDl, g_tDl);
    cudaGetSymbolAddress((void**)&ptSh, g_tSh);
    cudaGetSymbolAddress((void**)&ptSl, g_tSl);
    cudaGetSymbolAddress((void**)&pWfh, g_Wfh);
    cudaGetSymbolAddress((void**)&pWfl, g_Wfl);
    cudaGetSymbolAddress((void**)&pW0h, g_W0h);
    cudaGetSymbolAddress((void**)&pW0l, g_W0l);
    cudaGetSymbolAddress((void**)&pW1h, g_W1h);
    cudaGetSymbolAddress((void**)&pW1l, g_W1l);

    static cudaStream_t s2 = nullptr;
    static cudaEvent_t evFork = nullptr, evJoin = nullptr;
    static int attr_set = 0;
    if (!attr_set) {
        cudaFuncSetAttribute(syrk_mma_kernel,
                             cudaFuncAttributeMaxDynamicSharedMemorySize, SYRK_SMEM_DYN);
        cudaFuncSetAttribute(gemm_mma_kernel<true>,
                             cudaFuncAttributeMaxDynamicSharedMemorySize, GEMM_SMEM_DYN);
        cudaFuncSetAttribute(gemm_mma_kernel<false>,
                             cudaFuncAttributeMaxDynamicSharedMemorySize, GEMM_SMEM_DYN);
        cudaStreamCreateWithFlags(&s2, cudaStreamNonBlocking);
        cudaEventCreateWithFlags(&evFork, cudaEventDisableTiming);
        cudaEventCreateWithFlags(&evJoin, cudaEventDisableTiming);
        attr_set = 1;
    }

    const int ND = n * DDIM;
    const int TPB = 256;
    dim3 blk(TPB);

    // ---- prologue (stream 0): splits + fuse GEMM + U splits ----
    gather_split2_kernel<<<(ND + TPB - 1) / TPB, blk>>>(emb1, demand, supply,
                                                        pX3h, pX3l, n, T);
    split2h_kernel<<<(K3 * DDIM + TPB - 1) / TPB, blk>>>(fuse_W, pWfh, pWfl, K3 * DDIM);
    split2h_kernel<<<(LLAYERS * DDIM * DDIM + TPB - 1) / TPB, blk>>>(gnn0_W, pW0h, pW0l,
                                                                     LLAYERS * DDIM * DDIM);
    split2h_kernel<<<(LLAYERS * DDIM * DDIM + TPB - 1) / TPB, blk>>>(gnn1_W, pW1h, pW1l,
                                                                     LLAYERS * DDIM * DDIM);
    cudaMemcpyAsync(out_emb1, emb1, (size_t)ND * sizeof(float), cudaMemcpyDeviceToDevice);

    {
        dim3 grid(DDIM / 128, (n + 127) / 128);
        gemm_mma_kernel<true><<<grid, blk, GEMM_SMEM_DYN>>>(pX3h, pX3l, pWfh, pWfl,
                                                            pU, fuse_b, n, DDIM, K3);
    }
    split2h_kernel<<<(ND + TPB - 1) / TPB, blk>>>(pU, pUh, pUl, ND);
    cudaMemcpyAsync(ptD, pU, (size_t)ND * sizeof(float), cudaMemcpyDeviceToDevice);

    // ---- fork: sparse branch on s2, dense branch continues on stream 0 ----
    cudaEventRecord(evFork, 0);
    cudaStreamWaitEvent(s2, evFork, 0);

    // === stream s2: sparse GCN branch ===
    cudaMemcpyAsync(ptS, pU, (size_t)ND * sizeof(float), cudaMemcpyDeviceToDevice, s2);
    fill_kernel<<<(n + TPB - 1) / TPB, blk, 0, s2>>>(pdeg2, 1.0f, n);
    edge_deg_kernel<<<(E + TPB - 1) / TPB, blk, 0, s2>>>(eidx + E, eattr, pdeg2, E);
    rsqrt_kernel<<<(n + TPB - 1) / TPB, blk, 0, s2>>>(pdis2, pdeg2, n);
    enorm_kernel<<<(E + TPB - 1) / TPB, blk, 0, s2>>>(eidx, eidx + E, eattr, pdis2, pen, E);
    for (int l = 0; l < LLAYERS; l++) {
        const __half* Ah = (l == 0) ? pUh : ptSh;
        const __half* Al = (l == 0) ? pUl : ptSl;
        dim3 grid(DDIM / 128, (n + 127) / 128);
        gemm_mma_kernel<false><<<grid, blk, GEMM_SMEM_DYN, s2>>>(Ah, Al,
                                                                 pW1h + (size_t)l * DDIM * DDIM,
                                                                 pW1l + (size_t)l * DDIM * DDIM,
                                                                 pxwS, nullptr, n, DDIM, DDIM);
        fill_kernel<<<(ND + TPB - 1) / TPB, blk, 0, s2>>>(pZ2b, 0.0f, ND);
        {
            int blocks = (E * 32 + TPB - 1) / TPB;
            scatter_kernel<<<blocks, blk, 0, s2>>>(pxwS, eidx, eidx + E, pen, pZ2b, E, DDIM);
        }
        sparse_combine_kernel<<<(ND + TPB - 1) / TPB, blk, 0, s2>>>(ptS, pZ2b, pxwS, pdis2,
                                                                    gnn1_b + (size_t)l * DDIM,
                                                                    n, DDIM, ptSh, ptSl);
    }
    cudaEventRecord(evJoin, s2);

    // === stream 0: dense branch (syrk -> softmax -> dense GCN) ===
    {
        int nblk = (n + 127) / 128;
        int ntiles = nblk * (nblk + 1) / 2;
        syrk_mma_kernel<<<ntiles, 256, SYRK_SMEM_DYN>>>(pUh, pUl, out_pred, n);
    }
    fill_kernel<<<(n + TPB - 1) / TPB, blk>>>(pdeg, 1.0f, n);
    zero_int_kernel<<<1, 1>>>(pnnz);
    softmax_relu_kernel<<<n, blk>>>(out_pred, n, pnnz, psr, psc, psv, pdeg);
    rsqrt_kernel<<<(n + TPB - 1) / TPB, blk>>>(pdis, pdeg, n);

    for (int l = 0; l < LLAYERS; l++) {
        const __half* Ah = (l == 0) ? pUh : ptDh;
        const __half* Al = (l == 0) ? pUl : ptDl;
        dim3 grid(DDIM / 128, (n + 127) / 128);
        gemm_mma_kernel<false><<<grid, blk, GEMM_SMEM_DYN>>>(Ah, Al,
                                                             pW0h + (size_t)l * DDIM * DDIM,
                                                             pW0l + (size_t)l * DDIM * DDIM,
                                                             pxw, nullptr, n, DDIM, DDIM);
        fill_kernel<<<(ND + TPB - 1) / TPB, blk>>>(pZ2, 0.0f, ND);
        {
            int blocks = (MAXNNZ * 32 + TPB - 1) / TPB;
            dense_scatter_kernel<<<blocks, blk>>>(pxw, psr, psc, psv, pdis, pZ2, pnnz);
        }
        dense_combine_kernel<<<(ND + TPB - 1) / TPB, blk>>>(ptD, pZ2, pxw, pdis,
                                                            gnn0_b + (size_t)l * DDIM,
                                                            n, DDIM, ptDh, ptDl);
    }

    // ---- join + final add ----
    cudaStreamWaitEvent((cudaStream_t)0, evJoin, 0);
    add_kernel<<<(ND + TPB - 1) / TPB, blk>>>(out_skill, ptD, ptS, ND);
}

// round 10
// speedup vs baseline: 8.0184x; 1.0682x over previous
#include <cuda_runtime.h>
#include <cuda_fp16.h>
#include <math.h>
#include <stdint.h>

#define NNODE 8000
#define DDIM  256
#define K3    768
#define EMAX  256000
#define LLAYERS 2
#define PRESERVE_F 0.1f
#define MAXNNZ (4 * NNODE)   // softmax rows sum to 1 => <=4 entries/row exceed 0.2

// ---------------- scratch (static device memory) ---------------------------------
__device__ float g_U [NNODE * DDIM];
__device__ float g_tmpD[NNODE * DDIM];
__device__ float g_tmpS[NNODE * DDIM];
__device__ float g_xw [NNODE * DDIM];     // dense-branch xw
__device__ float g_xwS[NNODE * DDIM];     // sparse-branch xw
__device__ float g_Z2 [NNODE * DDIM];     // dense-branch agg (layer 0)
__device__ float g_Z2c[NNODE * DDIM];     // dense-branch agg (layer 1)
__device__ float g_Z2b[NNODE * DDIM];     // sparse-branch agg
__device__ float g_deg [NNODE];
__device__ float g_dis [NNODE];
__device__ float g_deg2[NNODE];
__device__ float g_dis2[NNODE];
__device__ float g_enorm[EMAX];
__device__ int   g_nnz;
__device__ int   g_sp_r[MAXNNZ];
__device__ int   g_sp_c[MAXNNZ];
__device__ float g_sp_v[MAXNNZ];
// fp16 2-way splits (x = h + l, ~22 mantissa bits)
__device__ __half g_X3h[NNODE * K3];
__device__ __half g_X3l[NNODE * K3];
__device__ __half g_Uh[NNODE * DDIM];
__device__ __half g_Ul[NNODE * DDIM];
__device__ __half g_tDh[NNODE * DDIM];
__device__ __half g_tDl[NNODE * DDIM];
__device__ __half g_tSh[NNODE * DDIM];
__device__ __half g_tSl[NNODE * DDIM];
__device__ __half g_Wfh[K3 * DDIM];
__device__ __half g_Wfl[K3 * DDIM];
__device__ __half g_W0h[LLAYERS * DDIM * DDIM];
__device__ __half g_W0l[LLAYERS * DDIM * DDIM];
__device__ __half g_W1h[LLAYERS * DDIM * DDIM];
__device__ __half g_W1l[LLAYERS * DDIM * DDIM];

__device__ __forceinline__ uint32_t smem_u32(const void* p) {
    uint32_t a;
    asm("{ .reg .u64 t; cvta.to.shared.u64 t, %1; cvt.u32.u64 %0, t; }" : "=r"(a) : "l"(p));
    return a;
}

__device__ __forceinline__ void red_add_v4(float* addr, float4 v) {
    asm volatile("red.global.add.v4.f32 [%0], {%1,%2,%3,%4};"
                 :: "l"(addr), "f"(v.x), "f"(v.y), "f"(v.z), "f"(v.w) : "memory");
}

#define LDSM_X4(r0, r1, r2, r3, addr) \
    asm volatile("ldmatrix.sync.aligned.m8n8.x4.shared.b16 {%0,%1,%2,%3}, [%4];" \
                 : "=r"(r0), "=r"(r1), "=r"(r2), "=r"(r3) : "r"(addr))
#define LDSM_X2(r0, r1, addr) \
    asm volatile("ldmatrix.sync.aligned.m8n8.x2.shared.b16 {%0,%1}, [%2];" \
                 : "=r"(r0), "=r"(r1) : "r"(addr))
#define LDSM_X2_T(r0, r1, addr) \
    asm volatile("ldmatrix.sync.aligned.m8n8.x2.trans.shared.b16 {%0,%1}, [%2];" \
                 : "=r"(r0), "=r"(r1) : "r"(addr))
#define MMA_F16(c, a0, a1, a2, a3, b0, b1) \
    asm volatile("mma.sync.aligned.m16n8k16.row.col.f32.f16.f16.f32 " \
                 "{%0,%1,%2,%3}, {%4,%5,%6,%7}, {%8,%9}, {%0,%1,%2,%3};" \
                 : "+f"((c)[0]), "+f"((c)[1]), "+f"((c)[2]), "+f"((c)[3]) \
                 : "r"(a0), "r"(a1), "r"(a2), "r"(a3), "r"(b0), "r"(b1))
#define CP_ASYNC16(saddr, gptr, sz) \
    asm volatile("cp.async.cg.shared.global [%0], [%1], 16, %2;" \
                 :: "r"(saddr), "l"(gptr), "r"(sz))
#define CP_COMMIT() asm volatile("cp.async.commit_group;")
#define CP_WAIT1()  asm volatile("cp.async.wait_group 1;")
#define CP_WAIT0()  asm volatile("cp.async.wait_group 0;")

#define LDT 40   // A-tile smem stride (fp16), 80 B
#define LDB 136  // B-tile smem stride (fp16), 272 B

// =================== syrk: C = U @ U^T (fp16 2-split, 2-stage, 2 CTA/SM) =========
#define SYRK_TILE_ELEMS (128 * LDT)
#define SYRK_STAGE_ELEMS (4 * SYRK_TILE_ELEMS)          // Ah Al Bh Bl
#define SYRK_SMEM_DYN (2 * SYRK_STAGE_ELEMS * 2)        // 81920 B -> 2 CTA/SM

__global__ __launch_bounds__(256, 2)
void syrk_mma_kernel(const __half* __restrict__ Uh,
                     const __half* __restrict__ Ul,
                     float* __restrict__ C, int n)
{
    extern __shared__ char smem[];
    __half* tiles = (__half*)smem;
    float* epi = (float*)smem;

    const int tid  = threadIdx.x;
    const int wid  = tid >> 5;
    const int lane = tid & 31;
    const int wm   = wid & 1;
    const int wn   = wid >> 1;
    const int group = lane >> 2;
    const int tig   = lane & 3;

    int t = blockIdx.x;
    int bi = (int)((sqrtf(8.0f * (float)t + 1.0f) - 1.0f) * 0.5f);
    while ((bi + 1) * (bi + 2) / 2 <= t) bi++;
    while (bi * (bi + 1) / 2 > t) bi--;
    int bj = t - bi * (bi + 1) / 2;
    const int m0 = bi * 128;
    const int n0 = bj * 128;

    float acc[4][4][4];
#pragma unroll
    for (int a = 0; a < 4; a++)
#pragma unroll
        for (int b = 0; b < 4; b++)
#pragma unroll
            for (int c = 0; c < 4; c++) acc[a][b][c] = 0.f;

    const __half* srcs[4] = { Uh, Ul, Uh, Ul };
    const uint32_t sT = smem_u32(tiles);

    const int a_row = (lane & 15);
    const int a_col = (lane >> 4) * 8;
    const int b_row = (lane & 7);
    const int b_col = ((lane >> 3) & 1) * 8;
    const uint32_t a_base = (uint32_t)((wm * 64 + a_row) * LDT + a_col) * 2;
    const uint32_t b_base = (uint32_t)((wn * 32 + b_row) * LDT + b_col) * 2;

    auto load_chunk = [&](int k0, int stage) {
        uint32_t dst0 = sT + (uint32_t)(stage * SYRK_STAGE_ELEMS) * 2;
#pragma unroll
        for (int s = 0; s < 4; s++) {
            const __half* src = srcs[s];
            const int rowbase = (s < 2) ? m0 : n0;
            uint32_t dts = dst0 + (uint32_t)(s * SYRK_TILE_ELEMS) * 2;
#pragma unroll
            for (int it = 0; it < 2; it++) {
                int lin = it * 256 + tid;
                int r   = lin >> 2;
                int c8  = (lin & 3) * 8;
                int g   = rowbase + r;
                uint32_t sz = (g < n) ? 16u : 0u;
                int g2 = (g < n) ? g : 0;
                const __half* gp = src + (size_t)g2 * DDIM + k0 + c8;
                CP_ASYNC16(dts + (uint32_t)(r * LDT + c8) * 2, gp, sz);
            }
        }
    };

    load_chunk(0, 0);
    CP_COMMIT();

#pragma unroll 1
    for (int kc = 0; kc < 8; kc++) {
        const int cur = kc & 1;
        if (kc + 1 < 8) {
            load_chunk((kc + 1) * 32, cur ^ 1);
            CP_COMMIT();
            CP_WAIT1();
        } else {
            CP_WAIT0();
        }
        __syncthreads();

        const uint32_t stg = sT + (uint32_t)(cur * SYRK_STAGE_ELEMS) * 2;
        const uint32_t sAh = stg;
        const uint32_t sAl = stg + SYRK_TILE_ELEMS * 2u;
        const uint32_t sBh = stg + SYRK_TILE_ELEMS * 4u;
        const uint32_t sBl = stg + SYRK_TILE_ELEMS * 6u;

#pragma unroll
        for (int ks = 0; ks < 2; ks++) {
            const uint32_t koff = (uint32_t)(ks * 16) * 2;
            uint32_t ah[4][4], bh[4][2];
#pragma unroll
            for (int mt = 0; mt < 4; mt++)
                LDSM_X4(ah[mt][0], ah[mt][1], ah[mt][2], ah[mt][3],
                        sAh + a_base + koff + (uint32_t)(mt * 16 * LDT) * 2);
#pragma unroll
            for (int nt = 0; nt < 4; nt++)
                LDSM_X2(bh[nt][0], bh[nt][1],
                        sBh + b_base + koff + (uint32_t)(nt * 8 * LDT) * 2);
            // hh
#pragma unroll
            for (int mt = 0; mt < 4; mt++)
#pragma unroll
                for (int nt = 0; nt < 4; nt++)
                    MMA_F16(acc[mt][nt], ah[mt][0], ah[mt][1], ah[mt][2], ah[mt][3],
                            bh[nt][0], bh[nt][1]);
            {   // hl
                uint32_t bl[4][2];
#pragma unroll
                for (int nt = 0; nt < 4; nt++)
                    LDSM_X2(bl[nt][0], bl[nt][1],
                            sBl + b_base + koff + (uint32_t)(nt * 8 * LDT) * 2);
#pragma unroll
                for (int mt = 0; mt < 4; mt++)
#pragma unroll
                    for (int nt = 0; nt < 4; nt++)
                        MMA_F16(acc[mt][nt], ah[mt][0], ah[mt][1], ah[mt][2], ah[mt][3],
                                bl[nt][0], bl[nt][1]);
            }
            {   // lh
                uint32_t al[4][4];
#pragma unroll
                for (int mt = 0; mt < 4; mt++)
                    LDSM_X4(al[mt][0], al[mt][1], al[mt][2], al[mt][3],
                            sAl + a_base + koff + (uint32_t)(mt * 16 * LDT) * 2);
#pragma unroll
                for (int mt = 0; mt < 4; mt++)
#pragma unroll
                    for (int nt = 0; nt < 4; nt++)
                        MMA_F16(acc[mt][nt], al[mt][0], al[mt][1], al[mt][2], al[mt][3],
                                bh[nt][0], bh[nt][1]);
            }
        }
        __syncthreads();
    }

    // direct write
#pragma unroll
    for (int mt = 0; mt < 4; mt++) {
#pragma unroll
        for (int nt = 0; nt < 4; nt++) {
            int lm = wm * 64 + mt * 16 + group;
            int ln = wn * 32 + nt * 8 + tig * 2;
            int gm = m0 + lm, gn = n0 + ln;
            if (gn + 1 < n) {
                if (gm < n)
                    *reinterpret_cast<float2*>(C + (size_t)gm * n + gn) =
                        make_float2(acc[mt][nt][0], acc[mt][nt][1]);
                if (gm + 8 < n)
                    *reinterpret_cast<float2*>(C + (size_t)(gm + 8) * n + gn) =
                        make_float2(acc[mt][nt][2], acc[mt][nt][3]);
            }
        }
    }

    // mirrored write via smem transpose
    if (bi != bj) {
        __syncthreads();
#pragma unroll
        for (int mt = 0; mt < 4; mt++) {
#pragma unroll
            for (int nt = 0; nt < 4; nt++) {
                int lm = wm * 64 + mt * 16 + group;
                int ln = wn * 32 + nt * 8 + tig * 2;
                epi[lm * 129 + ln]           = acc[mt][nt][0];
                epi[lm * 129 + ln + 1]       = acc[mt][nt][1];
                epi[(lm + 8) * 129 + ln]     = acc[mt][nt][2];
                epi[(lm + 8) * 129 + ln + 1] = acc[mt][nt][3];
            }
        }
        __syncthreads();
        const int c_row = tid >> 1;
        const int half  = tid & 1;
        const int grow  = n0 + c_row;
        if (grow < n) {
            float* outrow = C + (size_t)grow * n;
#pragma unroll
            for (int i = 0; i < 16; i++) {
                int ml = half * 64 + i * 4;
                if (m0 + ml + 3 < n) {
                    float4 v = make_float4(epi[(ml + 0) * 129 + c_row],
                                           epi[(ml + 1) * 129 + c_row],
                                           epi[(ml + 2) * 129 + c_row],
                                           epi[(ml + 3) * 129 + c_row]);
                    *reinterpret_cast<float4*>(outrow + m0 + ml) = v;
                } else {
                    for (int q = 0; q < 4; q++)
                        if (m0 + ml + q < n)
                            outrow[m0 + ml + q] = epi[(ml + q) * 129 + c_row];
                }
            }
        }
    }
}

// =================== GEMM: C = A @ B (+bias), fp16 2-split, 2-stage ==============
#define GEMM_AT_ELEMS (128 * LDT)
#define GEMM_BT_ELEMS (32 * LDB)
#define GEMM_STAGE_ELEMS (2 * (GEMM_AT_ELEMS + GEMM_BT_ELEMS))
#define GEMM_SMEM_DYN (2 * GEMM_STAGE_ELEMS * 2)        // 75776 B -> 2 CTA/SM

template<bool BIAS>
__global__ __launch_bounds__(256, 2)
void gemm_mma_kernel(const __half* __restrict__ Ah_,
                     const __half* __restrict__ Al_,
                     const __half* __restrict__ Bh_,
                     const __half* __restrict__ Bl_,
                     float* __restrict__ C, const float* __restrict__ bias,
                     int M, int N, int K)
{
    extern __shared__ char smem[];
    __half* tiles = (__half*)smem;

    const int tid  = threadIdx.x;
    const int wid  = tid >> 5;
    const int lane = tid & 31;
    const int wm   = wid & 1;
    const int wn   = wid >> 1;
    const int group = lane >> 2;
    const int tig   = lane & 3;

    const int n0 = blockIdx.x * 128;
    const int m0 = blockIdx.y * 128;

    float acc[4][4][4];
#pragma unroll
    for (int a = 0; a < 4; a++)
#pragma unroll
        for (int b = 0; b < 4; b++)
#pragma unroll
            for (int c = 0; c < 4; c++) acc[a][b][c] = 0.f;

    const __half* Asrc[2] = { Ah_, Al_ };
    const __half* Bsrc[2] = { Bh_, Bl_ };
    const uint32_t sT = smem_u32(tiles);

    const int a_row = (lane & 15);
    const int a_col = (lane >> 4) * 8;
    const uint32_t a_base = (uint32_t)((wm * 64 + a_row) * LDT + a_col) * 2;
    const uint32_t bt_base = (uint32_t)((lane & 15) * LDB + wn * 32) * 2;

    auto load_chunk = [&](int k0, int stage) {
        uint32_t dst0 = sT + (uint32_t)(stage * GEMM_STAGE_ELEMS) * 2;
#pragma unroll
        for (int s = 0; s < 2; s++) {
            uint32_t dts = dst0 + (uint32_t)(s * GEMM_AT_ELEMS) * 2;
#pragma unroll
            for (int it = 0; it < 2; it++) {
                int lin = it * 256 + tid;
                int r   = lin >> 2;
                int c8  = (lin & 3) * 8;
                int g   = m0 + r;
                uint32_t sz = (g < M) ? 16u : 0u;
                int g2 = (g < M) ? g : 0;
                const __half* gp = Asrc[s] + (size_t)g2 * K + k0 + c8;
                CP_ASYNC16(dts + (uint32_t)(r * LDT + c8) * 2, gp, sz);
            }
        }
        uint32_t dstB = dst0 + (uint32_t)(2 * GEMM_AT_ELEMS) * 2;
#pragma unroll
        for (int s = 0; s < 2; s++) {
            uint32_t dts = dstB + (uint32_t)(s * GEMM_BT_ELEMS) * 2;
#pragma unroll
            for (int it = 0; it < 2; it++) {
                int lin = it * 256 + tid;
                int r   = lin >> 4;
                int c8  = (lin & 15) * 8;
                const __half* gp = Bsrc[s] + (size_t)(k0 + r) * N + n0 + c8;
                CP_ASYNC16(dts + (uint32_t)(r * LDB + c8) * 2, gp, 16u);
            }
        }
    };

    const int NC = K / 32;
    load_chunk(0, 0);
    CP_COMMIT();

#pragma unroll 1
    for (int kc = 0; kc < NC; kc++) {
        const int cur = kc & 1;
        if (kc + 1 < NC) {
            load_chunk((kc + 1) * 32, cur ^ 1);
            CP_COMMIT();
            CP_WAIT1();
        } else {
            CP_WAIT0();
        }
        __syncthreads();

        const uint32_t stg = sT + (uint32_t)(cur * GEMM_STAGE_ELEMS) * 2;
        const uint32_t sAh = stg;
        const uint32_t sAl = stg + GEMM_AT_ELEMS * 2u;
        const uint32_t sBh = stg + GEMM_AT_ELEMS * 4u;
        const uint32_t sBl = sBh + GEMM_BT_ELEMS * 2u;

#pragma unroll
        for (int ks = 0; ks < 2; ks++) {
            const uint32_t akoff = (uint32_t)(ks * 16) * 2;
            const uint32_t bkoff = (uint32_t)(ks * 16 * LDB) * 2;
            uint32_t ah[4][4], bh[4][2];
#pragma unroll
            for (int mt = 0; mt < 4; mt++)
                LDSM_X4(ah[mt][0], ah[mt][1], ah[mt][2], ah[mt][3],
                        sAh + a_base + akoff + (uint32_t)(mt * 16 * LDT) * 2);
#pragma unroll
            for (int nt = 0; nt < 4; nt++)
                LDSM_X2_T(bh[nt][0], bh[nt][1],
                          sBh + bt_base + bkoff + (uint32_t)(nt * 8) * 2);
            // hh
#pragma unroll
            for (int mt = 0; mt < 4; mt++)
#pragma unroll
                for (int nt = 0; nt < 4; nt++)
                    MMA_F16(acc[mt][nt], ah[mt][0], ah[mt][1], ah[mt][2], ah[mt][3],
                            bh[nt][0], bh[nt][1]);
            {   // hl
                uint32_t bl[4][2];
#pragma unroll
                for (int nt = 0; nt < 4; nt++)
                    LDSM_X2_T(bl[nt][0], bl[nt][1],
                              sBl + bt_base + bkoff + (uint32_t)(nt * 8) * 2);
#pragma unroll
                for (int mt = 0; mt < 4; mt++)
#pragma unroll
                    for (int nt = 0; nt < 4; nt++)
                        MMA_F16(acc[mt][nt], ah[mt][0], ah[mt][1], ah[mt][2], ah[mt][3],
                                bl[nt][0], bl[nt][1]);
            }
            {   // lh
                uint32_t al[4][4];
#pragma unroll
                for (int mt = 0; mt < 4; mt++)
                    LDSM_X4(al[mt][0], al[mt][1], al[mt][2], al[mt][3],
                            sAl + a_base + akoff + (uint32_t)(mt * 16 * LDT) * 2);
#pragma unroll
                for (int mt = 0; mt < 4; mt++)
#pragma unroll
                    for (int nt = 0; nt < 4; nt++)
                        MMA_F16(acc[mt][nt], al[mt][0], al[mt][1], al[mt][2], al[mt][3],
                                bh[nt][0], bh[nt][1]);
            }
        }
        __syncthreads();
    }

    // epilogue
#pragma unroll
    for (int mt = 0; mt < 4; mt++) {
#pragma unroll
        for (int nt = 0; nt < 4; nt++) {
            int lm = wm * 64 + mt * 16 + group;
            int ln = wn * 32 + nt * 8 + tig * 2;
            int gm = m0 + lm, gn = n0 + ln;
            float b0 = 0.f, b1 = 0.f;
            if (BIAS) { b0 = bias[gn]; b1 = bias[gn + 1]; }
            if (gm < M)
                *reinterpret_cast<float2*>(C + (size_t)gm * N + gn) =
                    make_float2(acc[mt][nt][0] + b0, acc[mt][nt][1] + b1);
            if (gm + 8 < M)
                *reinterpret_cast<float2*>(C + (size_t)(gm + 8) * N + gn) =
                    make_float2(acc[mt][nt][2] + b0, acc[mt][nt][3] + b1);
        }
    }
}

// ---------------- split kernels (fp16 2-way) --------------------------------------
__global__ void split2h_kernel(const float* __restrict__ U,
                               __half* __restrict__ Uh,
                               __half* __restrict__ Ul, int total)
{
    int i = blockIdx.x * blockDim.x + threadIdx.x;
    if (i >= total) return;
    float x = U[i];
    __half h = __float2half(x);
    Uh[i] = h;
    Ul[i] = __float2half(x - __half2float(h));
}

__global__ void gather_split2_kernel(const float* __restrict__ emb1,
                                     const float* __restrict__ demand,
                                     const float* __restrict__ supply,
                                     __half* __restrict__ Xh,
                                     __half* __restrict__ Xl, int n, int T)
{
    int i = blockIdx.x * blockDim.x + threadIdx.x;
    int total = n * DDIM;
    if (i >= total) return;
    int node = i / DDIM, d = i % DDIM;
    float v[3];
    v[0] = emb1[(size_t)node * DDIM + d];
    v[1] = demand[((size_t)node * T + (T - 1)) * DDIM + d];
    v[2] = supply[((size_t)node * T + (T - 1)) * DDIM + d];
#pragma unroll
    for (int s = 0; s < 3; s++) {
        size_t idx = (size_t)node * K3 + s * DDIM + d;
        float x = v[s];
        __half h = __float2half(x);
        Xh[idx] = h;
        Xl[idx] = __float2half(x - __half2float(h));
    }
}

// ---------------- small kernels ---------------------------------------------------
__global__ void softmax_relu_kernel(float* __restrict__ Z, int n,
                                    int* __restrict__ nnz,
                                    int* __restrict__ sr, int* __restrict__ sc,
                                    float* __restrict__ sv,
                                    float* __restrict__ deg)
{
    __shared__ float row[NNODE];
    __shared__ float red[256];
    int r = blockIdx.x;
    int t = threadIdx.x;
    float* zr = Z + (size_t)r * n;
    const int n4 = n >> 2;

    float mx = -3.4e38f;
    for (int c4 = t; c4 < n4; c4 += 256) {
        float4 v = reinterpret_cast<const float4*>(zr)[c4];
        reinterpret_cast<float4*>(row)[c4] = v;
        mx = fmaxf(mx, fmaxf(fmaxf(v.x, v.y), fmaxf(v.z, v.w)));
    }
    for (int c = n4 * 4 + t; c < n; c += 256) { float v = zr[c]; row[c] = v; mx = fmaxf(mx, v); }
    red[t] = mx; __syncthreads();
    for (int s = 128; s > 0; s >>= 1) {
        if (t < s) red[t] = fmaxf(red[t], red[t + s]);
        __syncthreads();
    }
    mx = red[0];
    __syncthreads();

    float sm = 0.f;
    for (int c4 = t; c4 < n4; c4 += 256) {
        float4 v = reinterpret_cast<const float4*>(row)[c4];
        v.x = __expf(v.x - mx); v.y = __expf(v.y - mx);
        v.z = __expf(v.z - mx); v.w = __expf(v.w - mx);
        reinterpret_cast<float4*>(row)[c4] = v;
        sm += v.x + v.y + v.z + v.w;
    }
    for (int c = n4 * 4 + t; c < n; c += 256) { float e = __expf(row[c] - mx); row[c] = e; sm += e; }
    red[t] = sm; __syncthreads();
    for (int s = 128; s > 0; s >>= 1) {
        if (t < s) red[t] += red[t + s];
        __syncthreads();
    }
    float inv = 1.0f / red[0];
    for (int c4 = t; c4 < n4; c4 += 256) {
        float4 v = reinterpret_cast<const float4*>(row)[c4];
        float4 p;
        p.x = fmaxf(v.x * inv - 0.2f, 0.f);
        p.y = fmaxf(v.y * inv - 0.2f, 0.f);
        p.z = fmaxf(v.z * inv - 0.2f, 0.f);
        p.w = fmaxf(v.w * inv - 0.2f, 0.f);
        reinterpret_cast<float4*>(zr)[c4] = p;
        float pv[4] = { p.x, p.y, p.z, p.w };
#pragma unroll
        for (int q = 0; q < 4; q++) {
            if (pv[q] > 0.f) {
                int c = c4 * 4 + q;
                int idx = atomicAdd(nnz, 1);
                if (idx < MAXNNZ) { sr[idx] = r; sc[idx] = c; sv[idx] = pv[q]; }
                atomicAdd(&deg[c], pv[q]);
            }
        }
    }
    for (int c = n4 * 4 + t; c < n; c += 256) {
        float p = fmaxf(row[c] * inv - 0.2f, 0.f);
        zr[c] = p;
        if (p > 0.f) {
            int idx = atomicAdd(nnz, 1);
            if (idx < MAXNNZ) { sr[idx] = r; sc[idx] = c; sv[idx] = p; }
            atomicAdd(&deg[c], p);
        }
    }
}

__global__ void fill_kernel(float* p, float v, int n)
{
    int i = blockIdx.x * blockDim.x + threadIdx.x;
    if (i < n) p[i] = v;
}

__global__ void zero_int_kernel(int* p) { *p = 0; }

__global__ void rsqrt_kernel(float* __restrict__ dst, const float* __restrict__ src, int n)
{
    int i = blockIdx.x * blockDim.x + threadIdx.x;
    if (i < n) dst[i] = rsqrtf(src[i]);
}

__global__ void dense_scatter_kernel(const float* __restrict__ xw,
                                     const int* __restrict__ sr,
                                     const int* __restrict__ sc,
                                     const float* __restrict__ sv,
                                     const float* __restrict__ dis,
                                     float* __restrict__ agg,
                                     const int* __restrict__ nnz)
{
    int warp = (blockIdx.x * blockDim.x + threadIdx.x) >> 5;
    int lane = threadIdx.x & 31;
    int m = *nnz; if (m > MAXNNZ) m = MAXNNZ;
    if (warp >= m) return;
    int r = sr[warp], c = sc[warp];
    float w = sv[warp] * dis[r];
    const float4* xr = reinterpret_cast<const float4*>(xw + (size_t)r * DDIM);
    float* ar = agg + (size_t)c * DDIM;
#pragma unroll
    for (int h = 0; h < 2; h++) {
        int f4 = h * 32 + lane;
        float4 x = xr[f4];
        red_add_v4(ar + f4 * 4, make_float4(w * x.x, w * x.y, w * x.z, w * x.w));
    }
}

__global__ void dense_combine_kernel(float* __restrict__ temp, const float* __restrict__ Z2,
                                     const float* __restrict__ xw, const float* __restrict__ dis,
                                     const float* __restrict__ b, int n, int d,
                                     __half* __restrict__ th,
                                     __half* __restrict__ tl)
{
    int i = blockIdx.x * blockDim.x + threadIdx.x;
    if (i >= n * d) return;
    int c = i / d, dd = i - c * d;
    float s = dis[c];
    float out = s * Z2[i] + s * s * xw[i] + b[dd];
    float v = (1.0f - PRESERVE_F) * out + PRESERVE_F * temp[i];
    temp[i] = v;
    __half h = __float2half(v);
    th[i] = h; tl[i] = __float2half(v - __half2float(h));
}

__global__ void edge_deg_kernel(const int* __restrict__ dst, const float* __restrict__ attr,
                                float* __restrict__ deg2, int E)
{
    int e = blockIdx.x * blockDim.x + threadIdx.x;
    if (e < E) atomicAdd(&deg2[dst[e]], attr[e]);
}

__global__ void enorm_kernel(const int* __restrict__ src, const int* __restrict__ dst,
                             const float* __restrict__ attr, const float* __restrict__ dis2,
                             float* __restrict__ enorm, int E)
{
    int e = blockIdx.x * blockDim.x + threadIdx.x;
    if (e < E) enorm[e] = dis2[src[e]] * attr[e] * dis2[dst[e]];
}

__global__ void scatter_kernel(const float* __restrict__ xw, const int* __restrict__ src,
                               const int* __restrict__ dst, const float* __restrict__ enorm,
                               float* __restrict__ agg, int E, int d)
{
    int warp = (blockIdx.x * blockDim.x + threadIdx.x) >> 5;
    int lane = threadIdx.x & 31;
    if (warp >= E) return;
    int s = src[warp], t = dst[warp];
    float w = enorm[warp];
    const float4* xr = reinterpret_cast<const float4*>(xw + (size_t)s * DDIM);
    float* ar = agg + (size_t)t * DDIM;
#pragma unroll
    for (int h = 0; h < 2; h++) {
        int f4 = h * 32 + lane;
        float4 x = xr[f4];
        red_add_v4(ar + f4 * 4, make_float4(w * x.x, w * x.y, w * x.z, w * x.w));
    }
}

__global__ void sparse_combine_kernel(float* __restrict__ temp, const float* __restrict__ agg,
                                      const float* __restrict__ xw, const float* __restrict__ dis2,
                                      const float* __restrict__ b, int n, int d,
                                      __half* __restrict__ th,
                                      __half* __restrict__ tl)
{
    int i = blockIdx.x * blockDim.x + threadIdx.x;
    if (i >= n * d) return;
    int c = i / d, dd = i - c * d;
    float s = dis2[c];
    float out = agg[i] + s * s * xw[i] + b[dd];
    float v = (1.0f - PRESERVE_F) * out + PRESERVE_F * temp[i];
    temp[i] = v;
    __half h = __float2half(v);
    th[i] = h; tl[i] = __float2half(v - __half2float(h));
}

__global__ void add_kernel(float* __restrict__ out, const float* __restrict__ a,
                           const float* __restrict__ b, int n)
{
    int i = blockIdx.x * blockDim.x + threadIdx.x;
    if (i < n) out[i] = a[i] + b[i];
}

// ---------------- host orchestration ----------------------------------------------
extern "C" void kernel_launch(void* const* d_in, const int* in_sizes, int n_in,
                              void* d_out, int out_size)
{
    const float* demand  = (const float*)d_in[0];
    const float* supply  = (const float*)d_in[1];
    const int*   eidx    = (const int*)  d_in[2];
    const float* eattr   = (const float*)d_in[3];
    const float* emb1    = (const float*)d_in[4];
    const float* fuse_W  = (const float*)d_in[5];
    const float* fuse_b  = (const float*)d_in[6];
    const float* gnn0_W  = (const float*)d_in[7];
    const float* gnn0_b  = (const float*)d_in[8];
    const float* gnn1_W  = (const float*)d_in[9];
    const float* gnn1_b  = (const float*)d_in[10];

    const int n = in_sizes[4] / DDIM;
    const int E = in_sizes[3];
    const int T = in_sizes[0] / (n * DDIM);

    float* out_emb1  = (float*)d_out;
    float* out_skill = out_emb1 + (size_t)n * DDIM;
    float* out_pred  = out_skill + (size_t)n * DDIM;

    float *pU, *ptD, *ptS, *pxw, *pxwS, *pZ2, *pZ2c, *pZ2b, *pdeg, *pdis, *pdeg2, *pdis2, *pen, *psv;
    int *pnnz, *psr, *psc;
    __half *pX3h, *pX3l, *pUh, *pUl, *ptDh, *ptDl, *ptSh, *ptSl;
    __half *pWfh, *pWfl, *pW0h, *pW0l, *pW1h, *pW1l;
    cudaGetSymbolAddress((void**)&pU,   g_U);
    cudaGetSymbolAddress((void**)&ptD,  g_tmpD);
    cudaGetSymbolAddress((void**)&ptS,  g_tmpS);
    cudaGetSymbolAddress((void**)&pxw,  g_xw);
    cudaGetSymbolAddress((void**)&pxwS, g_xwS);
    cudaGetSymbolAddress((void**)&pZ2,  g_Z2);
    cudaGetSymbolAddress((void**)&pZ2c, g_Z2c);
    cudaGetSymbolAddress((void**)&pZ2b, g_Z2b);
    cudaGetSymbolAddress((void**)&pdeg, g_deg);
    cudaGetSymbolAddress((void**)&pdis, g_dis);
    cudaGetSymbolAddress((void**)&pdeg2,g_deg2);
    cudaGetSymbolAddress((void**)&pdis2,g_dis2);
    cudaGetSymbolAddress((void**)&pen,  g_enorm);
    cudaGetSymbolAddress((void**)&pnnz, g_nnz);
    cudaGetSymbolAddress((void**)&psr,  g_sp_r);
    cudaGetSymbolAddress((void**)&psc,  g_sp_c);
    cudaGetSymbolAddress((void**)&psv,  g_sp_v);
    cudaGetSymbolAddress((void**)&pX3h, g_X3h);
    cudaGetSymbolAddress((void**)&pX3l, g_X3l);
    cudaGetSymbolAddress((void**)&pUh,  g_Uh);
    cudaGetSymbolAddress((void**)&pUl,  g_Ul);
    cudaGetSymbolAddress((void**)&ptDh, g_tDh);
    cudaGetSymbolAddress((void**)&ptDl, g_tDl);
    cudaGetSymbolAddress((void**)&ptSh, g_tSh);
    cudaGetSymbolAddress((void**)&ptSl, g_tSl);
    cudaGetSymbolAddress((void**)&pWfh, g_Wfh);
    cudaGetSymbolAddress((void**)&pWfl, g_Wfl);
    cudaGetSymbolAddress((void**)&pW0h, g_W0h);
    cudaGetSymbolAddress((void**)&pW0l, g_W0l);
    cudaGetSymbolAddress((void**)&pW1h, g_W1h);
    cudaGetSymbolAddress((void**)&pW1l, g_W1l);

    static cudaStream_t s2 = nullptr, s3 = nullptr;
    static cudaEvent_t evFork = nullptr, evJoin = nullptr, evD = nullptr;
    static int attr_set = 0;
    if (!attr_set) {
        cudaFuncSetAttribute(syrk_mma_kernel,
                             cudaFuncAttributeMaxDynamicSharedMemorySize, SYRK_SMEM_DYN);
        cudaFuncSetAttribute(gemm_mma_kernel<true>,
                             cudaFuncAttributeMaxDynamicSharedMemorySize, GEMM_SMEM_DYN);
        cudaFuncSetAttribute(gemm_mma_kernel<false>,
                             cudaFuncAttributeMaxDynamicSharedMemorySize, GEMM_SMEM_DYN);
        cudaStreamCreateWithFlags(&s2, cudaStreamNonBlocking);
        cudaStreamCreateWithFlags(&s3, cudaStreamNonBlocking);
        cudaEventCreateWithFlags(&evFork, cudaEventDisableTiming);
        cudaEventCreateWithFlags(&evJoin, cudaEventDisableTiming);
        cudaEventCreateWithFlags(&evD, cudaEventDisableTiming);
        attr_set = 1;
    }

    const int ND = n * DDIM;
    const int TPB = 256;
    dim3 blk(TPB);
    dim3 gemm_grid(DDIM / 128, (n + 127) / 128);

    // ---- prologue (stream 0): splits + fuse GEMM + U splits ----
    gather_split2_kernel<<<(ND + TPB - 1) / TPB, blk>>>(emb1, demand, supply,
                                                        pX3h, pX3l, n, T);
    split2h_kernel<<<(K3 * DDIM + TPB - 1) / TPB, blk>>>(fuse_W, pWfh, pWfl, K3 * DDIM);
    split2h_kernel<<<(LLAYERS * DDIM * DDIM + TPB - 1) / TPB, blk>>>(gnn0_W, pW0h, pW0l,
                                                                     LLAYERS * DDIM * DDIM);
    split2h_kernel<<<(LLAYERS * DDIM * DDIM + TPB - 1) / TPB, blk>>>(gnn1_W, pW1h, pW1l,
                                                                     LLAYERS * DDIM * DDIM);
    cudaMemcpyAsync(out_emb1, emb1, (size_t)ND * sizeof(float), cudaMemcpyDeviceToDevice);

    gemm_mma_kernel<true><<<gemm_grid, blk, GEMM_SMEM_DYN>>>(pX3h, pX3l, pWfh, pWfl,
                                                             pU, fuse_b, n, DDIM, K3);
    split2h_kernel<<<(ND + TPB - 1) / TPB, blk>>>(pU, pUh, pUl, ND);

    // ---- fork ----
    cudaEventRecord(evFork, 0);
    cudaStreamWaitEvent(s2, evFork, 0);
    cudaStreamWaitEvent(s3, evFork, 0);

    // === stream s3: dense-branch prep (independent of syrk/softmax) ===
    cudaMemcpyAsync(ptD, pU, (size_t)ND * sizeof(float), cudaMemcpyDeviceToDevice, s3);
    fill_kernel<<<(n + TPB - 1) / TPB, blk, 0, s3>>>(pdeg, 1.0f, n);
    zero_int_kernel<<<1, 1, 0, s3>>>(pnnz);
    fill_kernel<<<(ND + TPB - 1) / TPB, blk, 0, s3>>>(pZ2, 0.0f, ND);
    fill_kernel<<<(ND + TPB - 1) / TPB, blk, 0, s3>>>(pZ2c, 0.0f, ND);
    // dense layer-0 GEMM: xw = U @ W0_0  (only needs U splits)
    gemm_mma_kernel<false><<<gemm_grid, blk, GEMM_SMEM_DYN, s3>>>(pUh, pUl, pW0h, pW0l,
                                                                  pxw, nullptr, n, DDIM, DDIM);
    cudaEventRecord(evD, s3);

    // === stream s2: sparse GCN branch ===
    cudaMemcpyAsync(ptS, pU, (size_t)ND * sizeof(float), cudaMemcpyDeviceToDevice, s2);
    fill_kernel<<<(n + TPB - 1) / TPB, blk, 0, s2>>>(pdeg2, 1.0f, n);
    edge_deg_kernel<<<(E + TPB - 1) / TPB, blk, 0, s2>>>(eidx + E, eattr, pdeg2, E);
    rsqrt_kernel<<<(n + TPB - 1) / TPB, blk, 0, s2>>>(pdis2, pdeg2, n);
    enorm_kernel<<<(E + TPB - 1) / TPB, blk, 0, s2>>>(eidx, eidx + E, eattr, pdis2, pen, E);
    for (int l = 0; l < LLAYERS; l++) {
        const __half* Ah = (l == 0) ? pUh : ptSh;
        const __half* Al = (l == 0) ? pUl : ptSl;
        gemm_mma_kernel<false><<<gemm_grid, blk, GEMM_SMEM_DYN, s2>>>(Ah, Al,
                                                                      pW1h + (size_t)l * DDIM * DDIM,
                                                                      pW1l + (size_t)l * DDIM * DDIM,
                                                                      pxwS, nullptr, n, DDIM, DDIM);
        fill_kernel<<<(ND + TPB - 1) / TPB, blk, 0, s2>>>(pZ2b, 0.0f, ND);
        {
            int blocks = (E * 32 + TPB - 1) / TPB;
            scatter_kernel<<<blocks, blk, 0, s2>>>(pxwS, eidx, eidx + E, pen, pZ2b, E, DDIM);
        }
        sparse_combine_kernel<<<(ND + TPB - 1) / TPB, blk, 0, s2>>>(ptS, pZ2b, pxwS, pdis2,
                                                                    gnn1_b + (size_t)l * DDIM,
                                                                    n, DDIM, ptSh, ptSl);
    }
    cudaEventRecord(evJoin, s2);

    // === stream 0: syrk -> softmax -> dense GCN epilogue ===
    {
        int nblk = (n + 127) / 128;
        int ntiles = nblk * (nblk + 1) / 2;
        syrk_mma_kernel<<<ntiles, 256, SYRK_SMEM_DYN>>>(pUh, pUl, out_pred, n);
    }
    cudaStreamWaitEvent((cudaStream_t)0, evD, 0);
    softmax_relu_kernel<<<n, blk>>>(out_pred, n, pnnz, psr, psc, psv, pdeg);
    rsqrt_kernel<<<(n + TPB - 1) / TPB, blk>>>(pdis, pdeg, n);

    for (int l = 0; l < LLAYERS; l++) {
        if (l > 0) {
            // xw = temp @ W0_l (layer-0 GEMM was prelaunched on s3)
            gemm_mma_kernel<false><<<gemm_grid, blk, GEMM_SMEM_DYN>>>(ptDh, ptDl,
                                                                      pW0h + (size_t)l * DDIM * DDIM,
                                                                      pW0l + (size_t)l * DDIM * DDIM,
                                                                      pxw, nullptr, n, DDIM, DDIM);
        }
        float* aggbuf = (l == 0) ? pZ2 : pZ2c;
        {
            int blocks = (MAXNNZ * 32 + TPB - 1) / TPB;
            dense_scatter_kernel<<<blocks, blk>>>(pxw, psr, psc, psv, pdis, aggbuf, pnnz);
        }
        dense_combine_kernel<<<(ND + TPB - 1) / TPB, blk>>>(ptD, aggbuf, pxw, pdis,
                                                            gnn0_b + (size_t)l * DDIM,
                                                            n, DDIM, ptDh, ptDl);
    }

    // ---- join + final add ----
    cudaStreamWaitEvent((cudaStream_t)0, evJoin, 0);
    add_kernel<<<(ND + TPB - 1) / TPB, blk>>>(out_skill, ptD, ptS, ND);
}